// round 9
// baseline (speedup 1.0000x reference)
#include <cuda_runtime.h>
#include <cuda_bf16.h>
#include <math.h>
#include <stdint.h>

#define Bn   4096
#define Hd   512
#define Fd   256
#define Zd   64
#define Td   16
#define Gd   2048
#define XK   832      // bf16 X row: [z(64) | y(256) | h(512)]
#define IK   1024     // head K:     [c(512) | y_j(256) | y_prev(256)]
#define CK   512      // c buffer row

// ---------------- persistent buffers ----------------
__device__ float g_baseg [(size_t)Bn * Gd];
__device__ float g_basehz[Bn * 128];
__device__ float g_c     [Bn * Hd];
__device__ float g_blstmp[Gd];
__device__ float g_bhz   [128];

__device__ __nv_bfloat16 g_Xh0[(size_t)Bn * XK], g_Xl0[(size_t)Bn * XK];
__device__ __nv_bfloat16 g_Xh1[(size_t)Bn * XK], g_Xl1[(size_t)Bn * XK];
__device__ __nv_bfloat16 g_Ch [(size_t)Bn * CK], g_Cl [(size_t)Bn * CK];
__device__ __nv_bfloat16 g_hih[(size_t)Bn * Hd], g_hil[(size_t)Bn * Hd];

__device__ __nv_bfloat16 g_WcatT_h[(size_t)Gd * XK], g_WcatT_l[(size_t)Gd * XK];
__device__ __nv_bfloat16 g_WxhT_h [(size_t)Gd * Hd], g_WxhT_l [(size_t)Gd * Hd];
__device__ __nv_bfloat16 g_W1T_h  [Fd * Hd], g_W1T_l  [Fd * Hd];
__device__ __nv_bfloat16 g_W2T_h  [Fd * Fd], g_W2T_l  [Fd * Fd];
__device__ __nv_bfloat16 g_W3T_h  [Fd * Fd], g_W3T_l  [Fd * Fd];
__device__ __nv_bfloat16 g_WheadT_h[128 * IK], g_WheadT_l[128 * IK];
__device__ __nv_bfloat16 g_WbaseT_h[128 * Hd], g_WbaseT_l[128 * Hd];

// ---------------- helpers ----------------
__device__ __forceinline__ void bsplit(float v, __nv_bfloat16& h, __nv_bfloat16& l) {
    h = __float2bfloat16_rn(v);
    l = __float2bfloat16_rn(v - __bfloat162float(h));
}
__device__ __forceinline__ uint32_t bpack(__nv_bfloat16 a, __nv_bfloat16 b) {
    __nv_bfloat162 t; t.x = a; t.y = b;
    return reinterpret_cast<uint32_t&>(t);
}
__device__ __forceinline__ __nv_bfloat162 bmk2(__nv_bfloat16 a, __nv_bfloat16 b) {
    __nv_bfloat162 t; t.x = a; t.y = b; return t;
}
__device__ __forceinline__ void mma16816(float* c, const uint32_t* a, const uint32_t* b) {
    asm volatile(
        "mma.sync.aligned.m16n8k16.row.col.f32.bf16.bf16.f32 "
        "{%0,%1,%2,%3}, {%4,%5,%6,%7}, {%8,%9}, {%0,%1,%2,%3};\n"
        : "+f"(c[0]), "+f"(c[1]), "+f"(c[2]), "+f"(c[3])
        : "r"(a[0]), "r"(a[1]), "r"(a[2]), "r"(a[3]), "r"(b[0]), "r"(b[1]));
}
__device__ __forceinline__ void ldsm4(uint32_t& r0, uint32_t& r1, uint32_t& r2, uint32_t& r3,
                                      uint32_t addr) {
    asm volatile("ldmatrix.sync.aligned.m8n8.x4.shared.b16 {%0,%1,%2,%3}, [%4];"
        : "=r"(r0), "=r"(r1), "=r"(r2), "=r"(r3) : "r"(addr));
}
__device__ __forceinline__ void cpa16(void* dst, const void* src) {
    uint32_t d = (uint32_t)__cvta_generic_to_shared(dst);
    asm volatile("cp.async.cg.shared.global [%0], [%1], 16;\n" :: "r"(d), "l"(src));
}
#define CPA_COMMIT() asm volatile("cp.async.commit_group;\n")
#define CPA_WAIT1()  asm volatile("cp.async.wait_group 1;\n")
#define CPA_WAIT0()  asm volatile("cp.async.wait_group 0;\n")

// ldmatrix-based stage mma (rows of 80B; hi at base, lo at base+HS)
template<int MT,int NTL,int AHS,int BHS>
__device__ __forceinline__ void stage_mma2(const char* Ab, const char* Bb, float* acc,
                                           int wm, int wn, int laneoff)
{
    uint32_t aH = (uint32_t)__cvta_generic_to_shared(Ab) + laneoff;
    uint32_t bH = (uint32_t)__cvta_generic_to_shared(Bb) + laneoff;
#pragma unroll
    for (int kk = 0; kk < 2; kk++) {
        const int kb = kk * 32;
        uint32_t bhf[NTL][2], blf[NTL][2];
#pragma unroll
        for (int np = 0; np < NTL / 2; np++) {
            uint32_t r0, r1, r2, r3;
            ldsm4(r0, r1, r2, r3, bH + (wn + np * 16) * 80 + kb);
            bhf[2*np][0] = r0; bhf[2*np+1][0] = r1; bhf[2*np][1] = r2; bhf[2*np+1][1] = r3;
            ldsm4(r0, r1, r2, r3, bH + BHS + (wn + np * 16) * 80 + kb);
            blf[2*np][0] = r0; blf[2*np+1][0] = r1; blf[2*np][1] = r2; blf[2*np+1][1] = r3;
        }
#pragma unroll
        for (int mt = 0; mt < MT; mt++) {
            uint32_t ah[4], al[4];
            ldsm4(ah[0], ah[1], ah[2], ah[3], aH + (wm + mt * 16) * 80 + kb);
            ldsm4(al[0], al[1], al[2], al[3], aH + AHS + (wm + mt * 16) * 80 + kb);
#pragma unroll
            for (int nt = 0; nt < NTL; nt++) {
                float* a = acc + (mt * NTL + nt) * 4;
                mma16816(a, ah, bhf[nt]);
                mma16816(a, ah, blf[nt]);
                mma16816(a, al, bhf[nt]);
            }
        }
    }
}

// ================= gate GEMM (+fused LSTM) =================
struct GArgs {
    const __nv_bfloat16 *Ah, *Al; int lda;
    const __nv_bfloat16 *Bh, *Bl; int ldb;
    const float* Ci; int ldci;
    float* C; int ldc;
    int K;
    float* cst;
    __nv_bfloat16 *Xh, *Xl;
    __nv_bfloat16 *Ch, *Cl;
};

template<int BM,int BN,int NTH>
__device__ __forceinline__ void stage_load(char* base, int tid, int bm, int bn,
    const __nv_bfloat16* Ah, const __nv_bfloat16* Al, int lda,
    const __nv_bfloat16* Bh, const __nv_bfloat16* Bl, int ldb, int k0)
{
#pragma unroll
    for (int i = tid; i < BM * 4; i += NTH) {
        int row = i >> 2, c4 = (i & 3) * 16;
        size_t off = ((size_t)(bm + row) * lda + k0) * 2 + c4;
        cpa16(base + row * 80 + c4, (const char*)Ah + off);
        cpa16(base + BM * 80 + row * 80 + c4, (const char*)Al + off);
    }
#pragma unroll
    for (int i = tid; i < BN * 4; i += NTH) {
        int row = i >> 2, c4 = (i & 3) * 16;
        size_t off = ((size_t)(bn + row) * ldb + k0) * 2 + c4;
        cpa16(base + BM * 160 + row * 80 + c4, (const char*)Bh + off);
        cpa16(base + BM * 160 + BN * 80 + row * 80 + c4, (const char*)Bl + off);
    }
    CPA_COMMIT();
}

// 3-buffer pipeline, one barrier per stage.
template<int BM,int BN,int WM,int WN,int NTH,int EPI,int CI>
__global__ void __launch_bounds__(NTH) gemm(GArgs g)
{
    extern __shared__ char sm[];
    constexpr int MT = WM / 16, NTL = WN / 8, NWN = BN / WN;
    constexpr int stageB = (BM + BN) * 160;
    const int tid = threadIdx.x, warp = tid >> 5, lane = tid & 31;
    const int gq = lane >> 2, tg = lane & 3;
    const int laneoff = (lane & 15) * 80 + (lane >> 4) * 16;
    const int wm = (warp / NWN) * WM, wn = (warp % NWN) * WN;
    const int bm = blockIdx.y * BM, bn = blockIdx.x * BN;
    const int K = g.K;

    float acc[MT * NTL * 4];
#pragma unroll
    for (int i = 0; i < MT * NTL * 4; i++) acc[i] = 0.f;

    const int nk = K >> 5;
    stage_load<BM,BN,NTH>(sm + 0 * stageB, tid, bm, bn, g.Ah, g.Al, g.lda, g.Bh, g.Bl, g.ldb, 0);
    stage_load<BM,BN,NTH>(sm + 1 * stageB, tid, bm, bn, g.Ah, g.Al, g.lda, g.Bh, g.Bl, g.ldb, 32);
    int cb = 0;   // current buffer index
    for (int kt = 0; kt < nk; kt++) {
        if (kt + 1 < nk) CPA_WAIT1(); else CPA_WAIT0();
        __syncthreads();
        if (kt + 2 < nk) {
            int nb = cb + 2; if (nb >= 3) nb -= 3;
            stage_load<BM,BN,NTH>(sm + nb * stageB, tid, bm, bn,
                                  g.Ah, g.Al, g.lda, g.Bh, g.Bl, g.ldb, (kt + 2) << 5);
        }
        const char* cur = sm + cb * stageB;
        stage_mma2<MT,NTL,BM*80,BN*80>(cur, cur + BM * 160, acc, wm, wn, laneoff);
        if (++cb == 3) cb = 0;
    }
    __syncthreads();   // all warps done with smem before epilogue reuse

    if (EPI == 1) {
        float* tile = (float*)sm;    // BM x BN fp32
#pragma unroll
        for (int mt = 0; mt < MT; mt++)
#pragma unroll
            for (int nt = 0; nt < NTL; nt++) {
                int r0 = wm + mt * 16 + gq, c0 = wn + nt * 8 + 2 * tg;
                float* a = acc + (mt * NTL + nt) * 4;
                const float* ci0 = g.Ci + (size_t)(bm + r0) * g.ldci + bn + c0;
                const float* ci1 = g.Ci + (size_t)(bm + r0 + 8) * g.ldci + bn + c0;
                tile[r0 * BN + c0]           = a[0] + ci0[0];
                tile[r0 * BN + c0 + 1]       = a[1] + ci0[1];
                tile[(r0 + 8) * BN + c0]     = a[2] + ci1[0];
                tile[(r0 + 8) * BN + c0 + 1] = a[3] + ci1[1];
            }
        __syncthreads();
        for (int idx = tid; idx < BM * 32; idx += NTH) {
            int row = idx >> 5, w = idx & 31;
            float ig = tile[row * BN + w];
            float fg = tile[row * BN + 32 + w];
            float gg = tile[row * BN + 64 + w];
            float og = tile[row * BN + 96 + w];
            int b = bm + row, j = blockIdx.x * 32 + w;
            float si = 1.f / (1.f + expf(-ig));
            float sf = 1.f / (1.f + expf(-fg));
            float so = 1.f / (1.f + expf(-og));
            float cn = sf * g.cst[b * Hd + j] + si * tanhf(gg);
            float hn = so * tanhf(cn);
            g.cst[b * Hd + j] = cn;
            __nv_bfloat16 hh, hl, ch, cl;
            bsplit(hn, hh, hl); bsplit(cn, ch, cl);
            g.Xh[(size_t)b * XK + 320 + j] = hh;
            g.Xl[(size_t)b * XK + 320 + j] = hl;
            g.Ch[(size_t)b * CK + j] = ch;
            g.Cl[(size_t)b * CK + j] = cl;
        }
        return;
    }

#pragma unroll
    for (int mt = 0; mt < MT; mt++)
#pragma unroll
        for (int nt = 0; nt < NTL; nt++) {
            float* a = acc + (mt * NTL + nt) * 4;
#pragma unroll
            for (int half = 0; half < 2; half++) {
                int r = bm + wm + mt * 16 + gq + half * 8;
                int c = bn + wn + nt * 8 + 2 * tg;
                float v0 = a[half * 2], v1 = a[half * 2 + 1];
                if (CI == 1) { v0 += g.Ci[c]; v1 += g.Ci[c + 1]; }
                *(float2*)&g.C[(size_t)r * g.ldc + c] = make_float2(v0, v1);
            }
        }
}

// ================= fused tail kernel (unchanged from R8) =================
struct TailArgs {
    const __nv_bfloat16 *XwH, *XwL;
    __nv_bfloat16 *XwHm, *XwLm;
    const __nv_bfloat16 *XrH, *XrL;
    const __nv_bfloat16 *Ch, *Cl;
    const float* basehz;
    const float *b1, *b2, *b3;
    const float *W5, *b5, *W6, *b6, *W8, *b8, *W9, *b9;
    const float *eps_inf, *eps_pri;
    float *fake, *out_mean, *out_lv, *out_z;
    int t;
};

template<int BN,int NTH>
__device__ __forceinline__ void tail_loadB(char* st, int tid,
    const __nv_bfloat16* Bh, const __nv_bfloat16* Bl, int ldb, int kg)
{
#pragma unroll
    for (int i = tid; i < BN * 4; i += NTH) {
        int row = i >> 2, c4 = (i & 3) * 16;
        size_t off = ((size_t)row * ldb + kg) * 2 + c4;
        cpa16(st + row * 80 + c4, (const char*)Bh + off);
        cpa16(st + BN * 80 + row * 80 + c4, (const char*)Bl + off);
    }
}

__device__ __forceinline__ void tail_loadA(char* st, int tid, int r0,
    const __nv_bfloat16* Ah, const __nv_bfloat16* Al, int lda, int kg)
{
    if (tid >= 128) return;
    int arow = tid >> 2, ac4 = (tid & 3) * 16;
    size_t off = ((size_t)(r0 + arow) * lda + kg) * 2 + ac4;
    cpa16(st + arow * 80 + ac4, (const char*)Ah + off);
    cpa16(st + 2560 + arow * 80 + ac4, (const char*)Al + off);
}

template<int NTL>
__device__ __forceinline__ void epi_chunk(const float* acc, const float* bias,
                                          char* dst, int wn, int gq, int tg)
{
#pragma unroll
    for (int mt = 0; mt < 2; mt++)
#pragma unroll
        for (int nt = 0; nt < NTL; nt++)
#pragma unroll
            for (int half = 0; half < 2; half++) {
                int row = mt * 16 + gq + half * 8;
                int col = wn + nt * 8 + 2 * tg;
                const float* a = acc + (mt * NTL + nt) * 4 + half * 2;
                float v0 = fmaxf(a[0] + bias[col], 0.f);
                float v1 = fmaxf(a[1] + bias[col + 1], 0.f);
                __nv_bfloat16 h0, l0, h1, l1;
                bsplit(v0, h0, l0); bsplit(v1, h1, l1);
                char* cb = dst + (col >> 5) * 5120;
                int kp = (col & 31) >> 1;
                ((uint32_t*)cb)[row * 20 + kp] = bpack(h0, h1);
                ((uint32_t*)(cb + 2560))[row * 20 + kp] = bpack(l0, l1);
            }
}

__global__ void __launch_bounds__(256) tail_kernel(TailArgs g)
{
    extern __shared__ char sm[];
    char* stages = sm;
    char* tA = sm + 92160;
    char* tB = sm + 133120;
    float* hzc = (float*)tB;

    const int tid = threadIdx.x, lane = tid & 31, warp = tid >> 5;
    const int gq = lane >> 2, tg = lane & 3;
    const int laneoff = (lane & 15) * 80 + (lane >> 4) * 16;
    const int r0 = blockIdx.x * 32;
    constexpr int DST = 46080;
    constexpr int HST = 25600;

    // dec1
    {
        float acc[32];
#pragma unroll
        for (int i = 0; i < 32; i++) acc[i] = 0.f;
        tail_loadA(stages, tid, r0, g.XwH + 320, g.XwL + 320, XK, 0);
        tail_loadB<256,256>(stages + 5120, tid, g_W1T_h, g_W1T_l, Hd, 0);
        CPA_COMMIT();
        for (int kt = 0; kt < 16; kt++) {
            char* cur = stages + (kt & 1) * DST;
            if (kt < 15) {
                char* nxt = stages + ((kt + 1) & 1) * DST;
                tail_loadA(nxt, tid, r0, g.XwH + 320, g.XwL + 320, XK, (kt + 1) * 32);
                tail_loadB<256,256>(nxt + 5120, tid, g_W1T_h, g_W1T_l, Hd, (kt + 1) * 32);
                CPA_COMMIT(); CPA_WAIT1();
            } else CPA_WAIT0();
            __syncthreads();
            stage_mma2<2,4,2560,20480>(cur, cur + 5120, acc, 0, warp * 32, laneoff);
            __syncthreads();
        }
        epi_chunk<4>(acc, g.b1, tA, warp * 32, gq, tg);
        __syncthreads();
    }
    // dec2
    {
        float acc[32];
#pragma unroll
        for (int i = 0; i < 32; i++) acc[i] = 0.f;
        tail_loadB<256,256>(stages + 5120, tid, g_W2T_h, g_W2T_l, Fd, 0);
        CPA_COMMIT();
        for (int kt = 0; kt < 8; kt++) {
            char* cur = stages + (kt & 1) * DST;
            if (kt < 7) {
                tail_loadB<256,256>(stages + ((kt + 1) & 1) * DST + 5120, tid,
                                    g_W2T_h, g_W2T_l, Fd, (kt + 1) * 32);
                CPA_COMMIT(); CPA_WAIT1();
            } else CPA_WAIT0();
            __syncthreads();
            stage_mma2<2,4,2560,20480>(tA + kt * 5120, cur + 5120, acc, 0, warp * 32, laneoff);
            __syncthreads();
        }
        epi_chunk<4>(acc, g.b2, tB, warp * 32, gq, tg);
        __syncthreads();
    }
    // dec3
    {
        float acc[32];
#pragma unroll
        for (int i = 0; i < 32; i++) acc[i] = 0.f;
        tail_loadB<256,256>(stages + 5120, tid, g_W3T_h, g_W3T_l, Fd, 0);
        CPA_COMMIT();
        for (int kt = 0; kt < 8; kt++) {
            char* cur = stages + (kt & 1) * DST;
            if (kt < 7) {
                tail_loadB<256,256>(stages + ((kt + 1) & 1) * DST + 5120, tid,
                                    g_W3T_h, g_W3T_l, Fd, (kt + 1) * 32);
                CPA_COMMIT(); CPA_WAIT1();
            } else CPA_WAIT0();
            __syncthreads();
            stage_mma2<2,4,2560,20480>(tB + kt * 5120, cur + 5120, acc, 0, warp * 32, laneoff);
            __syncthreads();
        }
#pragma unroll
        for (int mt = 0; mt < 2; mt++)
#pragma unroll
            for (int nt = 0; nt < 4; nt++)
#pragma unroll
                for (int half = 0; half < 2; half++) {
                    int row = mt * 16 + gq + half * 8;
                    int col = warp * 32 + nt * 8 + 2 * tg;
                    int b = r0 + row;
                    const float* a = acc + (mt * 4 + nt) * 4 + half * 2;
                    float v0 = fmaxf(a[0] + g.b3[col], 0.f);
                    float v1 = fmaxf(a[1] + g.b3[col + 1], 0.f);
                    *(float2*)&g.fake[(size_t)b * (Td * Fd) + g.t * Fd + col] = make_float2(v0, v1);
                    __nv_bfloat16 h0, l0, h1, l1;
                    bsplit(v0, h0, l0); bsplit(v1, h1, l1);
                    *(__nv_bfloat162*)&g.XwHm[(size_t)b * XK + 64 + col] = bmk2(h0, h1);
                    *(__nv_bfloat162*)&g.XwLm[(size_t)b * XK + 64 + col] = bmk2(l0, l1);
                    char* cb = tA + (col >> 5) * 5120;
                    int kp = (col & 31) >> 1;
                    ((uint32_t*)cb)[row * 20 + kp] = bpack(h0, h1);
                    ((uint32_t*)(cb + 2560))[row * 20 + kp] = bpack(l0, l1);
                }
        __syncthreads();
    }
    // head
    {
        float acc[16];
#pragma unroll
        for (int i = 0; i < 16; i++) acc[i] = 0.f;
        tail_loadA(stages, tid, r0, g.Ch, g.Cl, CK, 0);
        tail_loadB<128,256>(stages + 5120, tid, g_WheadT_h, g_WheadT_l, IK, 0);
        CPA_COMMIT();
        for (int kt = 0; kt < 32; kt++) {
            char* cur = stages + (kt & 1) * HST;
            if (kt < 31) {
                char* nxt = stages + ((kt + 1) & 1) * HST;
                int kn = kt + 1;
                if (kn < 16)       tail_loadA(nxt, tid, r0, g.Ch, g.Cl, CK, kn * 32);
                else if (kn >= 24) tail_loadA(nxt, tid, r0, g.XrH, g.XrL, XK, 64 + (kn - 24) * 32);
                tail_loadB<128,256>(nxt + 5120, tid, g_WheadT_h, g_WheadT_l, IK, kn * 32);
                CPA_COMMIT(); CPA_WAIT1();
            } else CPA_WAIT0();
            __syncthreads();
            const char* Ab = (kt >= 16 && kt < 24) ? (tA + (kt - 16) * 5120) : cur;
            stage_mma2<2,2,2560,10240>(Ab, cur + 5120, acc, 0, warp * 16, laneoff);
            __syncthreads();
        }
#pragma unroll
        for (int mt = 0; mt < 2; mt++)
#pragma unroll
            for (int nt = 0; nt < 2; nt++)
#pragma unroll
                for (int half = 0; half < 2; half++) {
                    int row = mt * 16 + gq + half * 8;
                    int col = warp * 16 + nt * 8 + 2 * tg;
                    const float* a = acc + (mt * 2 + nt) * 4 + half * 2;
                    const float* bz = g.basehz + (size_t)(r0 + row) * 128 + col;
                    hzc[row * 130 + col]     = fmaxf(a[0] + bz[0], 0.f);
                    hzc[row * 130 + col + 1] = fmaxf(a[1] + bz[1], 0.f);
                }
        __syncthreads();
    }
    // finish
    for (int idx = tid; idx < 32 * 64; idx += 256) {
        int row = idx >> 6, z = idx & 63, b = r0 + row;
        float m = g.b5[z], l = g.b6[z], mp = g.b8[z], lp = g.b9[z];
        const float* hz = &hzc[row * 130];
#pragma unroll 8
        for (int k = 0; k < 64; k++) {
            float av = hz[k], ap = hz[64 + k];
            m  += av * g.W5[k * Zd + z];
            l  += av * g.W6[k * Zd + z];
            mp += ap * g.W8[k * Zd + z];
            lp += ap * g.W9[k * Zd + z];
        }
        m = fmaxf(m, 0.f); l = fmaxf(l, 0.f); mp = fmaxf(mp, 0.f); lp = fmaxf(lp, 0.f);
        size_t gi = (size_t)b * Zd + z;
        float zi = m  + g.eps_inf[(size_t)g.t * Bn * Zd + gi] * sqrtf(expf(l));
        float zp = mp + g.eps_pri[(size_t)g.t * Bn * Zd + gi] * sqrtf(expf(lp));
        g.out_mean[(size_t)b * Td * Zd + (size_t)g.t * Zd + z] = m;
        g.out_lv  [(size_t)b * Td * Zd + (size_t)g.t * Zd + z] = l;
        g.out_z[(size_t)(2 * g.t)     * Bn * Zd + gi] = zi;
        g.out_z[(size_t)(2 * g.t + 1) * Bn * Zd + gi] = zp;
        __nv_bfloat16 zh, zl; bsplit(zi, zh, zl);
        g.XwHm[(size_t)b * XK + z] = zh;
        g.XwLm[(size_t)b * XK + z] = zl;
    }
}

// ---------------- single merged prep kernel ----------------
__device__ __forceinline__ int perm_n(int np) {
    int chunk = np >> 7, r = np & 127, gate = r >> 5, w = r & 31;
    return gate * 512 + chunk * 32 + w;
}

__global__ void prep_all(const float* __restrict__ h_i,
                         const float* __restrict__ Wx, const float* __restrict__ Wh,
                         const float* __restrict__ bl,
                         const float* __restrict__ W1, const float* __restrict__ W2,
                         const float* __restrict__ W3,
                         const float* __restrict__ W4, const float* __restrict__ W7,
                         const float* __restrict__ b4, const float* __restrict__ b7)
{
    size_t i = (size_t)blockIdx.x * blockDim.x + threadIdx.x;
    __nv_bfloat16 h, l;

    const size_t nX = (size_t)Bn * XK;
    if (i < nX) {
        __nv_bfloat16 z = __float2bfloat16(0.f);
        g_Xh0[i] = z; g_Xl0[i] = z; g_Xh1[i] = z; g_Xl1[i] = z;
        return;
    }
    i -= nX;
    const size_t nC = (size_t)Bn * Hd;
    if (i < nC) { g_c[i] = 0.f; return; }
    i -= nC;
    if (i < (size_t)Bn * Hd) {
        bsplit(h_i[i], h, l);
        g_hih[i] = h; g_hil[i] = l;
        return;
    }
    i -= (size_t)Bn * Hd;
    if (i < (size_t)Gd * XK) {
        int k = (int)(i % XK), np = (int)(i / XK);
        int n = perm_n(np);
        float v;
        if (k < 64)       v = Wx[(size_t)k * Gd + n];
        else if (k < 320) v = Wx[(size_t)(512 + k) * Gd + n];
        else              v = Wh[(size_t)(k - 320) * Gd + n];
        bsplit(v, h, l);
        g_WcatT_h[i] = h; g_WcatT_l[i] = l;
        return;
    }
    i -= (size_t)Gd * XK;
    if (i < (size_t)Gd * Hd) {
        int k = (int)(i % Hd), np = (int)(i / Hd);
        int n = perm_n(np);
        bsplit(Wx[(size_t)(64 + k) * Gd + n], h, l);
        g_WxhT_h[i] = h; g_WxhT_l[i] = l;
        if (k == 0) g_blstmp[np] = bl[n];
        return;
    }
    i -= (size_t)Gd * Hd;
    if (i < (size_t)Fd * Hd) {
        int k = (int)(i % Hd), n = (int)(i / Hd);
        bsplit(W1[(size_t)k * Fd + n], h, l);
        g_W1T_h[i] = h; g_W1T_l[i] = l;
        return;
    }
    i -= (size_t)Fd * Hd;
    if (i < (size_t)Fd * Fd) {
        int k = (int)(i % Fd), n = (int)(i / Fd);
        bsplit(W2[(size_t)k * Fd + n], h, l);
        g_W2T_h[i] = h; g_W2T_l[i] = l;
        return;
    }
    i -= (size_t)Fd * Fd;
    if (i < (size_t)Fd * Fd) {
        int k = (int)(i % Fd), n = (int)(i / Fd);
        bsplit(W3[(size_t)k * Fd + n], h, l);
        g_W3T_h[i] = h; g_W3T_l[i] = l;
        return;
    }
    i -= (size_t)Fd * Fd;
    if (i < (size_t)128 * IK) {
        int k = (int)(i % IK), n = (int)(i / IK);
        float v;
        if (n < 64) v = W4[(size_t)(512 + k) * Zd + n];
        else {
            int n2 = n - 64;
            if (k < 512)      v = W7[(size_t)(512 + k) * Zd + n2];
            else if (k < 768) v = 0.f;
            else              v = W7[(size_t)(1024 + k - 768) * Zd + n2];
        }
        bsplit(v, h, l);
        g_WheadT_h[i] = h; g_WheadT_l[i] = l;
        return;
    }
    i -= (size_t)128 * IK;
    if (i < (size_t)128 * Hd) {
        int k = (int)(i % Hd), n = (int)(i / Hd);
        float v = (n < 64) ? W4[(size_t)k * Zd + n] : W7[(size_t)k * Zd + (n - 64)];
        bsplit(v, h, l);
        g_WbaseT_h[i] = h; g_WbaseT_l[i] = l;
        if (k == 0) g_bhz[n] = (n < 64) ? b4[n] : b7[n - 64];
    }
}

// ---------------- host ----------------
template<typename T> static T* sym(const void* s) { void* p = nullptr; cudaGetSymbolAddress(&p, s); return (T*)p; }

extern "C" void kernel_launch(void* const* d_in, const int* in_sizes, int n_in,
                              void* d_out, int out_size) {
    const float* h_i     = (const float*)d_in[0];
    const float* eps_inf = (const float*)d_in[1];
    const float* eps_pri = (const float*)d_in[2];
    const float* Wx      = (const float*)d_in[3];
    const float* Wh      = (const float*)d_in[4];
    const float* b_lstm  = (const float*)d_in[5];
    const float* W1 = (const float*)d_in[6],  *b1 = (const float*)d_in[7];
    const float* W2 = (const float*)d_in[8],  *b2 = (const float*)d_in[9];
    const float* W3 = (const float*)d_in[10], *b3 = (const float*)d_in[11];
    const float* W4 = (const float*)d_in[12], *b4 = (const float*)d_in[13];
    const float* W5 = (const float*)d_in[14], *b5 = (const float*)d_in[15];
    const float* W6 = (const float*)d_in[16], *b6 = (const float*)d_in[17];
    const float* W7 = (const float*)d_in[18], *b7 = (const float*)d_in[19];
    const float* W8 = (const float*)d_in[20], *b8 = (const float*)d_in[21];
    const float* W9 = (const float*)d_in[22], *b9 = (const float*)d_in[23];

    float* out      = (float*)d_out;
    float* out_fake = out;
    float* out_mean = out_fake + (size_t)Bn * Td * Fd;
    float* out_lv   = out_mean + (size_t)Bn * Td * Zd;
    float* out_z    = out_lv   + (size_t)Bn * Td * Zd;

    __nv_bfloat16* Xh0 = sym<__nv_bfloat16>(g_Xh0); __nv_bfloat16* Xl0 = sym<__nv_bfloat16>(g_Xl0);
    __nv_bfloat16* Xh1 = sym<__nv_bfloat16>(g_Xh1); __nv_bfloat16* Xl1 = sym<__nv_bfloat16>(g_Xl1);
    __nv_bfloat16* Ch  = sym<__nv_bfloat16>(g_Ch);  __nv_bfloat16* Cl  = sym<__nv_bfloat16>(g_Cl);

    float* pBaseg  = sym<float>(g_baseg);
    float* pBasehz = sym<float>(g_basehz);
    float* pBlstmp = sym<float>(g_blstmp);
    float* pBhz    = sym<float>(g_bhz);

    constexpr int SMGATE  = 3 * (256 + 128) * 160;   // 184320
    constexpr int SMSMALL = 3 * (64 + 64) * 160;     // 61440
    constexpr int SMTAIL  = 174080;
    cudaFuncSetAttribute(gemm<256,128,64,64,256,0,1>, cudaFuncAttributeMaxDynamicSharedMemorySize, SMGATE);
    cudaFuncSetAttribute(gemm<256,128,64,64,256,1,2>, cudaFuncAttributeMaxDynamicSharedMemorySize, SMGATE);
    cudaFuncSetAttribute(gemm<64,64,32,32,128,0,1>,   cudaFuncAttributeMaxDynamicSharedMemorySize, SMSMALL);
    cudaFuncSetAttribute(tail_kernel,                 cudaFuncAttributeMaxDynamicSharedMemorySize, SMTAIL);

    // ---- init (single launch) ----
    {
        size_t tot = (size_t)Bn * XK + 2 * (size_t)Bn * Hd
                   + (size_t)Gd * XK + (size_t)Gd * Hd
                   + (size_t)Fd * Hd + 2 * (size_t)Fd * Fd
                   + (size_t)128 * IK + (size_t)128 * Hd;
        prep_all<<<(unsigned)((tot + 255) / 256), 256>>>(h_i, Wx, Wh, b_lstm,
                                                         W1, W2, W3, W4, W7, b4, b7);
    }

    // ---- hoisted base GEMMs ----
    {
        GArgs b{};
        b.Ah = sym<__nv_bfloat16>(g_hih); b.Al = sym<__nv_bfloat16>(g_hil); b.lda = Hd;
        b.Bh = sym<__nv_bfloat16>(g_WxhT_h); b.Bl = sym<__nv_bfloat16>(g_WxhT_l); b.ldb = Hd;
        b.Ci = pBlstmp; b.C = pBaseg; b.ldc = Gd; b.K = Hd;
        gemm<256,128,64,64,256,0,1><<<dim3(16, 16), 256, SMGATE>>>(b);

        b.Bh = sym<__nv_bfloat16>(g_WbaseT_h); b.Bl = sym<__nv_bfloat16>(g_WbaseT_l); b.ldb = Hd;
        b.Ci = pBhz; b.C = pBasehz; b.ldc = 128; b.K = Hd;
        gemm<64,64,32,32,128,0,1><<<dim3(2, 64), 128, SMSMALL>>>(b);
    }

    for (int t = 0; t < Td; t++) {
        __nv_bfloat16* XrH = (t & 1) ? Xh1 : Xh0;
        __nv_bfloat16* XrL = (t & 1) ? Xl1 : Xl0;
        __nv_bfloat16* XwH = (t & 1) ? Xh0 : Xh1;
        __nv_bfloat16* XwL = (t & 1) ? Xl0 : Xl1;

        {
            GArgs b{};
            b.Ah = XrH; b.Al = XrL; b.lda = XK;
            b.Bh = sym<__nv_bfloat16>(g_WcatT_h); b.Bl = sym<__nv_bfloat16>(g_WcatT_l); b.ldb = XK;
            b.Ci = pBaseg; b.ldci = Gd; b.K = XK;
            b.cst = sym<float>(g_c);
            b.Xh = XwH; b.Xl = XwL;
            b.Ch = Ch; b.Cl = Cl;
            gemm<256,128,64,64,256,1,2><<<dim3(16, 16), 256, SMGATE>>>(b);
        }
        {
            TailArgs ta{};
            ta.XwH = XwH; ta.XwL = XwL; ta.XwHm = XwH; ta.XwLm = XwL;
            ta.XrH = XrH; ta.XrL = XrL;
            ta.Ch = Ch; ta.Cl = Cl;
            ta.basehz = pBasehz;
            ta.b1 = b1; ta.b2 = b2; ta.b3 = b3;
            ta.W5 = W5; ta.b5 = b5; ta.W6 = W6; ta.b6 = b6;
            ta.W8 = W8; ta.b8 = b8; ta.W9 = W9; ta.b9 = b9;
            ta.eps_inf = eps_inf; ta.eps_pri = eps_pri;
            ta.fake = out_fake; ta.out_mean = out_mean; ta.out_lv = out_lv; ta.out_z = out_z;
            ta.t = t;
            tail_kernel<<<Bn / 32, 256, SMTAIL>>>(ta);
        }
    }
}

// round 11
// speedup vs baseline: 1.0507x; 1.0507x over previous
#include <cuda_runtime.h>
#include <cuda.h>
#include <cuda_bf16.h>
#include <math.h>
#include <stdint.h>

#define Bn   4096
#define Hd   512
#define Fd   256
#define Zd   64
#define Td   16
#define Gd   2048
#define XK   832      // bf16 X row: [z(64) | y(256) | h(512)]
#define IK   1024     // head K:     [c(512) | y_j(256) | y_prev(256)]
#define CK   512      // c buffer row

// ---------------- persistent buffers ----------------
__device__ float g_baseg [(size_t)Bn * Gd];
__device__ float g_basehz[Bn * 128];
__device__ float g_c     [Bn * Hd];
__device__ float g_blstmp[Gd];
__device__ float g_bhz   [128];

__device__ __nv_bfloat16 g_Xh0[(size_t)Bn * XK], g_Xl0[(size_t)Bn * XK];
__device__ __nv_bfloat16 g_Xh1[(size_t)Bn * XK], g_Xl1[(size_t)Bn * XK];
__device__ __nv_bfloat16 g_Ch [(size_t)Bn * CK], g_Cl [(size_t)Bn * CK];
__device__ __nv_bfloat16 g_hih[(size_t)Bn * Hd], g_hil[(size_t)Bn * Hd];

__device__ __nv_bfloat16 g_WcatT_h[(size_t)Gd * XK], g_WcatT_l[(size_t)Gd * XK];
__device__ __nv_bfloat16 g_WxhT_h [(size_t)Gd * Hd], g_WxhT_l [(size_t)Gd * Hd];
__device__ __nv_bfloat16 g_W1T_h  [Fd * Hd], g_W1T_l  [Fd * Hd];
__device__ __nv_bfloat16 g_W2T_h  [Fd * Fd], g_W2T_l  [Fd * Fd];
__device__ __nv_bfloat16 g_W3T_h  [Fd * Fd], g_W3T_l  [Fd * Fd];
__device__ __nv_bfloat16 g_WheadT_h[128 * IK], g_WheadT_l[128 * IK];
__device__ __nv_bfloat16 g_WbaseT_h[128 * Hd], g_WbaseT_l[128 * Hd];

// ---------------- helpers ----------------
__device__ __forceinline__ void bsplit(float v, __nv_bfloat16& h, __nv_bfloat16& l) {
    h = __float2bfloat16_rn(v);
    l = __float2bfloat16_rn(v - __bfloat162float(h));
}
__device__ __forceinline__ uint32_t bpack(__nv_bfloat16 a, __nv_bfloat16 b) {
    __nv_bfloat162 t; t.x = a; t.y = b;
    return reinterpret_cast<uint32_t&>(t);
}
__device__ __forceinline__ __nv_bfloat162 bmk2(__nv_bfloat16 a, __nv_bfloat16 b) {
    __nv_bfloat162 t; t.x = a; t.y = b; return t;
}
__device__ __forceinline__ void mma16816(float* c, const uint32_t* a, const uint32_t* b) {
    asm volatile(
        "mma.sync.aligned.m16n8k16.row.col.f32.bf16.bf16.f32 "
        "{%0,%1,%2,%3}, {%4,%5,%6,%7}, {%8,%9}, {%0,%1,%2,%3};\n"
        : "+f"(c[0]), "+f"(c[1]), "+f"(c[2]), "+f"(c[3])
        : "r"(a[0]), "r"(a[1]), "r"(a[2]), "r"(a[3]), "r"(b[0]), "r"(b[1]));
}
__device__ __forceinline__ void ldsm4(uint32_t& r0, uint32_t& r1, uint32_t& r2, uint32_t& r3,
                                      uint32_t addr) {
    asm volatile("ldmatrix.sync.aligned.m8n8.x4.shared.b16 {%0,%1,%2,%3}, [%4];"
        : "=r"(r0), "=r"(r1), "=r"(r2), "=r"(r3) : "r"(addr));
}
__device__ __forceinline__ void cpa16(void* dst, const void* src) {
    uint32_t d = (uint32_t)__cvta_generic_to_shared(dst);
    asm volatile("cp.async.cg.shared.global [%0], [%1], 16;\n" :: "r"(d), "l"(src));
}
#define CPA_COMMIT() asm volatile("cp.async.commit_group;\n")
#define CPA_WAIT1()  asm volatile("cp.async.wait_group 1;\n")
#define CPA_WAIT0()  asm volatile("cp.async.wait_group 0;\n")

__device__ __forceinline__ uint32_t smem_u32(const void* p) {
    return (uint32_t)__cvta_generic_to_shared(p);
}

// ---- TMA / mbarrier (sm_90 baseline PTX; no arch-'a' features) ----
#define MBAR_INIT(a, n) \
    asm volatile("mbarrier.init.shared.b64 [%0], %1;" :: "r"(a), "r"(n) : "memory")
#define MBAR_EXPECT_TX(a, bytes) \
    asm volatile("mbarrier.arrive.expect_tx.shared.b64 _, [%0], %1;" :: "r"(a), "r"(bytes) : "memory")
#define MBAR_WAIT(a, par) do { \
    asm volatile("{\n\t.reg .pred P1;\n\tWL%=:\n\t" \
        "mbarrier.try_wait.parity.acquire.cta.shared::cta.b64 P1, [%0], %1, 0x989680;\n\t" \
        "@P1 bra.uni WD%=;\n\tbra.uni WL%=;\n\tWD%=:\n\t}" \
        :: "r"(a), "r"(par) : "memory"); \
} while (0)
#define TMA2D(dst, mapp, cx, cy, mb) \
    asm volatile("cp.async.bulk.tensor.2d.shared::cta.global.tile.mbarrier::complete_tx::bytes " \
        "[%0], [%1, {%2, %3}], [%4];" \
        :: "r"(dst), "l"(mapp), "r"(cx), "r"(cy), "r"(mb) : "memory")

// ================= TMA + mma.sync gate kernel =================
// 128x128 block tile, 13 K-chunks of 64. Tiles land SW128-swizzled (128B rows):
// element row r, 16B-chunk c lives at r*128 + ((c ^ (r&7))<<4).
__global__ void __launch_bounds__(256) gate_tma(
    const __grid_constant__ CUtensorMap mAh,
    const __grid_constant__ CUtensorMap mAl,
    const __grid_constant__ CUtensorMap mBh,
    const __grid_constant__ CUtensorMap mBl,
    const float* __restrict__ baseg, float* __restrict__ cst,
    __nv_bfloat16* __restrict__ Xh, __nv_bfloat16* __restrict__ Xl,
    __nv_bfloat16* __restrict__ Chp, __nv_bfloat16* __restrict__ Clp)
{
    extern __shared__ char sm[];
    const uint32_t sb = smem_u32(sm);
    const int tid = threadIdx.x, warp = tid >> 5, lane = tid & 31;
    const int bm = blockIdx.y * 128, bn = blockIdx.x * 128;
    const uint32_t F0 = sb + 8, F1 = sb + 16;
    const int wm = (warp >> 2) * 64, wn = (warp & 3) * 32;   // 2x4 warps, 64x32 tiles
    const int gq = lane >> 2, tg = lane & 3;
    const int ch = lane >> 4, r7 = lane & 7;
    const int lrow = (lane & 15) * 128;

    if (tid == 0) { MBAR_INIT(F0, 1); MBAR_INIT(F1, 1); }
    __syncthreads();

    float acc[64];
#pragma unroll
    for (int i = 0; i < 64; i++) acc[i] = 0.f;

    // prologue: chunks 0,1
    if (tid == 0) {
        MBAR_EXPECT_TX(F0, 65536);
        uint32_t d = sb + 1024;
        TMA2D(d,         &mAh, 0, bm, F0);
        TMA2D(d + 16384, &mAl, 0, bm, F0);
        TMA2D(d + 32768, &mBh, 0, bn, F0);
        TMA2D(d + 49152, &mBl, 0, bn, F0);
        MBAR_EXPECT_TX(F1, 65536);
        d = sb + 1024 + 65536;
        TMA2D(d,         &mAh, 64, bm, F1);
        TMA2D(d + 16384, &mAl, 64, bm, F1);
        TMA2D(d + 32768, &mBh, 64, bn, F1);
        TMA2D(d + 49152, &mBl, 64, bn, F1);
    }

    int pf0 = 0, pf1 = 0;
    for (int c = 0; c <= 12; c++) {
        if ((c & 1) == 0) { MBAR_WAIT(F0, pf0); pf0 ^= 1; }
        else              { MBAR_WAIT(F1, pf1); pf1 ^= 1; }
        const uint32_t bo = sb + 1024 + (c & 1) * 65536;
        const uint32_t aH = bo, aL = bo + 16384, bH = bo + 32768, bL = bo + 49152;
#pragma unroll
        for (int g = 0; g < 4; g++) {
            const int xo = (((2 * g + ch) ^ r7) << 4) + lrow;
            uint32_t bhf[4][2], blf[4][2];
#pragma unroll
            for (int np = 0; np < 2; np++) {
                uint32_t r0, r1, r2, r3;
                ldsm4(r0, r1, r2, r3, bH + (wn + np * 16) * 128 + xo);
                bhf[2*np][0] = r0; bhf[2*np+1][0] = r1; bhf[2*np][1] = r2; bhf[2*np+1][1] = r3;
                ldsm4(r0, r1, r2, r3, bL + (wn + np * 16) * 128 + xo);
                blf[2*np][0] = r0; blf[2*np+1][0] = r1; blf[2*np][1] = r2; blf[2*np+1][1] = r3;
            }
#pragma unroll
            for (int mt = 0; mt < 4; mt++) {
                uint32_t ah[4], al[4];
                ldsm4(ah[0], ah[1], ah[2], ah[3], aH + (wm + mt * 16) * 128 + xo);
                ldsm4(al[0], al[1], al[2], al[3], aL + (wm + mt * 16) * 128 + xo);
#pragma unroll
                for (int nt = 0; nt < 4; nt++) {
                    float* a = acc + (mt * 4 + nt) * 4;
                    mma16816(a, ah, bhf[nt]);
                    mma16816(a, ah, blf[nt]);
                    mma16816(a, al, bhf[nt]);
                }
            }
        }
        __syncthreads();
        if (tid == 0 && c + 2 <= 12) {
            const uint32_t mb = (c & 1) ? F1 : F0;
            MBAR_EXPECT_TX(mb, 65536);
            const uint32_t d = sb + 1024 + (c & 1) * 65536;
            const int kc = (c + 2) * 64;
            TMA2D(d,         &mAh, kc, bm, mb);
            TMA2D(d + 16384, &mAl, kc, bm, mb);
            TMA2D(d + 32768, &mBh, kc, bn, mb);
            TMA2D(d + 49152, &mBl, kc, bn, mb);
        }
    }

    // ---- epilogue: stage raw acc, then row-coalesced LSTM ----
    float* tile = (float*)(sm + 1024);   // 128x128 fp32 = 64KB (reuses buf0)
#pragma unroll
    for (int mt = 0; mt < 4; mt++)
#pragma unroll
        for (int nt = 0; nt < 4; nt++) {
            int r0 = wm + mt * 16 + gq, c0 = wn + nt * 8 + 2 * tg;
            float* a = acc + (mt * 4 + nt) * 4;
            tile[r0 * 128 + c0]           = a[0];
            tile[r0 * 128 + c0 + 1]       = a[1];
            tile[(r0 + 8) * 128 + c0]     = a[2];
            tile[(r0 + 8) * 128 + c0 + 1] = a[3];
        }
    __syncthreads();

    for (int idx = tid; idx < 128 * 32; idx += 256) {
        int row = idx >> 5, w = idx & 31;
        int b = bm + row, jg = blockIdx.x * 32 + w;
        const float* bg = baseg + (size_t)b * Gd + bn;
        float ig = tile[row * 128 + w]      + bg[w];
        float fg = tile[row * 128 + 32 + w] + bg[32 + w];
        float gg = tile[row * 128 + 64 + w] + bg[64 + w];
        float og = tile[row * 128 + 96 + w] + bg[96 + w];
        float si = 1.f / (1.f + expf(-ig));
        float sf = 1.f / (1.f + expf(-fg));
        float so = 1.f / (1.f + expf(-og));
        float cn = sf * cst[b * Hd + jg] + si * tanhf(gg);
        float hn = so * tanhf(cn);
        cst[b * Hd + jg] = cn;
        __nv_bfloat16 hh, hl, cc, cl;
        bsplit(hn, hh, hl); bsplit(cn, cc, cl);
        Xh[(size_t)b * XK + 320 + jg] = hh;
        Xl[(size_t)b * XK + 320 + jg] = hl;
        Chp[(size_t)b * CK + jg] = cc;
        Clp[(size_t)b * CK + jg] = cl;
    }
}

// ================= mma.sync GEMM (base GEMMs; 80B-row layout) =================
struct GArgs {
    const __nv_bfloat16 *Ah, *Al; int lda;
    const __nv_bfloat16 *Bh, *Bl; int ldb;
    const float* Ci; int ldci;
    float* C; int ldc;
    int K;
};

template<int MT,int NTL,int AHS,int BHS>
__device__ __forceinline__ void stage_mma2(const char* Ab, const char* Bb, float* acc,
                                           int wm, int wn, int laneoff)
{
    uint32_t aH = smem_u32(Ab) + laneoff;
    uint32_t bH = smem_u32(Bb) + laneoff;
#pragma unroll
    for (int kk = 0; kk < 2; kk++) {
        const int kb = kk * 32;
        uint32_t bhf[NTL][2], blf[NTL][2];
#pragma unroll
        for (int np = 0; np < NTL / 2; np++) {
            uint32_t r0, r1, r2, r3;
            ldsm4(r0, r1, r2, r3, bH + (wn + np * 16) * 80 + kb);
            bhf[2*np][0] = r0; bhf[2*np+1][0] = r1; bhf[2*np][1] = r2; bhf[2*np+1][1] = r3;
            ldsm4(r0, r1, r2, r3, bH + BHS + (wn + np * 16) * 80 + kb);
            blf[2*np][0] = r0; blf[2*np+1][0] = r1; blf[2*np][1] = r2; blf[2*np+1][1] = r3;
        }
#pragma unroll
        for (int mt = 0; mt < MT; mt++) {
            uint32_t ah[4], al[4];
            ldsm4(ah[0], ah[1], ah[2], ah[3], aH + (wm + mt * 16) * 80 + kb);
            ldsm4(al[0], al[1], al[2], al[3], aH + AHS + (wm + mt * 16) * 80 + kb);
#pragma unroll
            for (int nt = 0; nt < NTL; nt++) {
                float* a = acc + (mt * NTL + nt) * 4;
                mma16816(a, ah, bhf[nt]);
                mma16816(a, ah, blf[nt]);
                mma16816(a, al, bhf[nt]);
            }
        }
    }
}

template<int BM,int BN,int NTH>
__device__ __forceinline__ void stage_load(char* base, int tid, int bm, int bn,
    const __nv_bfloat16* Ah, const __nv_bfloat16* Al, int lda,
    const __nv_bfloat16* Bh, const __nv_bfloat16* Bl, int ldb, int k0)
{
#pragma unroll
    for (int i = tid; i < BM * 4; i += NTH) {
        int row = i >> 2, c4 = (i & 3) * 16;
        size_t off = ((size_t)(bm + row) * lda + k0) * 2 + c4;
        cpa16(base + row * 80 + c4, (const char*)Ah + off);
        cpa16(base + BM * 80 + row * 80 + c4, (const char*)Al + off);
    }
#pragma unroll
    for (int i = tid; i < BN * 4; i += NTH) {
        int row = i >> 2, c4 = (i & 3) * 16;
        size_t off = ((size_t)(bn + row) * ldb + k0) * 2 + c4;
        cpa16(base + BM * 160 + row * 80 + c4, (const char*)Bh + off);
        cpa16(base + BM * 160 + BN * 80 + row * 80 + c4, (const char*)Bl + off);
    }
    CPA_COMMIT();
}

template<int BM,int BN,int WM,int WN,int NTH>
__global__ void __launch_bounds__(NTH) gemm(GArgs g)
{
    extern __shared__ char sm[];
    constexpr int MT = WM / 16, NTL = WN / 8, NWN = BN / WN;
    constexpr int stageB = (BM + BN) * 160;
    const int tid = threadIdx.x, warp = tid >> 5, lane = tid & 31;
    const int gq = lane >> 2, tg = lane & 3;
    const int laneoff = (lane & 15) * 80 + (lane >> 4) * 16;
    const int wm = (warp / NWN) * WM, wn = (warp % NWN) * WN;
    const int bm = blockIdx.y * BM, bn = blockIdx.x * BN;
    const int K = g.K;

    float acc[MT * NTL * 4];
#pragma unroll
    for (int i = 0; i < MT * NTL * 4; i++) acc[i] = 0.f;

    const int nk = K >> 5;
    stage_load<BM,BN,NTH>(sm, tid, bm, bn, g.Ah, g.Al, g.lda, g.Bh, g.Bl, g.ldb, 0);
    for (int kt = 0; kt < nk; kt++) {
        if (kt + 1 < nk) {
            stage_load<BM,BN,NTH>(sm + ((kt + 1) & 1) * stageB, tid, bm, bn,
                                  g.Ah, g.Al, g.lda, g.Bh, g.Bl, g.ldb, (kt + 1) << 5);
            CPA_WAIT1();
        } else CPA_WAIT0();
        __syncthreads();
        const char* cur = sm + (kt & 1) * stageB;
        stage_mma2<MT,NTL,BM*80,BN*80>(cur, cur + BM * 160, acc, wm, wn, laneoff);
        __syncthreads();
    }

#pragma unroll
    for (int mt = 0; mt < MT; mt++)
#pragma unroll
        for (int nt = 0; nt < NTL; nt++) {
            float* a = acc + (mt * NTL + nt) * 4;
#pragma unroll
            for (int half = 0; half < 2; half++) {
                int r = bm + wm + mt * 16 + gq + half * 8;
                int c = bn + wn + nt * 8 + 2 * tg;
                float v0 = a[half * 2] + g.Ci[c], v1 = a[half * 2 + 1] + g.Ci[c + 1];
                *(float2*)&g.C[(size_t)r * g.ldc + c] = make_float2(v0, v1);
            }
        }
}

// ================= fused tail kernel (unchanged) =================
struct TailArgs {
    const __nv_bfloat16 *XwH, *XwL;
    __nv_bfloat16 *XwHm, *XwLm;
    const __nv_bfloat16 *XrH, *XrL;
    const __nv_bfloat16 *Ch, *Cl;
    const float* basehz;
    const float *b1, *b2, *b3;
    const float *W5, *b5, *W6, *b6, *W8, *b8, *W9, *b9;
    const float *eps_inf, *eps_pri;
    float *fake, *out_mean, *out_lv, *out_z;
    int t;
};

template<int BN,int NTH>
__device__ __forceinline__ void tail_loadB(char* st, int tid,
    const __nv_bfloat16* Bh, const __nv_bfloat16* Bl, int ldb, int kg)
{
#pragma unroll
    for (int i = tid; i < BN * 4; i += NTH) {
        int row = i >> 2, c4 = (i & 3) * 16;
        size_t off = ((size_t)row * ldb + kg) * 2 + c4;
        cpa16(st + row * 80 + c4, (const char*)Bh + off);
        cpa16(st + BN * 80 + row * 80 + c4, (const char*)Bl + off);
    }
}

__device__ __forceinline__ void tail_loadA(char* st, int tid, int r0,
    const __nv_bfloat16* Ah, const __nv_bfloat16* Al, int lda, int kg)
{
    if (tid >= 128) return;
    int arow = tid >> 2, ac4 = (tid & 3) * 16;
    size_t off = ((size_t)(r0 + arow) * lda + kg) * 2 + ac4;
    cpa16(st + arow * 80 + ac4, (const char*)Ah + off);
    cpa16(st + 2560 + arow * 80 + ac4, (const char*)Al + off);
}

template<int NTL>
__device__ __forceinline__ void epi_chunk(const float* acc, const float* bias,
                                          char* dst, int wn, int gq, int tg)
{
#pragma unroll
    for (int mt = 0; mt < 2; mt++)
#pragma unroll
        for (int nt = 0; nt < NTL; nt++)
#pragma unroll
            for (int half = 0; half < 2; half++) {
                int row = mt * 16 + gq + half * 8;
                int col = wn + nt * 8 + 2 * tg;
                const float* a = acc + (mt * NTL + nt) * 4 + half * 2;
                float v0 = fmaxf(a[0] + bias[col], 0.f);
                float v1 = fmaxf(a[1] + bias[col + 1], 0.f);
                __nv_bfloat16 h0, l0, h1, l1;
                bsplit(v0, h0, l0); bsplit(v1, h1, l1);
                char* cb = dst + (col >> 5) * 5120;
                int kp = (col & 31) >> 1;
                ((uint32_t*)cb)[row * 20 + kp] = bpack(h0, h1);
                ((uint32_t*)(cb + 2560))[row * 20 + kp] = bpack(l0, l1);
            }
}

__global__ void __launch_bounds__(256) tail_kernel(TailArgs g)
{
    extern __shared__ char sm[];
    char* stages = sm;
    char* tA = sm + 92160;
    char* tB = sm + 133120;
    float* hzc = (float*)tB;

    const int tid = threadIdx.x, lane = tid & 31, warp = tid >> 5;
    const int gq = lane >> 2, tg = lane & 3;
    const int laneoff = (lane & 15) * 80 + (lane >> 4) * 16;
    const int r0 = blockIdx.x * 32;
    constexpr int DST = 46080;
    constexpr int HST = 25600;

    // dec1
    {
        float acc[32];
#pragma unroll
        for (int i = 0; i < 32; i++) acc[i] = 0.f;
        tail_loadA(stages, tid, r0, g.XwH + 320, g.XwL + 320, XK, 0);
        tail_loadB<256,256>(stages + 5120, tid, g_W1T_h, g_W1T_l, Hd, 0);
        CPA_COMMIT();
        for (int kt = 0; kt < 16; kt++) {
            char* cur = stages + (kt & 1) * DST;
            if (kt < 15) {
                char* nxt = stages + ((kt + 1) & 1) * DST;
                tail_loadA(nxt, tid, r0, g.XwH + 320, g.XwL + 320, XK, (kt + 1) * 32);
                tail_loadB<256,256>(nxt + 5120, tid, g_W1T_h, g_W1T_l, Hd, (kt + 1) * 32);
                CPA_COMMIT(); CPA_WAIT1();
            } else CPA_WAIT0();
            __syncthreads();
            stage_mma2<2,4,2560,20480>(cur, cur + 5120, acc, 0, warp * 32, laneoff);
            __syncthreads();
        }
        epi_chunk<4>(acc, g.b1, tA, warp * 32, gq, tg);
        __syncthreads();
    }
    // dec2
    {
        float acc[32];
#pragma unroll
        for (int i = 0; i < 32; i++) acc[i] = 0.f;
        tail_loadB<256,256>(stages + 5120, tid, g_W2T_h, g_W2T_l, Fd, 0);
        CPA_COMMIT();
        for (int kt = 0; kt < 8; kt++) {
            char* cur = stages + (kt & 1) * DST;
            if (kt < 7) {
                tail_loadB<256,256>(stages + ((kt + 1) & 1) * DST + 5120, tid,
                                    g_W2T_h, g_W2T_l, Fd, (kt + 1) * 32);
                CPA_COMMIT(); CPA_WAIT1();
            } else CPA_WAIT0();
            __syncthreads();
            stage_mma2<2,4,2560,20480>(tA + kt * 5120, cur + 5120, acc, 0, warp * 32, laneoff);
            __syncthreads();
        }
        epi_chunk<4>(acc, g.b2, tB, warp * 32, gq, tg);
        __syncthreads();
    }
    // dec3
    {
        float acc[32];
#pragma unroll
        for (int i = 0; i < 32; i++) acc[i] = 0.f;
        tail_loadB<256,256>(stages + 5120, tid, g_W3T_h, g_W3T_l, Fd, 0);
        CPA_COMMIT();
        for (int kt = 0; kt < 8; kt++) {
            char* cur = stages + (kt & 1) * DST;
            if (kt < 7) {
                tail_loadB<256,256>(stages + ((kt + 1) & 1) * DST + 5120, tid,
                                    g_W3T_h, g_W3T_l, Fd, (kt + 1) * 32);
                CPA_COMMIT(); CPA_WAIT1();
            } else CPA_WAIT0();
            __syncthreads();
            stage_mma2<2,4,2560,20480>(tB + kt * 5120, cur + 5120, acc, 0, warp * 32, laneoff);
            __syncthreads();
        }
#pragma unroll
        for (int mt = 0; mt < 2; mt++)
#pragma unroll
            for (int nt = 0; nt < 4; nt++)
#pragma unroll
                for (int half = 0; half < 2; half++) {
                    int row = mt * 16 + gq + half * 8;
                    int col = warp * 32 + nt * 8 + 2 * tg;
                    int b = r0 + row;
                    const float* a = acc + (mt * 4 + nt) * 4 + half * 2;
                    float v0 = fmaxf(a[0] + g.b3[col], 0.f);
                    float v1 = fmaxf(a[1] + g.b3[col + 1], 0.f);
                    *(float2*)&g.fake[(size_t)b * (Td * Fd) + g.t * Fd + col] = make_float2(v0, v1);
                    __nv_bfloat16 h0, l0, h1, l1;
                    bsplit(v0, h0, l0); bsplit(v1, h1, l1);
                    *(__nv_bfloat162*)&g.XwHm[(size_t)b * XK + 64 + col] = bmk2(h0, h1);
                    *(__nv_bfloat162*)&g.XwLm[(size_t)b * XK + 64 + col] = bmk2(l0, l1);
                    char* cb = tA + (col >> 5) * 5120;
                    int kp = (col & 31) >> 1;
                    ((uint32_t*)cb)[row * 20 + kp] = bpack(h0, h1);
                    ((uint32_t*)(cb + 2560))[row * 20 + kp] = bpack(l0, l1);
                }
        __syncthreads();
    }
    // head
    {
        float acc[16];
#pragma unroll
        for (int i = 0; i < 16; i++) acc[i] = 0.f;
        tail_loadA(stages, tid, r0, g.Ch, g.Cl, CK, 0);
        tail_loadB<128,256>(stages + 5120, tid, g_WheadT_h, g_WheadT_l, IK, 0);
        CPA_COMMIT();
        for (int kt = 0; kt < 32; kt++) {
            char* cur = stages + (kt & 1) * HST;
            if (kt < 31) {
                char* nxt = stages + ((kt + 1) & 1) * HST;
                int kn = kt + 1;
                if (kn < 16)       tail_loadA(nxt, tid, r0, g.Ch, g.Cl, CK, kn * 32);
                else if (kn >= 24) tail_loadA(nxt, tid, r0, g.XrH, g.XrL, XK, 64 + (kn - 24) * 32);
                tail_loadB<128,256>(nxt + 5120, tid, g_WheadT_h, g_WheadT_l, IK, kn * 32);
                CPA_COMMIT(); CPA_WAIT1();
            } else CPA_WAIT0();
            __syncthreads();
            const char* Ab = (kt >= 16 && kt < 24) ? (tA + (kt - 16) * 5120) : cur;
            stage_mma2<2,2,2560,10240>(Ab, cur + 5120, acc, 0, warp * 16, laneoff);
            __syncthreads();
        }
#pragma unroll
        for (int mt = 0; mt < 2; mt++)
#pragma unroll
            for (int nt = 0; nt < 2; nt++)
#pragma unroll
                for (int half = 0; half < 2; half++) {
                    int row = mt * 16 + gq + half * 8;
                    int col = warp * 16 + nt * 8 + 2 * tg;
                    const float* a = acc + (mt * 2 + nt) * 4 + half * 2;
                    const float* bz = g.basehz + (size_t)(r0 + row) * 128 + col;
                    hzc[row * 130 + col]     = fmaxf(a[0] + bz[0], 0.f);
                    hzc[row * 130 + col + 1] = fmaxf(a[1] + bz[1], 0.f);
                }
        __syncthreads();
    }
    // finish
    for (int idx = tid; idx < 32 * 64; idx += 256) {
        int row = idx >> 6, z = idx & 63, b = r0 + row;
        float m = g.b5[z], l = g.b6[z], mp = g.b8[z], lp = g.b9[z];
        const float* hz = &hzc[row * 130];
#pragma unroll 8
        for (int k = 0; k < 64; k++) {
            float av = hz[k], ap = hz[64 + k];
            m  += av * g.W5[k * Zd + z];
            l  += av * g.W6[k * Zd + z];
            mp += ap * g.W8[k * Zd + z];
            lp += ap * g.W9[k * Zd + z];
        }
        m = fmaxf(m, 0.f); l = fmaxf(l, 0.f); mp = fmaxf(mp, 0.f); lp = fmaxf(lp, 0.f);
        size_t gi = (size_t)b * Zd + z;
        float zi = m  + g.eps_inf[(size_t)g.t * Bn * Zd + gi] * sqrtf(expf(l));
        float zp = mp + g.eps_pri[(size_t)g.t * Bn * Zd + gi] * sqrtf(expf(lp));
        g.out_mean[(size_t)b * Td * Zd + (size_t)g.t * Zd + z] = m;
        g.out_lv  [(size_t)b * Td * Zd + (size_t)g.t * Zd + z] = l;
        g.out_z[(size_t)(2 * g.t)     * Bn * Zd + gi] = zi;
        g.out_z[(size_t)(2 * g.t + 1) * Bn * Zd + gi] = zp;
        __nv_bfloat16 zh, zl; bsplit(zi, zh, zl);
        g.XwHm[(size_t)b * XK + z] = zh;
        g.XwLm[(size_t)b * XK + z] = zl;
    }
}

// ---------------- single merged prep kernel ----------------
__device__ __forceinline__ int perm_n(int np) {
    int chunk = np >> 7, r = np & 127, gate = r >> 5, w = r & 31;
    return gate * 512 + chunk * 32 + w;
}

__global__ void prep_all(const float* __restrict__ h_i,
                         const float* __restrict__ Wx, const float* __restrict__ Wh,
                         const float* __restrict__ bl,
                         const float* __restrict__ W1, const float* __restrict__ W2,
                         const float* __restrict__ W3,
                         const float* __restrict__ W4, const float* __restrict__ W7,
                         const float* __restrict__ b4, const float* __restrict__ b7)
{
    size_t i = (size_t)blockIdx.x * blockDim.x + threadIdx.x;
    __nv_bfloat16 h, l;

    const size_t nX = (size_t)Bn * XK;
    if (i < nX) {
        __nv_bfloat16 z = __float2bfloat16(0.f);
        g_Xh0[i] = z; g_Xl0[i] = z; g_Xh1[i] = z; g_Xl1[i] = z;
        return;
    }
    i -= nX;
    const size_t nC = (size_t)Bn * Hd;
    if (i < nC) { g_c[i] = 0.f; return; }
    i -= nC;
    if (i < (size_t)Bn * Hd) {
        bsplit(h_i[i], h, l);
        g_hih[i] = h; g_hil[i] = l;
        return;
    }
    i -= (size_t)Bn * Hd;
    if (i < (size_t)Gd * XK) {
        int k = (int)(i % XK), np = (int)(i / XK);
        int n = perm_n(np);
        float v;
        if (k < 64)       v = Wx[(size_t)k * Gd + n];
        else if (k < 320) v = Wx[(size_t)(512 + k) * Gd + n];
        else              v = Wh[(size_t)(k - 320) * Gd + n];
        bsplit(v, h, l);
        g_WcatT_h[i] = h; g_WcatT_l[i] = l;
        return;
    }
    i -= (size_t)Gd * XK;
    if (i < (size_t)Gd * Hd) {
        int k = (int)(i % Hd), np = (int)(i / Hd);
        int n = perm_n(np);
        bsplit(Wx[(size_t)(64 + k) * Gd + n], h, l);
        g_WxhT_h[i] = h; g_WxhT_l[i] = l;
        if (k == 0) g_blstmp[np] = bl[n];
        return;
    }
    i -= (size_t)Gd * Hd;
    if (i < (size_t)Fd * Hd) {
        int k = (int)(i % Hd), n = (int)(i / Hd);
        bsplit(W1[(size_t)k * Fd + n], h, l);
        g_W1T_h[i] = h; g_W1T_l[i] = l;
        return;
    }
    i -= (size_t)Fd * Hd;
    if (i < (size_t)Fd * Fd) {
        int k = (int)(i % Fd), n = (int)(i / Fd);
        bsplit(W2[(size_t)k * Fd + n], h, l);
        g_W2T_h[i] = h; g_W2T_l[i] = l;
        return;
    }
    i -= (size_t)Fd * Fd;
    if (i < (size_t)Fd * Fd) {
        int k = (int)(i % Fd), n = (int)(i / Fd);
        bsplit(W3[(size_t)k * Fd + n], h, l);
        g_W3T_h[i] = h; g_W3T_l[i] = l;
        return;
    }
    i -= (size_t)Fd * Fd;
    if (i < (size_t)128 * IK) {
        int k = (int)(i % IK), n = (int)(i / IK);
        float v;
        if (n < 64) v = W4[(size_t)(512 + k) * Zd + n];
        else {
            int n2 = n - 64;
            if (k < 512)      v = W7[(size_t)(512 + k) * Zd + n2];
            else if (k < 768) v = 0.f;
            else              v = W7[(size_t)(1024 + k - 768) * Zd + n2];
        }
        bsplit(v, h, l);
        g_WheadT_h[i] = h; g_WheadT_l[i] = l;
        return;
    }
    i -= (size_t)128 * IK;
    if (i < (size_t)128 * Hd) {
        int k = (int)(i % Hd), n = (int)(i / Hd);
        float v = (n < 64) ? W4[(size_t)k * Zd + n] : W7[(size_t)k * Zd + (n - 64)];
        bsplit(v, h, l);
        g_WbaseT_h[i] = h; g_WbaseT_l[i] = l;
        if (k == 0) g_bhz[n] = (n < 64) ? b4[n] : b7[n - 64];
    }
}

// ---------------- host ----------------
template<typename T> static T* sym(const void* s) { void* p = nullptr; cudaGetSymbolAddress(&p, s); return (T*)p; }

typedef CUresult (*PFN_encode)(CUtensorMap*, CUtensorMapDataType, cuuint32_t, void*,
                               const cuuint64_t*, const cuuint64_t*, const cuuint32_t*,
                               const cuuint32_t*, CUtensorMapInterleave, CUtensorMapSwizzle,
                               CUtensorMapL2promotion, CUtensorMapFloatOOBfill);

static void make_map(PFN_encode enc, CUtensorMap* m, void* base, unsigned long long rows) {
    cuuint64_t dims[2]    = {(cuuint64_t)XK, (cuuint64_t)rows};
    cuuint64_t strides[1] = {(cuuint64_t)XK * 2};
    cuuint32_t box[2]     = {64, 128};
    cuuint32_t es[2]      = {1, 1};
    enc(m, CU_TENSOR_MAP_DATA_TYPE_BFLOAT16, 2, base, dims, strides, box, es,
        CU_TENSOR_MAP_INTERLEAVE_NONE, CU_TENSOR_MAP_SWIZZLE_128B,
        CU_TENSOR_MAP_L2_PROMOTION_L2_128B, CU_TENSOR_MAP_FLOAT_OOB_FILL_NONE);
}

extern "C" void kernel_launch(void* const* d_in, const int* in_sizes, int n_in,
                              void* d_out, int out_size) {
    const float* h_i     = (const float*)d_in[0];
    const float* eps_inf = (const float*)d_in[1];
    const float* eps_pri = (const float*)d_in[2];
    const float* Wx      = (const float*)d_in[3];
    const float* Wh      = (const float*)d_in[4];
    const float* b_lstm  = (const float*)d_in[5];
    const float* W1 = (const float*)d_in[6],  *b1 = (const float*)d_in[7];
    const float* W2 = (const float*)d_in[8],  *b2 = (const float*)d_in[9];
    const float* W3 = (const float*)d_in[10], *b3 = (const float*)d_in[11];
    const float* W4 = (const float*)d_in[12], *b4 = (const float*)d_in[13];
    const float* W5 = (const float*)d_in[14], *b5 = (const float*)d_in[15];
    const float* W6 = (const float*)d_in[16], *b6 = (const float*)d_in[17];
    const float* W7 = (const float*)d_in[18], *b7 = (const float*)d_in[19];
    const float* W8 = (const float*)d_in[20], *b8 = (const float*)d_in[21];
    const float* W9 = (const float*)d_in[22], *b9 = (const float*)d_in[23];

    float* out      = (float*)d_out;
    float* out_fake = out;
    float* out_mean = out_fake + (size_t)Bn * Td * Fd;
    float* out_lv   = out_mean + (size_t)Bn * Td * Zd;
    float* out_z    = out_lv   + (size_t)Bn * Td * Zd;

    __nv_bfloat16* Xh0 = sym<__nv_bfloat16>(g_Xh0); __nv_bfloat16* Xl0 = sym<__nv_bfloat16>(g_Xl0);
    __nv_bfloat16* Xh1 = sym<__nv_bfloat16>(g_Xh1); __nv_bfloat16* Xl1 = sym<__nv_bfloat16>(g_Xl1);
    __nv_bfloat16* Ch  = sym<__nv_bfloat16>(g_Ch);  __nv_bfloat16* Cl  = sym<__nv_bfloat16>(g_Cl);

    float* pBaseg  = sym<float>(g_baseg);
    float* pBasehz = sym<float>(g_basehz);
    float* pBlstmp = sym<float>(g_blstmp);
    float* pBhz    = sym<float>(g_bhz);

    // tensor maps (host-side; graph-capture safe)
    PFN_encode enc = nullptr;
    {
        void* fn = nullptr;
        cudaDriverEntryPointQueryResult st;
#if CUDART_VERSION >= 12050
        cudaGetDriverEntryPointByVersion("cuTensorMapEncodeTiled", &fn, 12000,
                                         cudaEnableDefault, &st);
#else
        cudaGetDriverEntryPoint("cuTensorMapEncodeTiled", &fn, cudaEnableDefault, &st);
#endif
        enc = (PFN_encode)fn;
    }
    static CUtensorMap mX[4], mW[2];
    make_map(enc, &mX[0], Xh0, Bn); make_map(enc, &mX[1], Xl0, Bn);
    make_map(enc, &mX[2], Xh1, Bn); make_map(enc, &mX[3], Xl1, Bn);
    make_map(enc, &mW[0], sym<__nv_bfloat16>(g_WcatT_h), Gd);
    make_map(enc, &mW[1], sym<__nv_bfloat16>(g_WcatT_l), Gd);

    constexpr int SMBASE  = 2 * (256 + 128) * 160;
    constexpr int SMSMALL = 2 * (64 + 64) * 160;
    constexpr int SMTAIL  = 174080;
    constexpr int SMGATE  = 1024 + 2 * 65536;   // 132096
    cudaFuncSetAttribute(gemm<256,128,64,64,256>, cudaFuncAttributeMaxDynamicSharedMemorySize, SMBASE);
    cudaFuncSetAttribute(gemm<64,64,32,32,128>,   cudaFuncAttributeMaxDynamicSharedMemorySize, SMSMALL);
    cudaFuncSetAttribute(tail_kernel,             cudaFuncAttributeMaxDynamicSharedMemorySize, SMTAIL);
    cudaFuncSetAttribute(gate_tma,                cudaFuncAttributeMaxDynamicSharedMemorySize, SMGATE);

    // ---- init ----
    {
        size_t tot = (size_t)Bn * XK + 2 * (size_t)Bn * Hd
                   + (size_t)Gd * XK + (size_t)Gd * Hd
                   + (size_t)Fd * Hd + 2 * (size_t)Fd * Fd
                   + (size_t)128 * IK + (size_t)128 * Hd;
        prep_all<<<(unsigned)((tot + 255) / 256), 256>>>(h_i, Wx, Wh, b_lstm,
                                                         W1, W2, W3, W4, W7, b4, b7);
    }

    // ---- hoisted base GEMMs ----
    {
        GArgs b{};
        b.Ah = sym<__nv_bfloat16>(g_hih); b.Al = sym<__nv_bfloat16>(g_hil); b.lda = Hd;
        b.Bh = sym<__nv_bfloat16>(g_WxhT_h); b.Bl = sym<__nv_bfloat16>(g_WxhT_l); b.ldb = Hd;
        b.Ci = pBlstmp; b.C = pBaseg; b.ldc = Gd; b.K = Hd;
        gemm<256,128,64,64,256><<<dim3(16, 16), 256, SMBASE>>>(b);

        b.Bh = sym<__nv_bfloat16>(g_WbaseT_h); b.Bl = sym<__nv_bfloat16>(g_WbaseT_l); b.ldb = Hd;
        b.Ci = pBhz; b.C = pBasehz; b.ldc = 128; b.K = Hd;
        gemm<64,64,32,32,128><<<dim3(2, 64), 128, SMSMALL>>>(b);
    }

    for (int t = 0; t < Td; t++) {
        __nv_bfloat16* XrH = (t & 1) ? Xh1 : Xh0;
        __nv_bfloat16* XrL = (t & 1) ? Xl1 : Xl0;
        __nv_bfloat16* XwH = (t & 1) ? Xh0 : Xh1;
        __nv_bfloat16* XwL = (t & 1) ? Xl0 : Xl1;
        const CUtensorMap& mAh = (t & 1) ? mX[2] : mX[0];
        const CUtensorMap& mAl = (t & 1) ? mX[3] : mX[1];

        gate_tma<<<dim3(16, 32), 256, SMGATE>>>(mAh, mAl, mW[0], mW[1],
                                                pBaseg, sym<float>(g_c),
                                                XwH, XwL, Ch, Cl);
        {
            TailArgs ta{};
            ta.XwH = XwH; ta.XwL = XwL; ta.XwHm = XwH; ta.XwLm = XwL;
            ta.XrH = XrH; ta.XrL = XrL;
            ta.Ch = Ch; ta.Cl = Cl;
            ta.basehz = pBasehz;
            ta.b1 = b1; ta.b2 = b2; ta.b3 = b3;
            ta.W5 = W5; ta.b5 = b5; ta.W6 = W6; ta.b6 = b6;
            ta.W8 = W8; ta.b8 = b8; ta.W9 = W9; ta.b9 = b9;
            ta.eps_inf = eps_inf; ta.eps_pri = eps_pri;
            ta.fake = out_fake; ta.out_mean = out_mean; ta.out_lv = out_lv; ta.out_z = out_z;
            ta.t = t;
            tail_kernel<<<Bn / 32, 256, SMTAIL>>>(ta);
        }
    }
}

// round 12
// speedup vs baseline: 1.1680x; 1.1116x over previous
#include <cuda_runtime.h>
#include <cuda.h>
#include <cuda_bf16.h>
#include <math.h>
#include <stdint.h>

#define Bn   4096
#define Hd   512
#define Fd   256
#define Zd   64
#define Td   16
#define Gd   2048
#define XK   832      // bf16 X row: [z(64) | y(256) | h(512)]
#define IK   1024     // head K:     [c(512) | y_j(256) | y_prev(256)]
#define CK   512      // c buffer row

// ---------------- persistent buffers ----------------
__device__ float g_baseg [(size_t)Bn * Gd];
__device__ float g_basehz[Bn * 128];
__device__ float g_c     [Bn * Hd];
__device__ float g_blstmp[Gd];
__device__ float g_bhz   [128];

__device__ __nv_bfloat16 g_Xh0[(size_t)Bn * XK], g_Xl0[(size_t)Bn * XK];
__device__ __nv_bfloat16 g_Xh1[(size_t)Bn * XK], g_Xl1[(size_t)Bn * XK];
__device__ __nv_bfloat16 g_Ch [(size_t)Bn * CK], g_Cl [(size_t)Bn * CK];
__device__ __nv_bfloat16 g_hih[(size_t)Bn * Hd], g_hil[(size_t)Bn * Hd];

__device__ __nv_bfloat16 g_WcatT_h[(size_t)Gd * XK], g_WcatT_l[(size_t)Gd * XK];
__device__ __nv_bfloat16 g_WxhT_h [(size_t)Gd * Hd], g_WxhT_l [(size_t)Gd * Hd];
__device__ __nv_bfloat16 g_W1T_h  [Fd * Hd], g_W1T_l  [Fd * Hd];
__device__ __nv_bfloat16 g_W2T_h  [Fd * Fd], g_W2T_l  [Fd * Fd];
__device__ __nv_bfloat16 g_W3T_h  [Fd * Fd], g_W3T_l  [Fd * Fd];
__device__ __nv_bfloat16 g_WheadT_h[128 * IK], g_WheadT_l[128 * IK];
__device__ __nv_bfloat16 g_WbaseT_h[128 * Hd], g_WbaseT_l[128 * Hd];

// ---------------- helpers ----------------
__device__ __forceinline__ void bsplit(float v, __nv_bfloat16& h, __nv_bfloat16& l) {
    h = __float2bfloat16_rn(v);
    l = __float2bfloat16_rn(v - __bfloat162float(h));
}
__device__ __forceinline__ uint32_t bpack(__nv_bfloat16 a, __nv_bfloat16 b) {
    __nv_bfloat162 t; t.x = a; t.y = b;
    return reinterpret_cast<uint32_t&>(t);
}
__device__ __forceinline__ __nv_bfloat162 bmk2(__nv_bfloat16 a, __nv_bfloat16 b) {
    __nv_bfloat162 t; t.x = a; t.y = b; return t;
}
// fast transcendentals (~2ulp): sigmoid via ex2+rcp, tanh via sigmoid
__device__ __forceinline__ float fsig(float x) {
    return __fdividef(1.f, 1.f + __expf(-x));
}
__device__ __forceinline__ float ftanh(float x) {
    return 2.f * fsig(2.f * x) - 1.f;
}
__device__ __forceinline__ void mma16816(float* c, const uint32_t* a, const uint32_t* b) {
    asm volatile(
        "mma.sync.aligned.m16n8k16.row.col.f32.bf16.bf16.f32 "
        "{%0,%1,%2,%3}, {%4,%5,%6,%7}, {%8,%9}, {%0,%1,%2,%3};\n"
        : "+f"(c[0]), "+f"(c[1]), "+f"(c[2]), "+f"(c[3])
        : "r"(a[0]), "r"(a[1]), "r"(a[2]), "r"(a[3]), "r"(b[0]), "r"(b[1]));
}
__device__ __forceinline__ void ldsm4(uint32_t& r0, uint32_t& r1, uint32_t& r2, uint32_t& r3,
                                      uint32_t addr) {
    asm volatile("ldmatrix.sync.aligned.m8n8.x4.shared.b16 {%0,%1,%2,%3}, [%4];"
        : "=r"(r0), "=r"(r1), "=r"(r2), "=r"(r3) : "r"(addr));
}
__device__ __forceinline__ void cpa16(void* dst, const void* src) {
    uint32_t d = (uint32_t)__cvta_generic_to_shared(dst);
    asm volatile("cp.async.cg.shared.global [%0], [%1], 16;\n" :: "r"(d), "l"(src));
}
#define CPA_COMMIT() asm volatile("cp.async.commit_group;\n")
#define CPA_WAIT1()  asm volatile("cp.async.wait_group 1;\n")
#define CPA_WAIT0()  asm volatile("cp.async.wait_group 0;\n")

__device__ __forceinline__ uint32_t smem_u32(const void* p) {
    return (uint32_t)__cvta_generic_to_shared(p);
}

// ---- TMA / mbarrier (sm_90 baseline PTX) ----
#define MBAR_INIT(a, n) \
    asm volatile("mbarrier.init.shared.b64 [%0], %1;" :: "r"(a), "r"(n) : "memory")
#define MBAR_EXPECT_TX(a, bytes) \
    asm volatile("mbarrier.arrive.expect_tx.shared.b64 _, [%0], %1;" :: "r"(a), "r"(bytes) : "memory")
#define MBAR_WAIT(a, par) do { \
    asm volatile("{\n\t.reg .pred P1;\n\tWL%=:\n\t" \
        "mbarrier.try_wait.parity.acquire.cta.shared::cta.b64 P1, [%0], %1, 0x989680;\n\t" \
        "@P1 bra.uni WD%=;\n\tbra.uni WL%=;\n\tWD%=:\n\t}" \
        :: "r"(a), "r"(par) : "memory"); \
} while (0)
#define TMA2D(dst, mapp, cx, cy, mb) \
    asm volatile("cp.async.bulk.tensor.2d.shared::cta.global.tile.mbarrier::complete_tx::bytes " \
        "[%0], [%1, {%2, %3}], [%4];" \
        :: "r"(dst), "l"(mapp), "r"(cx), "r"(cy), "r"(mb) : "memory")

// ================= TMA + mma.sync gate kernel =================
__global__ void __launch_bounds__(256) gate_tma(
    const __grid_constant__ CUtensorMap mAh,
    const __grid_constant__ CUtensorMap mAl,
    const __grid_constant__ CUtensorMap mBh,
    const __grid_constant__ CUtensorMap mBl,
    const float* __restrict__ baseg, float* __restrict__ cst,
    __nv_bfloat16* __restrict__ Xh, __nv_bfloat16* __restrict__ Xl,
    __nv_bfloat16* __restrict__ Chp, __nv_bfloat16* __restrict__ Clp)
{
    extern __shared__ char sm[];
    const uint32_t sb = smem_u32(sm);
    const int tid = threadIdx.x, warp = tid >> 5, lane = tid & 31;
    const int bm = blockIdx.y * 128, bn = blockIdx.x * 128;
    const uint32_t F0 = sb + 8, F1 = sb + 16;
    const int wm = (warp >> 2) * 64, wn = (warp & 3) * 32;
    const int gq = lane >> 2, tg = lane & 3;
    const int ch = lane >> 4, r7 = lane & 7;
    const int lrow = (lane & 15) * 128;

    if (tid == 0) { MBAR_INIT(F0, 1); MBAR_INIT(F1, 1); }
    __syncthreads();

    float acc[64];
#pragma unroll
    for (int i = 0; i < 64; i++) acc[i] = 0.f;

    if (tid == 0) {
        MBAR_EXPECT_TX(F0, 65536);
        uint32_t d = sb + 1024;
        TMA2D(d,         &mAh, 0, bm, F0);
        TMA2D(d + 16384, &mAl, 0, bm, F0);
        TMA2D(d + 32768, &mBh, 0, bn, F0);
        TMA2D(d + 49152, &mBl, 0, bn, F0);
        MBAR_EXPECT_TX(F1, 65536);
        d = sb + 1024 + 65536;
        TMA2D(d,         &mAh, 64, bm, F1);
        TMA2D(d + 16384, &mAl, 64, bm, F1);
        TMA2D(d + 32768, &mBh, 64, bn, F1);
        TMA2D(d + 49152, &mBl, 64, bn, F1);
    }

    int pf0 = 0, pf1 = 0;
    for (int c = 0; c <= 12; c++) {
        if ((c & 1) == 0) { MBAR_WAIT(F0, pf0); pf0 ^= 1; }
        else              { MBAR_WAIT(F1, pf1); pf1 ^= 1; }
        const uint32_t bo = sb + 1024 + (c & 1) * 65536;
        const uint32_t aH = bo, aL = bo + 16384, bH = bo + 32768, bL = bo + 49152;
#pragma unroll
        for (int g = 0; g < 4; g++) {
            const int xo = (((2 * g + ch) ^ r7) << 4) + lrow;
            uint32_t bhf[4][2], blf[4][2];
#pragma unroll
            for (int np = 0; np < 2; np++) {
                uint32_t r0, r1, r2, r3;
                ldsm4(r0, r1, r2, r3, bH + (wn + np * 16) * 128 + xo);
                bhf[2*np][0] = r0; bhf[2*np+1][0] = r1; bhf[2*np][1] = r2; bhf[2*np+1][1] = r3;
                ldsm4(r0, r1, r2, r3, bL + (wn + np * 16) * 128 + xo);
                blf[2*np][0] = r0; blf[2*np+1][0] = r1; blf[2*np][1] = r2; blf[2*np+1][1] = r3;
            }
#pragma unroll
            for (int mt = 0; mt < 4; mt++) {
                uint32_t ah[4], al[4];
                ldsm4(ah[0], ah[1], ah[2], ah[3], aH + (wm + mt * 16) * 128 + xo);
                ldsm4(al[0], al[1], al[2], al[3], aL + (wm + mt * 16) * 128 + xo);
#pragma unroll
                for (int nt = 0; nt < 4; nt++) {
                    float* a = acc + (mt * 4 + nt) * 4;
                    mma16816(a, ah, bhf[nt]);
                    mma16816(a, ah, blf[nt]);
                    mma16816(a, al, bhf[nt]);
                }
            }
        }
        __syncthreads();
        if (tid == 0 && c + 2 <= 12) {
            const uint32_t mb = (c & 1) ? F1 : F0;
            MBAR_EXPECT_TX(mb, 65536);
            const uint32_t d = sb + 1024 + (c & 1) * 65536;
            const int kc = (c + 2) * 64;
            TMA2D(d,         &mAh, kc, bm, mb);
            TMA2D(d + 16384, &mAl, kc, bm, mb);
            TMA2D(d + 32768, &mBh, kc, bn, mb);
            TMA2D(d + 49152, &mBl, kc, bn, mb);
        }
    }

    // ---- epilogue: stage raw acc, then row-coalesced fast-math LSTM ----
    float* tile = (float*)(sm + 1024);
#pragma unroll
    for (int mt = 0; mt < 4; mt++)
#pragma unroll
        for (int nt = 0; nt < 4; nt++) {
            int r0 = wm + mt * 16 + gq, c0 = wn + nt * 8 + 2 * tg;
            float* a = acc + (mt * 4 + nt) * 4;
            tile[r0 * 128 + c0]           = a[0];
            tile[r0 * 128 + c0 + 1]       = a[1];
            tile[(r0 + 8) * 128 + c0]     = a[2];
            tile[(r0 + 8) * 128 + c0 + 1] = a[3];
        }
    __syncthreads();

    for (int idx = tid; idx < 128 * 32; idx += 256) {
        int row = idx >> 5, w = idx & 31;
        int b = bm + row, jg = blockIdx.x * 32 + w;
        const float* bg = baseg + (size_t)b * Gd + bn;
        float ig = tile[row * 128 + w]      + bg[w];
        float fg = tile[row * 128 + 32 + w] + bg[32 + w];
        float gg = tile[row * 128 + 64 + w] + bg[64 + w];
        float og = tile[row * 128 + 96 + w] + bg[96 + w];
        float si = fsig(ig), sf = fsig(fg), so = fsig(og);
        float cn = sf * cst[b * Hd + jg] + si * ftanh(gg);
        float hn = so * ftanh(cn);
        cst[b * Hd + jg] = cn;
        __nv_bfloat16 hh, hl, cc, cl;
        bsplit(hn, hh, hl); bsplit(cn, cc, cl);
        Xh[(size_t)b * XK + 320 + jg] = hh;
        Xl[(size_t)b * XK + 320 + jg] = hl;
        Chp[(size_t)b * CK + jg] = cc;
        Clp[(size_t)b * CK + jg] = cl;
    }
}

// ================= mma.sync GEMM (base GEMMs; 80B-row layout) =================
struct GArgs {
    const __nv_bfloat16 *Ah, *Al; int lda;
    const __nv_bfloat16 *Bh, *Bl; int ldb;
    const float* Ci; int ldci;
    float* C; int ldc;
    int K;
};

template<int MT,int NTL,int AHS,int BHS>
__device__ __forceinline__ void stage_mma2(const char* Ab, const char* Bb, float* acc,
                                           int wm, int wn, int laneoff)
{
    uint32_t aH = smem_u32(Ab) + laneoff;
    uint32_t bH = smem_u32(Bb) + laneoff;
#pragma unroll
    for (int kk = 0; kk < 2; kk++) {
        const int kb = kk * 32;
        uint32_t bhf[NTL][2], blf[NTL][2];
#pragma unroll
        for (int np = 0; np < NTL / 2; np++) {
            uint32_t r0, r1, r2, r3;
            ldsm4(r0, r1, r2, r3, bH + (wn + np * 16) * 80 + kb);
            bhf[2*np][0] = r0; bhf[2*np+1][0] = r1; bhf[2*np][1] = r2; bhf[2*np+1][1] = r3;
            ldsm4(r0, r1, r2, r3, bH + BHS + (wn + np * 16) * 80 + kb);
            blf[2*np][0] = r0; blf[2*np+1][0] = r1; blf[2*np][1] = r2; blf[2*np+1][1] = r3;
        }
#pragma unroll
        for (int mt = 0; mt < MT; mt++) {
            uint32_t ah[4], al[4];
            ldsm4(ah[0], ah[1], ah[2], ah[3], aH + (wm + mt * 16) * 80 + kb);
            ldsm4(al[0], al[1], al[2], al[3], aH + AHS + (wm + mt * 16) * 80 + kb);
#pragma unroll
            for (int nt = 0; nt < NTL; nt++) {
                float* a = acc + (mt * NTL + nt) * 4;
                mma16816(a, ah, bhf[nt]);
                mma16816(a, ah, blf[nt]);
                mma16816(a, al, bhf[nt]);
            }
        }
    }
}

template<int BM,int BN,int NTH>
__device__ __forceinline__ void stage_load(char* base, int tid, int bm, int bn,
    const __nv_bfloat16* Ah, const __nv_bfloat16* Al, int lda,
    const __nv_bfloat16* Bh, const __nv_bfloat16* Bl, int ldb, int k0)
{
#pragma unroll
    for (int i = tid; i < BM * 4; i += NTH) {
        int row = i >> 2, c4 = (i & 3) * 16;
        size_t off = ((size_t)(bm + row) * lda + k0) * 2 + c4;
        cpa16(base + row * 80 + c4, (const char*)Ah + off);
        cpa16(base + BM * 80 + row * 80 + c4, (const char*)Al + off);
    }
#pragma unroll
    for (int i = tid; i < BN * 4; i += NTH) {
        int row = i >> 2, c4 = (i & 3) * 16;
        size_t off = ((size_t)(bn + row) * ldb + k0) * 2 + c4;
        cpa16(base + BM * 160 + row * 80 + c4, (const char*)Bh + off);
        cpa16(base + BM * 160 + BN * 80 + row * 80 + c4, (const char*)Bl + off);
    }
    CPA_COMMIT();
}

template<int BM,int BN,int WM,int WN,int NTH>
__global__ void __launch_bounds__(NTH) gemm(GArgs g)
{
    extern __shared__ char sm[];
    constexpr int MT = WM / 16, NTL = WN / 8, NWN = BN / WN;
    constexpr int stageB = (BM + BN) * 160;
    const int tid = threadIdx.x, warp = tid >> 5, lane = tid & 31;
    const int gq = lane >> 2, tg = lane & 3;
    const int laneoff = (lane & 15) * 80 + (lane >> 4) * 16;
    const int wm = (warp / NWN) * WM, wn = (warp % NWN) * WN;
    const int bm = blockIdx.y * BM, bn = blockIdx.x * BN;
    const int K = g.K;

    float acc[MT * NTL * 4];
#pragma unroll
    for (int i = 0; i < MT * NTL * 4; i++) acc[i] = 0.f;

    const int nk = K >> 5;
    stage_load<BM,BN,NTH>(sm, tid, bm, bn, g.Ah, g.Al, g.lda, g.Bh, g.Bl, g.ldb, 0);
    for (int kt = 0; kt < nk; kt++) {
        if (kt + 1 < nk) {
            stage_load<BM,BN,NTH>(sm + ((kt + 1) & 1) * stageB, tid, bm, bn,
                                  g.Ah, g.Al, g.lda, g.Bh, g.Bl, g.ldb, (kt + 1) << 5);
            CPA_WAIT1();
        } else CPA_WAIT0();
        __syncthreads();
        const char* cur = sm + (kt & 1) * stageB;
        stage_mma2<MT,NTL,BM*80,BN*80>(cur, cur + BM * 160, acc, wm, wn, laneoff);
        __syncthreads();
    }

#pragma unroll
    for (int mt = 0; mt < MT; mt++)
#pragma unroll
        for (int nt = 0; nt < NTL; nt++) {
            float* a = acc + (mt * NTL + nt) * 4;
#pragma unroll
            for (int half = 0; half < 2; half++) {
                int r = bm + wm + mt * 16 + gq + half * 8;
                int c = bn + wn + nt * 8 + 2 * tg;
                float v0 = a[half * 2] + g.Ci[c], v1 = a[half * 2 + 1] + g.Ci[c + 1];
                *(float2*)&g.C[(size_t)r * g.ldc + c] = make_float2(v0, v1);
            }
        }
}

// ================= fused tail kernel =================
struct TailArgs {
    const __nv_bfloat16 *XwH, *XwL;
    __nv_bfloat16 *XwHm, *XwLm;
    const __nv_bfloat16 *XrH, *XrL;
    const __nv_bfloat16 *Ch, *Cl;
    const float* basehz;
    const float *b1, *b2, *b3;
    const float *W5, *b5, *W6, *b6, *W8, *b8, *W9, *b9;
    const float *eps_inf, *eps_pri;
    float *fake, *out_mean, *out_lv, *out_z;
    int t;
};

template<int BN,int NTH>
__device__ __forceinline__ void tail_loadB(char* st, int tid,
    const __nv_bfloat16* Bh, const __nv_bfloat16* Bl, int ldb, int kg)
{
#pragma unroll
    for (int i = tid; i < BN * 4; i += NTH) {
        int row = i >> 2, c4 = (i & 3) * 16;
        size_t off = ((size_t)row * ldb + kg) * 2 + c4;
        cpa16(st + row * 80 + c4, (const char*)Bh + off);
        cpa16(st + BN * 80 + row * 80 + c4, (const char*)Bl + off);
    }
}

__device__ __forceinline__ void tail_loadA(char* st, int tid, int r0,
    const __nv_bfloat16* Ah, const __nv_bfloat16* Al, int lda, int kg)
{
    if (tid >= 128) return;
    int arow = tid >> 2, ac4 = (tid & 3) * 16;
    size_t off = ((size_t)(r0 + arow) * lda + kg) * 2 + ac4;
    cpa16(st + arow * 80 + ac4, (const char*)Ah + off);
    cpa16(st + 2560 + arow * 80 + ac4, (const char*)Al + off);
}

template<int NTL>
__device__ __forceinline__ void epi_chunk(const float* acc, const float* bias,
                                          char* dst, int wn, int gq, int tg)
{
#pragma unroll
    for (int mt = 0; mt < 2; mt++)
#pragma unroll
        for (int nt = 0; nt < NTL; nt++)
#pragma unroll
            for (int half = 0; half < 2; half++) {
                int row = mt * 16 + gq + half * 8;
                int col = wn + nt * 8 + 2 * tg;
                const float* a = acc + (mt * NTL + nt) * 4 + half * 2;
                float v0 = fmaxf(a[0] + bias[col], 0.f);
                float v1 = fmaxf(a[1] + bias[col + 1], 0.f);
                __nv_bfloat16 h0, l0, h1, l1;
                bsplit(v0, h0, l0); bsplit(v1, h1, l1);
                char* cb = dst + (col >> 5) * 5120;
                int kp = (col & 31) >> 1;
                ((uint32_t*)cb)[row * 20 + kp] = bpack(h0, h1);
                ((uint32_t*)(cb + 2560))[row * 20 + kp] = bpack(l0, l1);
            }
}

__global__ void __launch_bounds__(256) tail_kernel(TailArgs g)
{
    extern __shared__ char sm[];
    char* stages = sm;
    char* tA = sm + 92160;
    char* tB = sm + 133120;
    float* hzc = (float*)tB;

    const int tid = threadIdx.x, lane = tid & 31, warp = tid >> 5;
    const int gq = lane >> 2, tg = lane & 3;
    const int laneoff = (lane & 15) * 80 + (lane >> 4) * 16;
    const int r0 = blockIdx.x * 32;
    constexpr int DST = 46080;
    constexpr int HST = 25600;

    // dec1
    {
        float acc[32];
#pragma unroll
        for (int i = 0; i < 32; i++) acc[i] = 0.f;
        tail_loadA(stages, tid, r0, g.XwH + 320, g.XwL + 320, XK, 0);
        tail_loadB<256,256>(stages + 5120, tid, g_W1T_h, g_W1T_l, Hd, 0);
        CPA_COMMIT();
        for (int kt = 0; kt < 16; kt++) {
            char* cur = stages + (kt & 1) * DST;
            if (kt < 15) {
                char* nxt = stages + ((kt + 1) & 1) * DST;
                tail_loadA(nxt, tid, r0, g.XwH + 320, g.XwL + 320, XK, (kt + 1) * 32);
                tail_loadB<256,256>(nxt + 5120, tid, g_W1T_h, g_W1T_l, Hd, (kt + 1) * 32);
                CPA_COMMIT(); CPA_WAIT1();
            } else CPA_WAIT0();
            __syncthreads();
            stage_mma2<2,4,2560,20480>(cur, cur + 5120, acc, 0, warp * 32, laneoff);
            __syncthreads();
        }
        epi_chunk<4>(acc, g.b1, tA, warp * 32, gq, tg);
        __syncthreads();
    }
    // dec2
    {
        float acc[32];
#pragma unroll
        for (int i = 0; i < 32; i++) acc[i] = 0.f;
        tail_loadB<256,256>(stages + 5120, tid, g_W2T_h, g_W2T_l, Fd, 0);
        CPA_COMMIT();
        for (int kt = 0; kt < 8; kt++) {
            char* cur = stages + (kt & 1) * DST;
            if (kt < 7) {
                tail_loadB<256,256>(stages + ((kt + 1) & 1) * DST + 5120, tid,
                                    g_W2T_h, g_W2T_l, Fd, (kt + 1) * 32);
                CPA_COMMIT(); CPA_WAIT1();
            } else CPA_WAIT0();
            __syncthreads();
            stage_mma2<2,4,2560,20480>(tA + kt * 5120, cur + 5120, acc, 0, warp * 32, laneoff);
            __syncthreads();
        }
        epi_chunk<4>(acc, g.b2, tB, warp * 32, gq, tg);
        __syncthreads();
    }
    // dec3
    {
        float acc[32];
#pragma unroll
        for (int i = 0; i < 32; i++) acc[i] = 0.f;
        tail_loadB<256,256>(stages + 5120, tid, g_W3T_h, g_W3T_l, Fd, 0);
        CPA_COMMIT();
        for (int kt = 0; kt < 8; kt++) {
            char* cur = stages + (kt & 1) * DST;
            if (kt < 7) {
                tail_loadB<256,256>(stages + ((kt + 1) & 1) * DST + 5120, tid,
                                    g_W3T_h, g_W3T_l, Fd, (kt + 1) * 32);
                CPA_COMMIT(); CPA_WAIT1();
            } else CPA_WAIT0();
            __syncthreads();
            stage_mma2<2,4,2560,20480>(tB + kt * 5120, cur + 5120, acc, 0, warp * 32, laneoff);
            __syncthreads();
        }
#pragma unroll
        for (int mt = 0; mt < 2; mt++)
#pragma unroll
            for (int nt = 0; nt < 4; nt++)
#pragma unroll
                for (int half = 0; half < 2; half++) {
                    int row = mt * 16 + gq + half * 8;
                    int col = warp * 32 + nt * 8 + 2 * tg;
                    int b = r0 + row;
                    const float* a = acc + (mt * 4 + nt) * 4 + half * 2;
                    float v0 = fmaxf(a[0] + g.b3[col], 0.f);
                    float v1 = fmaxf(a[1] + g.b3[col + 1], 0.f);
                    *(float2*)&g.fake[(size_t)b * (Td * Fd) + g.t * Fd + col] = make_float2(v0, v1);
                    __nv_bfloat16 h0, l0, h1, l1;
                    bsplit(v0, h0, l0); bsplit(v1, h1, l1);
                    *(__nv_bfloat162*)&g.XwHm[(size_t)b * XK + 64 + col] = bmk2(h0, h1);
                    *(__nv_bfloat162*)&g.XwLm[(size_t)b * XK + 64 + col] = bmk2(l0, l1);
                    char* cb = tA + (col >> 5) * 5120;
                    int kp = (col & 31) >> 1;
                    ((uint32_t*)cb)[row * 20 + kp] = bpack(h0, h1);
                    ((uint32_t*)(cb + 2560))[row * 20 + kp] = bpack(l0, l1);
                }
        __syncthreads();
    }
    // head
    {
        float acc[16];
#pragma unroll
        for (int i = 0; i < 16; i++) acc[i] = 0.f;
        tail_loadA(stages, tid, r0, g.Ch, g.Cl, CK, 0);
        tail_loadB<128,256>(stages + 5120, tid, g_WheadT_h, g_WheadT_l, IK, 0);
        CPA_COMMIT();
        for (int kt = 0; kt < 32; kt++) {
            char* cur = stages + (kt & 1) * HST;
            if (kt < 31) {
                char* nxt = stages + ((kt + 1) & 1) * HST;
                int kn = kt + 1;
                if (kn < 16)       tail_loadA(nxt, tid, r0, g.Ch, g.Cl, CK, kn * 32);
                else if (kn >= 24) tail_loadA(nxt, tid, r0, g.XrH, g.XrL, XK, 64 + (kn - 24) * 32);
                tail_loadB<128,256>(nxt + 5120, tid, g_WheadT_h, g_WheadT_l, IK, kn * 32);
                CPA_COMMIT(); CPA_WAIT1();
            } else CPA_WAIT0();
            __syncthreads();
            const char* Ab = (kt >= 16 && kt < 24) ? (tA + (kt - 16) * 5120) : cur;
            stage_mma2<2,2,2560,10240>(Ab, cur + 5120, acc, 0, warp * 16, laneoff);
            __syncthreads();
        }
#pragma unroll
        for (int mt = 0; mt < 2; mt++)
#pragma unroll
            for (int nt = 0; nt < 2; nt++)
#pragma unroll
                for (int half = 0; half < 2; half++) {
                    int row = mt * 16 + gq + half * 8;
                    int col = warp * 16 + nt * 8 + 2 * tg;
                    const float* a = acc + (mt * 2 + nt) * 4 + half * 2;
                    const float* bz = g.basehz + (size_t)(r0 + row) * 128 + col;
                    hzc[row * 130 + col]     = fmaxf(a[0] + bz[0], 0.f);
                    hzc[row * 130 + col + 1] = fmaxf(a[1] + bz[1], 0.f);
                }
        __syncthreads();
    }
    // finish (fast math: sqrt(exp(l)) = exp(l/2))
    for (int idx = tid; idx < 32 * 64; idx += 256) {
        int row = idx >> 6, z = idx & 63, b = r0 + row;
        float m = g.b5[z], l = g.b6[z], mp = g.b8[z], lp = g.b9[z];
        const float* hz = &hzc[row * 130];
#pragma unroll 8
        for (int k = 0; k < 64; k++) {
            float av = hz[k], ap = hz[64 + k];
            m  += av * g.W5[k * Zd + z];
            l  += av * g.W6[k * Zd + z];
            mp += ap * g.W8[k * Zd + z];
            lp += ap * g.W9[k * Zd + z];
        }
        m = fmaxf(m, 0.f); l = fmaxf(l, 0.f); mp = fmaxf(mp, 0.f); lp = fmaxf(lp, 0.f);
        size_t gi = (size_t)b * Zd + z;
        float zi = m  + g.eps_inf[(size_t)g.t * Bn * Zd + gi] * __expf(0.5f * l);
        float zp = mp + g.eps_pri[(size_t)g.t * Bn * Zd + gi] * __expf(0.5f * lp);
        g.out_mean[(size_t)b * Td * Zd + (size_t)g.t * Zd + z] = m;
        g.out_lv  [(size_t)b * Td * Zd + (size_t)g.t * Zd + z] = l;
        g.out_z[(size_t)(2 * g.t)     * Bn * Zd + gi] = zi;
        g.out_z[(size_t)(2 * g.t + 1) * Bn * Zd + gi] = zp;
        __nv_bfloat16 zh, zl; bsplit(zi, zh, zl);
        g.XwHm[(size_t)b * XK + z] = zh;
        g.XwLm[(size_t)b * XK + z] = zl;
    }
}

// ---------------- single merged prep kernel ----------------
__device__ __forceinline__ int perm_n(int np) {
    int chunk = np >> 7, r = np & 127, gate = r >> 5, w = r & 31;
    return gate * 512 + chunk * 32 + w;
}

__global__ void prep_all(const float* __restrict__ h_i,
                         const float* __restrict__ Wx, const float* __restrict__ Wh,
                         const float* __restrict__ bl,
                         const float* __restrict__ W1, const float* __restrict__ W2,
                         const float* __restrict__ W3,
                         const float* __restrict__ W4, const float* __restrict__ W7,
                         const float* __restrict__ b4, const float* __restrict__ b7)
{
    size_t i = (size_t)blockIdx.x * blockDim.x + threadIdx.x;
    __nv_bfloat16 h, l;

    const size_t nX = (size_t)Bn * XK;
    if (i < nX) {
        __nv_bfloat16 z = __float2bfloat16(0.f);
        g_Xh0[i] = z; g_Xl0[i] = z; g_Xh1[i] = z; g_Xl1[i] = z;
        return;
    }
    i -= nX;
    const size_t nC = (size_t)Bn * Hd;
    if (i < nC) { g_c[i] = 0.f; return; }
    i -= nC;
    if (i < (size_t)Bn * Hd) {
        bsplit(h_i[i], h, l);
        g_hih[i] = h; g_hil[i] = l;
        return;
    }
    i -= (size_t)Bn * Hd;
    if (i < (size_t)Gd * XK) {
        int k = (int)(i % XK), np = (int)(i / XK);
        int n = perm_n(np);
        float v;
        if (k < 64)       v = Wx[(size_t)k * Gd + n];
        else if (k < 320) v = Wx[(size_t)(512 + k) * Gd + n];
        else              v = Wh[(size_t)(k - 320) * Gd + n];
        bsplit(v, h, l);
        g_WcatT_h[i] = h; g_WcatT_l[i] = l;
        return;
    }
    i -= (size_t)Gd * XK;
    if (i < (size_t)Gd * Hd) {
        int k = (int)(i % Hd), np = (int)(i / Hd);
        int n = perm_n(np);
        bsplit(Wx[(size_t)(64 + k) * Gd + n], h, l);
        g_WxhT_h[i] = h; g_WxhT_l[i] = l;
        if (k == 0) g_blstmp[np] = bl[n];
        return;
    }
    i -= (size_t)Gd * Hd;
    if (i < (size_t)Fd * Hd) {
        int k = (int)(i % Hd), n = (int)(i / Hd);
        bsplit(W1[(size_t)k * Fd + n], h, l);
        g_W1T_h[i] = h; g_W1T_l[i] = l;
        return;
    }
    i -= (size_t)Fd * Hd;
    if (i < (size_t)Fd * Fd) {
        int k = (int)(i % Fd), n = (int)(i / Fd);
        bsplit(W2[(size_t)k * Fd + n], h, l);
        g_W2T_h[i] = h; g_W2T_l[i] = l;
        return;
    }
    i -= (size_t)Fd * Fd;
    if (i < (size_t)Fd * Fd) {
        int k = (int)(i % Fd), n = (int)(i / Fd);
        bsplit(W3[(size_t)k * Fd + n], h, l);
        g_W3T_h[i] = h; g_W3T_l[i] = l;
        return;
    }
    i -= (size_t)Fd * Fd;
    if (i < (size_t)128 * IK) {
        int k = (int)(i % IK), n = (int)(i / IK);
        float v;
        if (n < 64) v = W4[(size_t)(512 + k) * Zd + n];
        else {
            int n2 = n - 64;
            if (k < 512)      v = W7[(size_t)(512 + k) * Zd + n2];
            else if (k < 768) v = 0.f;
            else              v = W7[(size_t)(1024 + k - 768) * Zd + n2];
        }
        bsplit(v, h, l);
        g_WheadT_h[i] = h; g_WheadT_l[i] = l;
        return;
    }
    i -= (size_t)128 * IK;
    if (i < (size_t)128 * Hd) {
        int k = (int)(i % Hd), n = (int)(i / Hd);
        float v = (n < 64) ? W4[(size_t)k * Zd + n] : W7[(size_t)k * Zd + (n - 64)];
        bsplit(v, h, l);
        g_WbaseT_h[i] = h; g_WbaseT_l[i] = l;
        if (k == 0) g_bhz[n] = (n < 64) ? b4[n] : b7[n - 64];
    }
}

// ---------------- host ----------------
template<typename T> static T* sym(const void* s) { void* p = nullptr; cudaGetSymbolAddress(&p, s); return (T*)p; }

typedef CUresult (*PFN_encode)(CUtensorMap*, CUtensorMapDataType, cuuint32_t, void*,
                               const cuuint64_t*, const cuuint64_t*, const cuuint32_t*,
                               const cuuint32_t*, CUtensorMapInterleave, CUtensorMapSwizzle,
                               CUtensorMapL2promotion, CUtensorMapFloatOOBfill);

static void make_map(PFN_encode enc, CUtensorMap* m, void* base, unsigned long long rows) {
    cuuint64_t dims[2]    = {(cuuint64_t)XK, (cuuint64_t)rows};
    cuuint64_t strides[1] = {(cuuint64_t)XK * 2};
    cuuint32_t box[2]     = {64, 128};
    cuuint32_t es[2]      = {1, 1};
    enc(m, CU_TENSOR_MAP_DATA_TYPE_BFLOAT16, 2, base, dims, strides, box, es,
        CU_TENSOR_MAP_INTERLEAVE_NONE, CU_TENSOR_MAP_SWIZZLE_128B,
        CU_TENSOR_MAP_L2_PROMOTION_L2_128B, CU_TENSOR_MAP_FLOAT_OOB_FILL_NONE);
}

extern "C" void kernel_launch(void* const* d_in, const int* in_sizes, int n_in,
                              void* d_out, int out_size) {
    const float* h_i     = (const float*)d_in[0];
    const float* eps_inf = (const float*)d_in[1];
    const float* eps_pri = (const float*)d_in[2];
    const float* Wx      = (const float*)d_in[3];
    const float* Wh      = (const float*)d_in[4];
    const float* b_lstm  = (const float*)d_in[5];
    const float* W1 = (const float*)d_in[6],  *b1 = (const float*)d_in[7];
    const float* W2 = (const float*)d_in[8],  *b2 = (const float*)d_in[9];
    const float* W3 = (const float*)d_in[10], *b3 = (const float*)d_in[11];
    const float* W4 = (const float*)d_in[12], *b4 = (const float*)d_in[13];
    const float* W5 = (const float*)d_in[14], *b5 = (const float*)d_in[15];
    const float* W6 = (const float*)d_in[16], *b6 = (const float*)d_in[17];
    const float* W7 = (const float*)d_in[18], *b7 = (const float*)d_in[19];
    const float* W8 = (const float*)d_in[20], *b8 = (const float*)d_in[21];
    const float* W9 = (const float*)d_in[22], *b9 = (const float*)d_in[23];

    float* out      = (float*)d_out;
    float* out_fake = out;
    float* out_mean = out_fake + (size_t)Bn * Td * Fd;
    float* out_lv   = out_mean + (size_t)Bn * Td * Zd;
    float* out_z    = out_lv   + (size_t)Bn * Td * Zd;

    __nv_bfloat16* Xh0 = sym<__nv_bfloat16>(g_Xh0); __nv_bfloat16* Xl0 = sym<__nv_bfloat16>(g_Xl0);
    __nv_bfloat16* Xh1 = sym<__nv_bfloat16>(g_Xh1); __nv_bfloat16* Xl1 = sym<__nv_bfloat16>(g_Xl1);
    __nv_bfloat16* Ch  = sym<__nv_bfloat16>(g_Ch);  __nv_bfloat16* Cl  = sym<__nv_bfloat16>(g_Cl);

    float* pBaseg  = sym<float>(g_baseg);
    float* pBasehz = sym<float>(g_basehz);
    float* pBlstmp = sym<float>(g_blstmp);
    float* pBhz    = sym<float>(g_bhz);

    PFN_encode enc = nullptr;
    {
        void* fn = nullptr;
        cudaDriverEntryPointQueryResult st;
#if CUDART_VERSION >= 12050
        cudaGetDriverEntryPointByVersion("cuTensorMapEncodeTiled", &fn, 12000,
                                         cudaEnableDefault, &st);
#else
        cudaGetDriverEntryPoint("cuTensorMapEncodeTiled", &fn, cudaEnableDefault, &st);
#endif
        enc = (PFN_encode)fn;
    }
    static CUtensorMap mX[4], mW[2];
    make_map(enc, &mX[0], Xh0, Bn); make_map(enc, &mX[1], Xl0, Bn);
    make_map(enc, &mX[2], Xh1, Bn); make_map(enc, &mX[3], Xl1, Bn);
    make_map(enc, &mW[0], sym<__nv_bfloat16>(g_WcatT_h), Gd);
    make_map(enc, &mW[1], sym<__nv_bfloat16>(g_WcatT_l), Gd);

    constexpr int SMBASE  = 2 * (256 + 128) * 160;
    constexpr int SMSMALL = 2 * (64 + 64) * 160;
    constexpr int SMTAIL  = 174080;
    constexpr int SMGATE  = 1024 + 2 * 65536;
    cudaFuncSetAttribute(gemm<256,128,64,64,256>, cudaFuncAttributeMaxDynamicSharedMemorySize, SMBASE);
    cudaFuncSetAttribute(gemm<64,64,32,32,128>,   cudaFuncAttributeMaxDynamicSharedMemorySize, SMSMALL);
    cudaFuncSetAttribute(tail_kernel,             cudaFuncAttributeMaxDynamicSharedMemorySize, SMTAIL);
    cudaFuncSetAttribute(gate_tma,                cudaFuncAttributeMaxDynamicSharedMemorySize, SMGATE);

    // ---- init ----
    {
        size_t tot = (size_t)Bn * XK + 2 * (size_t)Bn * Hd
                   + (size_t)Gd * XK + (size_t)Gd * Hd
                   + (size_t)Fd * Hd + 2 * (size_t)Fd * Fd
                   + (size_t)128 * IK + (size_t)128 * Hd;
        prep_all<<<(unsigned)((tot + 255) / 256), 256>>>(h_i, Wx, Wh, b_lstm,
                                                         W1, W2, W3, W4, W7, b4, b7);
    }

    // ---- hoisted base GEMMs ----
    {
        GArgs b{};
        b.Ah = sym<__nv_bfloat16>(g_hih); b.Al = sym<__nv_bfloat16>(g_hil); b.lda = Hd;
        b.Bh = sym<__nv_bfloat16>(g_WxhT_h); b.Bl = sym<__nv_bfloat16>(g_WxhT_l); b.ldb = Hd;
        b.Ci = pBlstmp; b.C = pBaseg; b.ldc = Gd; b.K = Hd;
        gemm<256,128,64,64,256><<<dim3(16, 16), 256, SMBASE>>>(b);

        b.Bh = sym<__nv_bfloat16>(g_WbaseT_h); b.Bl = sym<__nv_bfloat16>(g_WbaseT_l); b.ldb = Hd;
        b.Ci = pBhz; b.C = pBasehz; b.ldc = 128; b.K = Hd;
        gemm<64,64,32,32,128><<<dim3(2, 64), 128, SMSMALL>>>(b);
    }

    for (int t = 0; t < Td; t++) {
        __nv_bfloat16* XrH = (t & 1) ? Xh1 : Xh0;
        __nv_bfloat16* XrL = (t & 1) ? Xl1 : Xl0;
        __nv_bfloat16* XwH = (t & 1) ? Xh0 : Xh1;
        __nv_bfloat16* XwL = (t & 1) ? Xl0 : Xl1;
        const CUtensorMap& mAh = (t & 1) ? mX[2] : mX[0];
        const CUtensorMap& mAl = (t & 1) ? mX[3] : mX[1];

        gate_tma<<<dim3(16, 32), 256, SMGATE>>>(mAh, mAl, mW[0], mW[1],
                                                pBaseg, sym<float>(g_c),
                                                XwH, XwL, Ch, Cl);
        {
            TailArgs ta{};
            ta.XwH = XwH; ta.XwL = XwL; ta.XwHm = XwH; ta.XwLm = XwL;
            ta.XrH = XrH; ta.XrL = XrL;
            ta.Ch = Ch; ta.Cl = Cl;
            ta.basehz = pBasehz;
            ta.b1 = b1; ta.b2 = b2; ta.b3 = b3;
            ta.W5 = W5; ta.b5 = b5; ta.W6 = W6; ta.b6 = b6;
            ta.W8 = W8; ta.b8 = b8; ta.W9 = W9; ta.b9 = b9;
            ta.eps_inf = eps_inf; ta.eps_pri = eps_pri;
            ta.fake = out_fake; ta.out_mean = out_mean; ta.out_lv = out_lv; ta.out_z = out_z;
            ta.t = t;
            tail_kernel<<<Bn / 32, 256, SMTAIL>>>(ta);
        }
    }
}

// round 13
// speedup vs baseline: 1.2389x; 1.0607x over previous
#include <cuda_runtime.h>
#include <cuda.h>
#include <cuda_bf16.h>
#include <math.h>
#include <stdint.h>

#define Bn   4096
#define Hd   512
#define Fd   256
#define Zd   64
#define Td   16
#define Gd   2048
#define XK   832      // bf16 X row: [z(64) | y(256) | h(512)]
#define IK   1024     // head K:     [c(512) | y_j(256) | y_prev(256)]
#define CK   512      // c buffer row

// ---------------- persistent buffers ----------------
__device__ float g_baseg [(size_t)Bn * Gd];
__device__ float g_basehz[Bn * 128];
__device__ float g_c     [Bn * Hd];
__device__ float g_blstmp[Gd];
__device__ float g_bhz   [128];

__device__ __nv_bfloat16 g_Xh0[(size_t)Bn * XK], g_Xl0[(size_t)Bn * XK];
__device__ __nv_bfloat16 g_Xh1[(size_t)Bn * XK], g_Xl1[(size_t)Bn * XK];
__device__ __nv_bfloat16 g_Ch [(size_t)Bn * CK], g_Cl [(size_t)Bn * CK];
__device__ __nv_bfloat16 g_hih[(size_t)Bn * Hd], g_hil[(size_t)Bn * Hd];

__device__ __nv_bfloat16 g_WcatT_h[(size_t)Gd * XK], g_WcatT_l[(size_t)Gd * XK];
__device__ __nv_bfloat16 g_WxhT_h [(size_t)Gd * Hd], g_WxhT_l [(size_t)Gd * Hd];
__device__ __nv_bfloat16 g_W1T_h  [Fd * Hd], g_W1T_l  [Fd * Hd];
__device__ __nv_bfloat16 g_W2T_h  [Fd * Fd], g_W2T_l  [Fd * Fd];
__device__ __nv_bfloat16 g_W3T_h  [Fd * Fd], g_W3T_l  [Fd * Fd];
__device__ __nv_bfloat16 g_WheadT_h[128 * IK], g_WheadT_l[128 * IK];
__device__ __nv_bfloat16 g_WbaseT_h[128 * Hd], g_WbaseT_l[128 * Hd];

// ---------------- helpers ----------------
__device__ __forceinline__ void bsplit(float v, __nv_bfloat16& h, __nv_bfloat16& l) {
    h = __float2bfloat16_rn(v);
    l = __float2bfloat16_rn(v - __bfloat162float(h));
}
__device__ __forceinline__ uint32_t bpack(__nv_bfloat16 a, __nv_bfloat16 b) {
    __nv_bfloat162 t; t.x = a; t.y = b;
    return reinterpret_cast<uint32_t&>(t);
}
__device__ __forceinline__ __nv_bfloat162 bmk2(__nv_bfloat16 a, __nv_bfloat16 b) {
    __nv_bfloat162 t; t.x = a; t.y = b; return t;
}
__device__ __forceinline__ float fsig(float x) {
    return __fdividef(1.f, 1.f + __expf(-x));
}
__device__ __forceinline__ float ftanh(float x) {
    return 2.f * fsig(2.f * x) - 1.f;
}
__device__ __forceinline__ void mma16816(float* c, const uint32_t* a, const uint32_t* b) {
    asm volatile(
        "mma.sync.aligned.m16n8k16.row.col.f32.bf16.bf16.f32 "
        "{%0,%1,%2,%3}, {%4,%5,%6,%7}, {%8,%9}, {%0,%1,%2,%3};\n"
        : "+f"(c[0]), "+f"(c[1]), "+f"(c[2]), "+f"(c[3])
        : "r"(a[0]), "r"(a[1]), "r"(a[2]), "r"(a[3]), "r"(b[0]), "r"(b[1]));
}
__device__ __forceinline__ void ldsm4(uint32_t& r0, uint32_t& r1, uint32_t& r2, uint32_t& r3,
                                      uint32_t addr) {
    asm volatile("ldmatrix.sync.aligned.m8n8.x4.shared.b16 {%0,%1,%2,%3}, [%4];"
        : "=r"(r0), "=r"(r1), "=r"(r2), "=r"(r3) : "r"(addr));
}
__device__ __forceinline__ void cpa16(void* dst, const void* src) {
    uint32_t d = (uint32_t)__cvta_generic_to_shared(dst);
    asm volatile("cp.async.cg.shared.global [%0], [%1], 16;\n" :: "r"(d), "l"(src));
}
#define CPA_COMMIT() asm volatile("cp.async.commit_group;\n")
#define CPA_WAIT1()  asm volatile("cp.async.wait_group 1;\n")
#define CPA_WAIT0()  asm volatile("cp.async.wait_group 0;\n")

__device__ __forceinline__ uint32_t smem_u32(const void* p) {
    return (uint32_t)__cvta_generic_to_shared(p);
}

// ---- TMA / mbarrier ----
#define MBAR_INIT(a, n) \
    asm volatile("mbarrier.init.shared.b64 [%0], %1;" :: "r"(a), "r"(n) : "memory")
#define MBAR_EXPECT_TX(a, bytes) \
    asm volatile("mbarrier.arrive.expect_tx.shared.b64 _, [%0], %1;" :: "r"(a), "r"(bytes) : "memory")
#define MBAR_WAIT(a, par) do { \
    asm volatile("{\n\t.reg .pred P1;\n\tWL%=:\n\t" \
        "mbarrier.try_wait.parity.acquire.cta.shared::cta.b64 P1, [%0], %1, 0x989680;\n\t" \
        "@P1 bra.uni WD%=;\n\tbra.uni WL%=;\n\tWD%=:\n\t}" \
        :: "r"(a), "r"(par) : "memory"); \
} while (0)
#define TMA2D(dst, mapp, cx, cy, mb) \
    asm volatile("cp.async.bulk.tensor.2d.shared::cta.global.tile.mbarrier::complete_tx::bytes " \
        "[%0], [%1, {%2, %3}], [%4];" \
        :: "r"(dst), "l"(mapp), "r"(cx), "r"(cy), "r"(mb) : "memory")

// ================= TMA + mma.sync gate kernel (unchanged from R12) =================
__global__ void __launch_bounds__(256) gate_tma(
    const __grid_constant__ CUtensorMap mAh,
    const __grid_constant__ CUtensorMap mAl,
    const __grid_constant__ CUtensorMap mBh,
    const __grid_constant__ CUtensorMap mBl,
    const float* __restrict__ baseg, float* __restrict__ cst,
    __nv_bfloat16* __restrict__ Xh, __nv_bfloat16* __restrict__ Xl,
    __nv_bfloat16* __restrict__ Chp, __nv_bfloat16* __restrict__ Clp)
{
    extern __shared__ char sm[];
    const uint32_t sb = smem_u32(sm);
    const int tid = threadIdx.x, warp = tid >> 5, lane = tid & 31;
    const int bm = blockIdx.y * 128, bn = blockIdx.x * 128;
    const uint32_t F0 = sb + 8, F1 = sb + 16;
    const int wm = (warp >> 2) * 64, wn = (warp & 3) * 32;
    const int gq = lane >> 2, tg = lane & 3;
    const int ch = lane >> 4, r7 = lane & 7;
    const int lrow = (lane & 15) * 128;

    if (tid == 0) { MBAR_INIT(F0, 1); MBAR_INIT(F1, 1); }
    __syncthreads();

    float acc[64];
#pragma unroll
    for (int i = 0; i < 64; i++) acc[i] = 0.f;

    if (tid == 0) {
        MBAR_EXPECT_TX(F0, 65536);
        uint32_t d = sb + 1024;
        TMA2D(d,         &mAh, 0, bm, F0);
        TMA2D(d + 16384, &mAl, 0, bm, F0);
        TMA2D(d + 32768, &mBh, 0, bn, F0);
        TMA2D(d + 49152, &mBl, 0, bn, F0);
        MBAR_EXPECT_TX(F1, 65536);
        d = sb + 1024 + 65536;
        TMA2D(d,         &mAh, 64, bm, F1);
        TMA2D(d + 16384, &mAl, 64, bm, F1);
        TMA2D(d + 32768, &mBh, 64, bn, F1);
        TMA2D(d + 49152, &mBl, 64, bn, F1);
    }

    int pf0 = 0, pf1 = 0;
    for (int c = 0; c <= 12; c++) {
        if ((c & 1) == 0) { MBAR_WAIT(F0, pf0); pf0 ^= 1; }
        else              { MBAR_WAIT(F1, pf1); pf1 ^= 1; }
        const uint32_t bo = sb + 1024 + (c & 1) * 65536;
        const uint32_t aH = bo, aL = bo + 16384, bH = bo + 32768, bL = bo + 49152;
#pragma unroll
        for (int g = 0; g < 4; g++) {
            const int xo = (((2 * g + ch) ^ r7) << 4) + lrow;
            uint32_t bhf[4][2], blf[4][2];
#pragma unroll
            for (int np = 0; np < 2; np++) {
                uint32_t r0, r1, r2, r3;
                ldsm4(r0, r1, r2, r3, bH + (wn + np * 16) * 128 + xo);
                bhf[2*np][0] = r0; bhf[2*np+1][0] = r1; bhf[2*np][1] = r2; bhf[2*np+1][1] = r3;
                ldsm4(r0, r1, r2, r3, bL + (wn + np * 16) * 128 + xo);
                blf[2*np][0] = r0; blf[2*np+1][0] = r1; blf[2*np][1] = r2; blf[2*np+1][1] = r3;
            }
#pragma unroll
            for (int mt = 0; mt < 4; mt++) {
                uint32_t ah[4], al[4];
                ldsm4(ah[0], ah[1], ah[2], ah[3], aH + (wm + mt * 16) * 128 + xo);
                ldsm4(al[0], al[1], al[2], al[3], aL + (wm + mt * 16) * 128 + xo);
#pragma unroll
                for (int nt = 0; nt < 4; nt++) {
                    float* a = acc + (mt * 4 + nt) * 4;
                    mma16816(a, ah, bhf[nt]);
                    mma16816(a, ah, blf[nt]);
                    mma16816(a, al, bhf[nt]);
                }
            }
        }
        __syncthreads();
        if (tid == 0 && c + 2 <= 12) {
            const uint32_t mb = (c & 1) ? F1 : F0;
            MBAR_EXPECT_TX(mb, 65536);
            const uint32_t d = sb + 1024 + (c & 1) * 65536;
            const int kc = (c + 2) * 64;
            TMA2D(d,         &mAh, kc, bm, mb);
            TMA2D(d + 16384, &mAl, kc, bm, mb);
            TMA2D(d + 32768, &mBh, kc, bn, mb);
            TMA2D(d + 49152, &mBl, kc, bn, mb);
        }
    }

    float* tile = (float*)(sm + 1024);
#pragma unroll
    for (int mt = 0; mt < 4; mt++)
#pragma unroll
        for (int nt = 0; nt < 4; nt++) {
            int r0 = wm + mt * 16 + gq, c0 = wn + nt * 8 + 2 * tg;
            float* a = acc + (mt * 4 + nt) * 4;
            tile[r0 * 128 + c0]           = a[0];
            tile[r0 * 128 + c0 + 1]       = a[1];
            tile[(r0 + 8) * 128 + c0]     = a[2];
            tile[(r0 + 8) * 128 + c0 + 1] = a[3];
        }
    __syncthreads();

    for (int idx = tid; idx < 128 * 32; idx += 256) {
        int row = idx >> 5, w = idx & 31;
        int b = bm + row, jg = blockIdx.x * 32 + w;
        const float* bg = baseg + (size_t)b * Gd + bn;
        float ig = tile[row * 128 + w]      + bg[w];
        float fg = tile[row * 128 + 32 + w] + bg[32 + w];
        float gg = tile[row * 128 + 64 + w] + bg[64 + w];
        float og = tile[row * 128 + 96 + w] + bg[96 + w];
        float si = fsig(ig), sf = fsig(fg), so = fsig(og);
        float cn = sf * cst[b * Hd + jg] + si * ftanh(gg);
        float hn = so * ftanh(cn);
        cst[b * Hd + jg] = cn;
        __nv_bfloat16 hh, hl, cc, cl;
        bsplit(hn, hh, hl); bsplit(cn, cc, cl);
        Xh[(size_t)b * XK + 320 + jg] = hh;
        Xl[(size_t)b * XK + 320 + jg] = hl;
        Chp[(size_t)b * CK + jg] = cc;
        Clp[(size_t)b * CK + jg] = cl;
    }
}

// ================= mma.sync GEMM (base GEMMs; 80B-row layout) =================
struct GArgs {
    const __nv_bfloat16 *Ah, *Al; int lda;
    const __nv_bfloat16 *Bh, *Bl; int ldb;
    const float* Ci; int ldci;
    float* C; int ldc;
    int K;
};

template<int MT,int NTL,int AHS,int BHS>
__device__ __forceinline__ void stage_mma2(const char* Ab, const char* Bb, float* acc,
                                           int wm, int wn, int laneoff)
{
    uint32_t aH = smem_u32(Ab) + laneoff;
    uint32_t bH = smem_u32(Bb) + laneoff;
#pragma unroll
    for (int kk = 0; kk < 2; kk++) {
        const int kb = kk * 32;
        uint32_t bhf[NTL][2], blf[NTL][2];
#pragma unroll
        for (int np = 0; np < NTL / 2; np++) {
            uint32_t r0, r1, r2, r3;
            ldsm4(r0, r1, r2, r3, bH + (wn + np * 16) * 80 + kb);
            bhf[2*np][0] = r0; bhf[2*np+1][0] = r1; bhf[2*np][1] = r2; bhf[2*np+1][1] = r3;
            ldsm4(r0, r1, r2, r3, bH + BHS + (wn + np * 16) * 80 + kb);
            blf[2*np][0] = r0; blf[2*np+1][0] = r1; blf[2*np][1] = r2; blf[2*np+1][1] = r3;
        }
#pragma unroll
        for (int mt = 0; mt < MT; mt++) {
            uint32_t ah[4], al[4];
            ldsm4(ah[0], ah[1], ah[2], ah[3], aH + (wm + mt * 16) * 80 + kb);
            ldsm4(al[0], al[1], al[2], al[3], aH + AHS + (wm + mt * 16) * 80 + kb);
#pragma unroll
            for (int nt = 0; nt < NTL; nt++) {
                float* a = acc + (mt * NTL + nt) * 4;
                mma16816(a, ah, bhf[nt]);
                mma16816(a, ah, blf[nt]);
                mma16816(a, al, bhf[nt]);
            }
        }
    }
}

template<int BM,int BN,int NTH>
__device__ __forceinline__ void stage_load(char* base, int tid, int bm, int bn,
    const __nv_bfloat16* Ah, const __nv_bfloat16* Al, int lda,
    const __nv_bfloat16* Bh, const __nv_bfloat16* Bl, int ldb, int k0)
{
#pragma unroll
    for (int i = tid; i < BM * 4; i += NTH) {
        int row = i >> 2, c4 = (i & 3) * 16;
        size_t off = ((size_t)(bm + row) * lda + k0) * 2 + c4;
        cpa16(base + row * 80 + c4, (const char*)Ah + off);
        cpa16(base + BM * 80 + row * 80 + c4, (const char*)Al + off);
    }
#pragma unroll
    for (int i = tid; i < BN * 4; i += NTH) {
        int row = i >> 2, c4 = (i & 3) * 16;
        size_t off = ((size_t)(bn + row) * ldb + k0) * 2 + c4;
        cpa16(base + BM * 160 + row * 80 + c4, (const char*)Bh + off);
        cpa16(base + BM * 160 + BN * 80 + row * 80 + c4, (const char*)Bl + off);
    }
    CPA_COMMIT();
}

template<int BM,int BN,int WM,int WN,int NTH>
__global__ void __launch_bounds__(NTH) gemm(GArgs g)
{
    extern __shared__ char sm[];
    constexpr int MT = WM / 16, NTL = WN / 8, NWN = BN / WN;
    constexpr int stageB = (BM + BN) * 160;
    const int tid = threadIdx.x, warp = tid >> 5, lane = tid & 31;
    const int gq = lane >> 2, tg = lane & 3;
    const int laneoff = (lane & 15) * 80 + (lane >> 4) * 16;
    const int wm = (warp / NWN) * WM, wn = (warp % NWN) * WN;
    const int bm = blockIdx.y * BM, bn = blockIdx.x * BN;
    const int K = g.K;

    float acc[MT * NTL * 4];
#pragma unroll
    for (int i = 0; i < MT * NTL * 4; i++) acc[i] = 0.f;

    const int nk = K >> 5;
    stage_load<BM,BN,NTH>(sm, tid, bm, bn, g.Ah, g.Al, g.lda, g.Bh, g.Bl, g.ldb, 0);
    for (int kt = 0; kt < nk; kt++) {
        if (kt + 1 < nk) {
            stage_load<BM,BN,NTH>(sm + ((kt + 1) & 1) * stageB, tid, bm, bn,
                                  g.Ah, g.Al, g.lda, g.Bh, g.Bl, g.ldb, (kt + 1) << 5);
            CPA_WAIT1();
        } else CPA_WAIT0();
        __syncthreads();
        const char* cur = sm + (kt & 1) * stageB;
        stage_mma2<MT,NTL,BM*80,BN*80>(cur, cur + BM * 160, acc, wm, wn, laneoff);
        __syncthreads();
    }

#pragma unroll
    for (int mt = 0; mt < MT; mt++)
#pragma unroll
        for (int nt = 0; nt < NTL; nt++) {
            float* a = acc + (mt * NTL + nt) * 4;
#pragma unroll
            for (int half = 0; half < 2; half++) {
                int r = bm + wm + mt * 16 + gq + half * 8;
                int c = bn + wn + nt * 8 + 2 * tg;
                float v0 = a[half * 2] + g.Ci[c], v1 = a[half * 2 + 1] + g.Ci[c + 1];
                *(float2*)&g.C[(size_t)r * g.ldc + c] = make_float2(v0, v1);
            }
        }
}

// ================= fused tail kernel (3-buffer, 1 barrier/stage; fast finish) =================
// smem: stages 3 x 46080 = 138240 | tA @138240 (40960) | tB @179200 (40960); total 220160
struct TailArgs {
    const __nv_bfloat16 *XwH, *XwL;
    __nv_bfloat16 *XwHm, *XwLm;
    const __nv_bfloat16 *XrH, *XrL;
    const __nv_bfloat16 *Ch, *Cl;
    const float* basehz;
    const float *b1, *b2, *b3;
    const float *W5, *b5, *W6, *b6, *W8, *b8, *W9, *b9;
    const float *eps_inf, *eps_pri;
    float *fake, *out_mean, *out_lv, *out_z;
    int t;
};

template<int BN,int NTH>
__device__ __forceinline__ void tail_loadB(char* st, int tid,
    const __nv_bfloat16* Bh, const __nv_bfloat16* Bl, int ldb, int kg)
{
#pragma unroll
    for (int i = tid; i < BN * 4; i += NTH) {
        int row = i >> 2, c4 = (i & 3) * 16;
        size_t off = ((size_t)row * ldb + kg) * 2 + c4;
        cpa16(st + row * 80 + c4, (const char*)Bh + off);
        cpa16(st + BN * 80 + row * 80 + c4, (const char*)Bl + off);
    }
}

__device__ __forceinline__ void tail_loadA(char* st, int tid, int r0,
    const __nv_bfloat16* Ah, const __nv_bfloat16* Al, int lda, int kg)
{
    if (tid >= 128) return;
    int arow = tid >> 2, ac4 = (tid & 3) * 16;
    size_t off = ((size_t)(r0 + arow) * lda + kg) * 2 + ac4;
    cpa16(st + arow * 80 + ac4, (const char*)Ah + off);
    cpa16(st + 2560 + arow * 80 + ac4, (const char*)Al + off);
}

template<int NTL>
__device__ __forceinline__ void epi_chunk(const float* acc, const float* bias,
                                          char* dst, int wn, int gq, int tg)
{
#pragma unroll
    for (int mt = 0; mt < 2; mt++)
#pragma unroll
        for (int nt = 0; nt < NTL; nt++)
#pragma unroll
            for (int half = 0; half < 2; half++) {
                int row = mt * 16 + gq + half * 8;
                int col = wn + nt * 8 + 2 * tg;
                const float* a = acc + (mt * NTL + nt) * 4 + half * 2;
                float v0 = fmaxf(a[0] + bias[col], 0.f);
                float v1 = fmaxf(a[1] + bias[col + 1], 0.f);
                __nv_bfloat16 h0, l0, h1, l1;
                bsplit(v0, h0, l0); bsplit(v1, h1, l1);
                char* cb = dst + (col >> 5) * 5120;
                int kp = (col & 31) >> 1;
                ((uint32_t*)cb)[row * 20 + kp] = bpack(h0, h1);
                ((uint32_t*)(cb + 2560))[row * 20 + kp] = bpack(l0, l1);
            }
}

__global__ void __launch_bounds__(256) tail_kernel(TailArgs g)
{
    extern __shared__ char sm[];
    char* stages = sm;
    char* tA = sm + 138240;
    char* tB = sm + 179200;
    float* hzc = (float*)tB;

    const int tid = threadIdx.x, lane = tid & 31, warp = tid >> 5;
    const int gq = lane >> 2, tg = lane & 3;
    const int laneoff = (lane & 15) * 80 + (lane >> 4) * 16;
    const int r0 = blockIdx.x * 32;
    constexpr int DST = 46080;
    constexpr int HST = 25600;

    // ---------- dec1: K=512, 16 stages, 3-buffer, 1 barrier/stage ----------
    {
        float acc[32];
#pragma unroll
        for (int i = 0; i < 32; i++) acc[i] = 0.f;
        tail_loadA(stages, tid, r0, g.XwH + 320, g.XwL + 320, XK, 0);
        tail_loadB<256,256>(stages + 5120, tid, g_W1T_h, g_W1T_l, Hd, 0);
        CPA_COMMIT();
        tail_loadA(stages + DST, tid, r0, g.XwH + 320, g.XwL + 320, XK, 32);
        tail_loadB<256,256>(stages + DST + 5120, tid, g_W1T_h, g_W1T_l, Hd, 32);
        CPA_COMMIT();
        int cb = 0;
        for (int kt = 0; kt < 16; kt++) {
            if (kt + 1 < 16) CPA_WAIT1(); else CPA_WAIT0();
            __syncthreads();
            if (kt + 2 < 16) {
                int nb = cb + 2; if (nb >= 3) nb -= 3;
                tail_loadA(stages + nb * DST, tid, r0, g.XwH + 320, g.XwL + 320, XK, (kt + 2) * 32);
                tail_loadB<256,256>(stages + nb * DST + 5120, tid, g_W1T_h, g_W1T_l, Hd, (kt + 2) * 32);
                CPA_COMMIT();
            }
            char* cur = stages + cb * DST;
            stage_mma2<2,4,2560,20480>(cur, cur + 5120, acc, 0, warp * 32, laneoff);
            if (++cb == 3) cb = 0;
        }
        __syncthreads();
        epi_chunk<4>(acc, g.b1, tA, warp * 32, gq, tg);
        __syncthreads();
    }
    // ---------- dec2: K=256 (A local in tA), 8 stages ----------
    {
        float acc[32];
#pragma unroll
        for (int i = 0; i < 32; i++) acc[i] = 0.f;
        tail_loadB<256,256>(stages + 5120, tid, g_W2T_h, g_W2T_l, Fd, 0);
        CPA_COMMIT();
        tail_loadB<256,256>(stages + DST + 5120, tid, g_W2T_h, g_W2T_l, Fd, 32);
        CPA_COMMIT();
        int cb = 0;
        for (int kt = 0; kt < 8; kt++) {
            if (kt + 1 < 8) CPA_WAIT1(); else CPA_WAIT0();
            __syncthreads();
            if (kt + 2 < 8) {
                int nb = cb + 2; if (nb >= 3) nb -= 3;
                tail_loadB<256,256>(stages + nb * DST + 5120, tid, g_W2T_h, g_W2T_l, Fd, (kt + 2) * 32);
                CPA_COMMIT();
            }
            stage_mma2<2,4,2560,20480>(tA + kt * 5120, stages + cb * DST + 5120, acc, 0, warp * 32, laneoff);
            if (++cb == 3) cb = 0;
        }
        __syncthreads();
        epi_chunk<4>(acc, g.b2, tB, warp * 32, gq, tg);
        __syncthreads();
    }
    // ---------- dec3: K=256 (A local in tB), 8 stages ----------
    {
        float acc[32];
#pragma unroll
        for (int i = 0; i < 32; i++) acc[i] = 0.f;
        tail_loadB<256,256>(stages + 5120, tid, g_W3T_h, g_W3T_l, Fd, 0);
        CPA_COMMIT();
        tail_loadB<256,256>(stages + DST + 5120, tid, g_W3T_h, g_W3T_l, Fd, 32);
        CPA_COMMIT();
        int cb = 0;
        for (int kt = 0; kt < 8; kt++) {
            if (kt + 1 < 8) CPA_WAIT1(); else CPA_WAIT0();
            __syncthreads();
            if (kt + 2 < 8) {
                int nb = cb + 2; if (nb >= 3) nb -= 3;
                tail_loadB<256,256>(stages + nb * DST + 5120, tid, g_W3T_h, g_W3T_l, Fd, (kt + 2) * 32);
                CPA_COMMIT();
            }
            stage_mma2<2,4,2560,20480>(tB + kt * 5120, stages + cb * DST + 5120, acc, 0, warp * 32, laneoff);
            if (++cb == 3) cb = 0;
        }
        __syncthreads();
#pragma unroll
        for (int mt = 0; mt < 2; mt++)
#pragma unroll
            for (int nt = 0; nt < 4; nt++)
#pragma unroll
                for (int half = 0; half < 2; half++) {
                    int row = mt * 16 + gq + half * 8;
                    int col = warp * 32 + nt * 8 + 2 * tg;
                    int b = r0 + row;
                    const float* a = acc + (mt * 4 + nt) * 4 + half * 2;
                    float v0 = fmaxf(a[0] + g.b3[col], 0.f);
                    float v1 = fmaxf(a[1] + g.b3[col + 1], 0.f);
                    *(float2*)&g.fake[(size_t)b * (Td * Fd) + g.t * Fd + col] = make_float2(v0, v1);
                    __nv_bfloat16 h0, l0, h1, l1;
                    bsplit(v0, h0, l0); bsplit(v1, h1, l1);
                    *(__nv_bfloat162*)&g.XwHm[(size_t)b * XK + 64 + col] = bmk2(h0, h1);
                    *(__nv_bfloat162*)&g.XwLm[(size_t)b * XK + 64 + col] = bmk2(l0, l1);
                    char* cb2 = tA + (col >> 5) * 5120;
                    int kp = (col & 31) >> 1;
                    ((uint32_t*)cb2)[row * 20 + kp] = bpack(h0, h1);
                    ((uint32_t*)(cb2 + 2560))[row * 20 + kp] = bpack(l0, l1);
                }
        __syncthreads();
    }
    // ---------- head: K=1024, 32 stages (A: c global / yj local / yprev global) ----------
    {
        float acc[16];
#pragma unroll
        for (int i = 0; i < 16; i++) acc[i] = 0.f;
        tail_loadA(stages, tid, r0, g.Ch, g.Cl, CK, 0);
        tail_loadB<128,256>(stages + 5120, tid, g_WheadT_h, g_WheadT_l, IK, 0);
        CPA_COMMIT();
        tail_loadA(stages + HST, tid, r0, g.Ch, g.Cl, CK, 32);
        tail_loadB<128,256>(stages + HST + 5120, tid, g_WheadT_h, g_WheadT_l, IK, 32);
        CPA_COMMIT();
        int cb = 0;
        for (int kt = 0; kt < 32; kt++) {
            if (kt + 1 < 32) CPA_WAIT1(); else CPA_WAIT0();
            __syncthreads();
            if (kt + 2 < 32) {
                int nb = cb + 2; if (nb >= 3) nb -= 3;
                int kn = kt + 2;
                char* nxt = stages + nb * HST;
                if (kn < 16)       tail_loadA(nxt, tid, r0, g.Ch, g.Cl, CK, kn * 32);
                else if (kn >= 24) tail_loadA(nxt, tid, r0, g.XrH, g.XrL, XK, 64 + (kn - 24) * 32);
                tail_loadB<128,256>(nxt + 5120, tid, g_WheadT_h, g_WheadT_l, IK, kn * 32);
                CPA_COMMIT();
            }
            char* cur = stages + cb * HST;
            const char* Ab = (kt >= 16 && kt < 24) ? (tA + (kt - 16) * 5120) : cur;
            stage_mma2<2,2,2560,10240>(Ab, cur + 5120, acc, 0, warp * 16, laneoff);
            if (++cb == 3) cb = 0;
        }
        __syncthreads();
#pragma unroll
        for (int mt = 0; mt < 2; mt++)
#pragma unroll
            for (int nt = 0; nt < 2; nt++)
#pragma unroll
                for (int half = 0; half < 2; half++) {
                    int row = mt * 16 + gq + half * 8;
                    int col = warp * 16 + nt * 8 + 2 * tg;
                    const float* a = acc + (mt * 2 + nt) * 4 + half * 2;
                    const float* bz = g.basehz + (size_t)(r0 + row) * 128 + col;
                    hzc[row * 130 + col]     = fmaxf(a[0] + bz[0], 0.f);
                    hzc[row * 130 + col + 1] = fmaxf(a[1] + bz[1], 0.f);
                }
        __syncthreads();
    }
    // ---------- finish: k-outer, weight loads hoisted (256 LDG/thread) ----------
    {
        const int z = tid & 63, rb = tid >> 6;      // rows rb, rb+4, ..., rb+28
        float m[8], l[8], mp[8], lp[8];
#pragma unroll
        for (int i = 0; i < 8; i++) { m[i] = g.b5[z]; l[i] = g.b6[z]; mp[i] = g.b8[z]; lp[i] = g.b9[z]; }
#pragma unroll 4
        for (int k = 0; k < 64; k++) {
            float w5 = g.W5[k * Zd + z], w6 = g.W6[k * Zd + z];
            float w8 = g.W8[k * Zd + z], w9 = g.W9[k * Zd + z];
#pragma unroll
            for (int i = 0; i < 8; i++) {
                int row = rb + 4 * i;
                float av = hzc[row * 130 + k];
                float ap = hzc[row * 130 + 64 + k];
                m[i]  += av * w5;  l[i]  += av * w6;
                mp[i] += ap * w8;  lp[i] += ap * w9;
            }
        }
#pragma unroll
        for (int i = 0; i < 8; i++) {
            int row = rb + 4 * i, b = r0 + row;
            float mm = fmaxf(m[i], 0.f),  ll = fmaxf(l[i], 0.f);
            float mmp = fmaxf(mp[i], 0.f), llp = fmaxf(lp[i], 0.f);
            size_t gi = (size_t)b * Zd + z;
            float zi = mm  + g.eps_inf[(size_t)g.t * Bn * Zd + gi] * __expf(0.5f * ll);
            float zp = mmp + g.eps_pri[(size_t)g.t * Bn * Zd + gi] * __expf(0.5f * llp);
            g.out_mean[(size_t)b * Td * Zd + (size_t)g.t * Zd + z] = mm;
            g.out_lv  [(size_t)b * Td * Zd + (size_t)g.t * Zd + z] = ll;
            g.out_z[(size_t)(2 * g.t)     * Bn * Zd + gi] = zi;
            g.out_z[(size_t)(2 * g.t + 1) * Bn * Zd + gi] = zp;
            __nv_bfloat16 zh, zl; bsplit(zi, zh, zl);
            g.XwHm[(size_t)b * XK + z] = zh;
            g.XwLm[(size_t)b * XK + z] = zl;
        }
    }
}

// ---------------- single merged prep kernel ----------------
__device__ __forceinline__ int perm_n(int np) {
    int chunk = np >> 7, r = np & 127, gate = r >> 5, w = r & 31;
    return gate * 512 + chunk * 32 + w;
}

__global__ void prep_all(const float* __restrict__ h_i,
                         const float* __restrict__ Wx, const float* __restrict__ Wh,
                         const float* __restrict__ bl,
                         const float* __restrict__ W1, const float* __restrict__ W2,
                         const float* __restrict__ W3,
                         const float* __restrict__ W4, const float* __restrict__ W7,
                         const float* __restrict__ b4, const float* __restrict__ b7)
{
    size_t i = (size_t)blockIdx.x * blockDim.x + threadIdx.x;
    __nv_bfloat16 h, l;

    const size_t nX = (size_t)Bn * XK;
    if (i < nX) {
        __nv_bfloat16 z = __float2bfloat16(0.f);
        g_Xh0[i] = z; g_Xl0[i] = z; g_Xh1[i] = z; g_Xl1[i] = z;
        return;
    }
    i -= nX;
    const size_t nC = (size_t)Bn * Hd;
    if (i < nC) { g_c[i] = 0.f; return; }
    i -= nC;
    if (i < (size_t)Bn * Hd) {
        bsplit(h_i[i], h, l);
        g_hih[i] = h; g_hil[i] = l;
        return;
    }
    i -= (size_t)Bn * Hd;
    if (i < (size_t)Gd * XK) {
        int k = (int)(i % XK), np = (int)(i / XK);
        int n = perm_n(np);
        float v;
        if (k < 64)       v = Wx[(size_t)k * Gd + n];
        else if (k < 320) v = Wx[(size_t)(512 + k) * Gd + n];
        else              v = Wh[(size_t)(k - 320) * Gd + n];
        bsplit(v, h, l);
        g_WcatT_h[i] = h; g_WcatT_l[i] = l;
        return;
    }
    i -= (size_t)Gd * XK;
    if (i < (size_t)Gd * Hd) {
        int k = (int)(i % Hd), np = (int)(i / Hd);
        int n = perm_n(np);
        bsplit(Wx[(size_t)(64 + k) * Gd + n], h, l);
        g_WxhT_h[i] = h; g_WxhT_l[i] = l;
        if (k == 0) g_blstmp[np] = bl[n];
        return;
    }
    i -= (size_t)Gd * Hd;
    if (i < (size_t)Fd * Hd) {
        int k = (int)(i % Hd), n = (int)(i / Hd);
        bsplit(W1[(size_t)k * Fd + n], h, l);
        g_W1T_h[i] = h; g_W1T_l[i] = l;
        return;
    }
    i -= (size_t)Fd * Hd;
    if (i < (size_t)Fd * Fd) {
        int k = (int)(i % Fd), n = (int)(i / Fd);
        bsplit(W2[(size_t)k * Fd + n], h, l);
        g_W2T_h[i] = h; g_W2T_l[i] = l;
        return;
    }
    i -= (size_t)Fd * Fd;
    if (i < (size_t)Fd * Fd) {
        int k = (int)(i % Fd), n = (int)(i / Fd);
        bsplit(W3[(size_t)k * Fd + n], h, l);
        g_W3T_h[i] = h; g_W3T_l[i] = l;
        return;
    }
    i -= (size_t)Fd * Fd;
    if (i < (size_t)128 * IK) {
        int k = (int)(i % IK), n = (int)(i / IK);
        float v;
        if (n < 64) v = W4[(size_t)(512 + k) * Zd + n];
        else {
            int n2 = n - 64;
            if (k < 512)      v = W7[(size_t)(512 + k) * Zd + n2];
            else if (k < 768) v = 0.f;
            else              v = W7[(size_t)(1024 + k - 768) * Zd + n2];
        }
        bsplit(v, h, l);
        g_WheadT_h[i] = h; g_WheadT_l[i] = l;
        return;
    }
    i -= (size_t)128 * IK;
    if (i < (size_t)128 * Hd) {
        int k = (int)(i % Hd), n = (int)(i / Hd);
        float v = (n < 64) ? W4[(size_t)k * Zd + n] : W7[(size_t)k * Zd + (n - 64)];
        bsplit(v, h, l);
        g_WbaseT_h[i] = h; g_WbaseT_l[i] = l;
        if (k == 0) g_bhz[n] = (n < 64) ? b4[n] : b7[n - 64];
    }
}

// ---------------- host ----------------
template<typename T> static T* sym(const void* s) { void* p = nullptr; cudaGetSymbolAddress(&p, s); return (T*)p; }

typedef CUresult (*PFN_encode)(CUtensorMap*, CUtensorMapDataType, cuuint32_t, void*,
                               const cuuint64_t*, const cuuint64_t*, const cuuint32_t*,
                               const cuuint32_t*, CUtensorMapInterleave, CUtensorMapSwizzle,
                               CUtensorMapL2promotion, CUtensorMapFloatOOBfill);

static void make_map(PFN_encode enc, CUtensorMap* m, void* base, unsigned long long rows) {
    cuuint64_t dims[2]    = {(cuuint64_t)XK, (cuuint64_t)rows};
    cuuint64_t strides[1] = {(cuuint64_t)XK * 2};
    cuuint32_t box[2]     = {64, 128};
    cuuint32_t es[2]      = {1, 1};
    enc(m, CU_TENSOR_MAP_DATA_TYPE_BFLOAT16, 2, base, dims, strides, box, es,
        CU_TENSOR_MAP_INTERLEAVE_NONE, CU_TENSOR_MAP_SWIZZLE_128B,
        CU_TENSOR_MAP_L2_PROMOTION_L2_128B, CU_TENSOR_MAP_FLOAT_OOB_FILL_NONE);
}

extern "C" void kernel_launch(void* const* d_in, const int* in_sizes, int n_in,
                              void* d_out, int out_size) {
    const float* h_i     = (const float*)d_in[0];
    const float* eps_inf = (const float*)d_in[1];
    const float* eps_pri = (const float*)d_in[2];
    const float* Wx      = (const float*)d_in[3];
    const float* Wh      = (const float*)d_in[4];
    const float* b_lstm  = (const float*)d_in[5];
    const float* W1 = (const float*)d_in[6],  *b1 = (const float*)d_in[7];
    const float* W2 = (const float*)d_in[8],  *b2 = (const float*)d_in[9];
    const float* W3 = (const float*)d_in[10], *b3 = (const float*)d_in[11];
    const float* W4 = (const float*)d_in[12], *b4 = (const float*)d_in[13];
    const float* W5 = (const float*)d_in[14], *b5 = (const float*)d_in[15];
    const float* W6 = (const float*)d_in[16], *b6 = (const float*)d_in[17];
    const float* W7 = (const float*)d_in[18], *b7 = (const float*)d_in[19];
    const float* W8 = (const float*)d_in[20], *b8 = (const float*)d_in[21];
    const float* W9 = (const float*)d_in[22], *b9 = (const float*)d_in[23];

    float* out      = (float*)d_out;
    float* out_fake = out;
    float* out_mean = out_fake + (size_t)Bn * Td * Fd;
    float* out_lv   = out_mean + (size_t)Bn * Td * Zd;
    float* out_z    = out_lv   + (size_t)Bn * Td * Zd;

    __nv_bfloat16* Xh0 = sym<__nv_bfloat16>(g_Xh0); __nv_bfloat16* Xl0 = sym<__nv_bfloat16>(g_Xl0);
    __nv_bfloat16* Xh1 = sym<__nv_bfloat16>(g_Xh1); __nv_bfloat16* Xl1 = sym<__nv_bfloat16>(g_Xl1);
    __nv_bfloat16* Ch  = sym<__nv_bfloat16>(g_Ch);  __nv_bfloat16* Cl  = sym<__nv_bfloat16>(g_Cl);

    float* pBaseg  = sym<float>(g_baseg);
    float* pBasehz = sym<float>(g_basehz);
    float* pBlstmp = sym<float>(g_blstmp);
    float* pBhz    = sym<float>(g_bhz);

    PFN_encode enc = nullptr;
    {
        void* fn = nullptr;
        cudaDriverEntryPointQueryResult st;
#if CUDART_VERSION >= 12050
        cudaGetDriverEntryPointByVersion("cuTensorMapEncodeTiled", &fn, 12000,
                                         cudaEnableDefault, &st);
#else
        cudaGetDriverEntryPoint("cuTensorMapEncodeTiled", &fn, cudaEnableDefault, &st);
#endif
        enc = (PFN_encode)fn;
    }
    static CUtensorMap mX[4], mW[2];
    make_map(enc, &mX[0], Xh0, Bn); make_map(enc, &mX[1], Xl0, Bn);
    make_map(enc, &mX[2], Xh1, Bn); make_map(enc, &mX[3], Xl1, Bn);
    make_map(enc, &mW[0], sym<__nv_bfloat16>(g_WcatT_h), Gd);
    make_map(enc, &mW[1], sym<__nv_bfloat16>(g_WcatT_l), Gd);

    constexpr int SMBASE  = 2 * (256 + 128) * 160;
    constexpr int SMSMALL = 2 * (64 + 64) * 160;
    constexpr int SMTAIL  = 220160;
    constexpr int SMGATE  = 1024 + 2 * 65536;
    cudaFuncSetAttribute(gemm<256,128,64,64,256>, cudaFuncAttributeMaxDynamicSharedMemorySize, SMBASE);
    cudaFuncSetAttribute(gemm<64,64,32,32,128>,   cudaFuncAttributeMaxDynamicSharedMemorySize, SMSMALL);
    cudaFuncSetAttribute(tail_kernel,             cudaFuncAttributeMaxDynamicSharedMemorySize, SMTAIL);
    cudaFuncSetAttribute(gate_tma,                cudaFuncAttributeMaxDynamicSharedMemorySize, SMGATE);

    // ---- init ----
    {
        size_t tot = (size_t)Bn * XK + 2 * (size_t)Bn * Hd
                   + (size_t)Gd * XK + (size_t)Gd * Hd
                   + (size_t)Fd * Hd + 2 * (size_t)Fd * Fd
                   + (size_t)128 * IK + (size_t)128 * Hd;
        prep_all<<<(unsigned)((tot + 255) / 256), 256>>>(h_i, Wx, Wh, b_lstm,
                                                         W1, W2, W3, W4, W7, b4, b7);
    }

    // ---- hoisted base GEMMs ----
    {
        GArgs b{};
        b.Ah = sym<__nv_bfloat16>(g_hih); b.Al = sym<__nv_bfloat16>(g_hil); b.lda = Hd;
        b.Bh = sym<__nv_bfloat16>(g_WxhT_h); b.Bl = sym<__nv_bfloat16>(g_WxhT_l); b.ldb = Hd;
        b.Ci = pBlstmp; b.C = pBaseg; b.ldc = Gd; b.K = Hd;
        gemm<256,128,64,64,256><<<dim3(16, 16), 256, SMBASE>>>(b);

        b.Bh = sym<__nv_bfloat16>(g_WbaseT_h); b.Bl = sym<__nv_bfloat16>(g_WbaseT_l); b.ldb = Hd;
        b.Ci = pBhz; b.C = pBasehz; b.ldc = 128; b.K = Hd;
        gemm<64,64,32,32,128><<<dim3(2, 64), 128, SMSMALL>>>(b);
    }

    for (int t = 0; t < Td; t++) {
        __nv_bfloat16* XrH = (t & 1) ? Xh1 : Xh0;
        __nv_bfloat16* XrL = (t & 1) ? Xl1 : Xl0;
        __nv_bfloat16* XwH = (t & 1) ? Xh0 : Xh1;
        __nv_bfloat16* XwL = (t & 1) ? Xl0 : Xl1;
        const CUtensorMap& mAh = (t & 1) ? mX[2] : mX[0];
        const CUtensorMap& mAl = (t & 1) ? mX[3] : mX[1];

        gate_tma<<<dim3(16, 32), 256, SMGATE>>>(mAh, mAl, mW[0], mW[1],
                                                pBaseg, sym<float>(g_c),
                                                XwH, XwL, Ch, Cl);
        {
            TailArgs ta{};
            ta.XwH = XwH; ta.XwL = XwL; ta.XwHm = XwH; ta.XwLm = XwL;
            ta.XrH = XrH; ta.XrL = XrL;
            ta.Ch = Ch; ta.Cl = Cl;
            ta.basehz = pBasehz;
            ta.b1 = b1; ta.b2 = b2; ta.b3 = b3;
            ta.W5 = W5; ta.b5 = b5; ta.W6 = W6; ta.b6 = b6;
            ta.W8 = W8; ta.b8 = b8; ta.W9 = W9; ta.b9 = b9;
            ta.eps_inf = eps_inf; ta.eps_pri = eps_pri;
            ta.fake = out_fake; ta.out_mean = out_mean; ta.out_lv = out_lv; ta.out_z = out_z;
            ta.t = t;
            tail_kernel<<<Bn / 32, 256, SMTAIL>>>(ta);
        }
    }
}

// round 14
// speedup vs baseline: 1.5362x; 1.2400x over previous
#include <cuda_runtime.h>
#include <cuda.h>
#include <cuda_bf16.h>
#include <math.h>
#include <stdint.h>

#define Bn   4096
#define Hd   512
#define Fd   256
#define Zd   64
#define Td   16
#define Gd   2048
#define XK   832      // bf16 X row: [z(64) | y(256) | h(512)]
#define IK   1024     // head K:     [c(512) | y_j(256) | y_prev(256)]
#define CK   512      // c buffer row

// ---------------- persistent buffers ----------------
__device__ float g_baseg [(size_t)Bn * Gd];
__device__ float g_basehz[Bn * 128];
__device__ float g_c     [Bn * Hd];
__device__ float g_blstmp[Gd];
__device__ float g_bhz   [128];

__device__ __nv_bfloat16 g_Xh0[(size_t)Bn * XK], g_Xl0[(size_t)Bn * XK];
__device__ __nv_bfloat16 g_Xh1[(size_t)Bn * XK], g_Xl1[(size_t)Bn * XK];
__device__ __nv_bfloat16 g_Ch [(size_t)Bn * CK], g_Cl [(size_t)Bn * CK];
__device__ __nv_bfloat16 g_hih[(size_t)Bn * Hd], g_hil[(size_t)Bn * Hd];

__device__ __nv_bfloat16 g_WcatT_h[(size_t)Gd * XK], g_WcatT_l[(size_t)Gd * XK];
__device__ __nv_bfloat16 g_WxhT_h [(size_t)Gd * Hd], g_WxhT_l [(size_t)Gd * Hd];
__device__ __nv_bfloat16 g_W1T_h  [Fd * Hd], g_W1T_l  [Fd * Hd];
__device__ __nv_bfloat16 g_W2T_h  [Fd * Fd], g_W2T_l  [Fd * Fd];
__device__ __nv_bfloat16 g_W3T_h  [Fd * Fd], g_W3T_l  [Fd * Fd];
__device__ __nv_bfloat16 g_WheadT_h[128 * IK], g_WheadT_l[128 * IK];
__device__ __nv_bfloat16 g_WbaseT_h[128 * Hd], g_WbaseT_l[128 * Hd];

// ---------------- helpers ----------------
__device__ __forceinline__ void bsplit(float v, __nv_bfloat16& h, __nv_bfloat16& l) {
    h = __float2bfloat16_rn(v);
    l = __float2bfloat16_rn(v - __bfloat162float(h));
}
__device__ __forceinline__ uint32_t bpack(__nv_bfloat16 a, __nv_bfloat16 b) {
    __nv_bfloat162 t; t.x = a; t.y = b;
    return reinterpret_cast<uint32_t&>(t);
}
__device__ __forceinline__ __nv_bfloat162 bmk2(__nv_bfloat16 a, __nv_bfloat16 b) {
    __nv_bfloat162 t; t.x = a; t.y = b; return t;
}
__device__ __forceinline__ float fsig(float x) {
    return __fdividef(1.f, 1.f + __expf(-x));
}
__device__ __forceinline__ float ftanh(float x) {
    return 2.f * fsig(2.f * x) - 1.f;
}
__device__ __forceinline__ void mma16816(float* c, const uint32_t* a, const uint32_t* b) {
    asm volatile(
        "mma.sync.aligned.m16n8k16.row.col.f32.bf16.bf16.f32 "
        "{%0,%1,%2,%3}, {%4,%5,%6,%7}, {%8,%9}, {%0,%1,%2,%3};\n"
        : "+f"(c[0]), "+f"(c[1]), "+f"(c[2]), "+f"(c[3])
        : "r"(a[0]), "r"(a[1]), "r"(a[2]), "r"(a[3]), "r"(b[0]), "r"(b[1]));
}
__device__ __forceinline__ void ldsm4(uint32_t& r0, uint32_t& r1, uint32_t& r2, uint32_t& r3,
                                      uint32_t addr) {
    asm volatile("ldmatrix.sync.aligned.m8n8.x4.shared.b16 {%0,%1,%2,%3}, [%4];"
        : "=r"(r0), "=r"(r1), "=r"(r2), "=r"(r3) : "r"(addr));
}
__device__ __forceinline__ void cpa16(void* dst, const void* src) {
    uint32_t d = (uint32_t)__cvta_generic_to_shared(dst);
    asm volatile("cp.async.cg.shared.global [%0], [%1], 16;\n" :: "r"(d), "l"(src));
}
#define CPA_COMMIT() asm volatile("cp.async.commit_group;\n")
#define CPA_WAIT1()  asm volatile("cp.async.wait_group 1;\n")
#define CPA_WAIT0()  asm volatile("cp.async.wait_group 0;\n")

__device__ __forceinline__ uint32_t smem_u32(const void* p) {
    return (uint32_t)__cvta_generic_to_shared(p);
}

// ---- TMA / mbarrier ----
#define MBAR_INIT(a, n) \
    asm volatile("mbarrier.init.shared.b64 [%0], %1;" :: "r"(a), "r"(n) : "memory")
#define MBAR_EXPECT_TX(a, bytes) \
    asm volatile("mbarrier.arrive.expect_tx.shared.b64 _, [%0], %1;" :: "r"(a), "r"(bytes) : "memory")
#define MBAR_WAIT(a, par) do { \
    asm volatile("{\n\t.reg .pred P1;\n\tWL%=:\n\t" \
        "mbarrier.try_wait.parity.acquire.cta.shared::cta.b64 P1, [%0], %1, 0x989680;\n\t" \
        "@P1 bra.uni WD%=;\n\tbra.uni WL%=;\n\tWD%=:\n\t}" \
        :: "r"(a), "r"(par) : "memory"); \
} while (0)
#define TMA2D(dst, mapp, cx, cy, mb) \
    asm volatile("cp.async.bulk.tensor.2d.shared::cta.global.tile.mbarrier::complete_tx::bytes " \
        "[%0], [%1, {%2, %3}], [%4];" \
        :: "r"(dst), "l"(mapp), "r"(cx), "r"(cy), "r"(mb) : "memory")

// ================= TMA + mma.sync gate kernel (BM=64, 2 blocks/SM) =================
// buffer layout per chunk (48KB): Ah(8K) Al(8K) Bh(16K) Bl(16K); 2 buffers.
__global__ void __launch_bounds__(256) gate_tma(
    const __grid_constant__ CUtensorMap mAh,   // box {64,64}
    const __grid_constant__ CUtensorMap mAl,
    const __grid_constant__ CUtensorMap mBh,   // box {64,128}
    const __grid_constant__ CUtensorMap mBl,
    const float* __restrict__ baseg, float* __restrict__ cst,
    __nv_bfloat16* __restrict__ Xh, __nv_bfloat16* __restrict__ Xl,
    __nv_bfloat16* __restrict__ Chp, __nv_bfloat16* __restrict__ Clp)
{
    extern __shared__ char sm[];
    const uint32_t sb = smem_u32(sm);
    const int tid = threadIdx.x, warp = tid >> 5, lane = tid & 31;
    const int bm = blockIdx.y * 64, bn = blockIdx.x * 128;
    const uint32_t F0 = sb + 8, F1 = sb + 16;
    const int wm = (warp >> 2) * 32, wn = (warp & 3) * 32;   // 2x4 warps, 32x32 tiles
    const int gq = lane >> 2, tg = lane & 3;
    const int ch = lane >> 4, r7 = lane & 7;
    const int lrow = (lane & 15) * 128;
    constexpr int BUF = 49152;
    constexpr int AL_O = 8192, BH_O = 16384, BL_O = 32768;

    if (tid == 0) { MBAR_INIT(F0, 1); MBAR_INIT(F1, 1); }
    __syncthreads();

    float acc[32];
#pragma unroll
    for (int i = 0; i < 32; i++) acc[i] = 0.f;

    if (tid == 0) {
        MBAR_EXPECT_TX(F0, BUF);
        uint32_t d = sb + 1024;
        TMA2D(d,        &mAh, 0, bm, F0);
        TMA2D(d + AL_O, &mAl, 0, bm, F0);
        TMA2D(d + BH_O, &mBh, 0, bn, F0);
        TMA2D(d + BL_O, &mBl, 0, bn, F0);
        MBAR_EXPECT_TX(F1, BUF);
        d = sb + 1024 + BUF;
        TMA2D(d,        &mAh, 64, bm, F1);
        TMA2D(d + AL_O, &mAl, 64, bm, F1);
        TMA2D(d + BH_O, &mBh, 64, bn, F1);
        TMA2D(d + BL_O, &mBl, 64, bn, F1);
    }

    int pf0 = 0, pf1 = 0;
    for (int c = 0; c <= 12; c++) {
        if ((c & 1) == 0) { MBAR_WAIT(F0, pf0); pf0 ^= 1; }
        else              { MBAR_WAIT(F1, pf1); pf1 ^= 1; }
        const uint32_t bo = sb + 1024 + (c & 1) * BUF;
        const uint32_t aH = bo, aL = bo + AL_O, bH = bo + BH_O, bL = bo + BL_O;
#pragma unroll
        for (int g = 0; g < 4; g++) {
            const int xo = (((2 * g + ch) ^ r7) << 4) + lrow;
            uint32_t bhf[4][2], blf[4][2];
#pragma unroll
            for (int np = 0; np < 2; np++) {
                uint32_t r0, r1, r2, r3;
                ldsm4(r0, r1, r2, r3, bH + (wn + np * 16) * 128 + xo);
                bhf[2*np][0] = r0; bhf[2*np+1][0] = r1; bhf[2*np][1] = r2; bhf[2*np+1][1] = r3;
                ldsm4(r0, r1, r2, r3, bL + (wn + np * 16) * 128 + xo);
                blf[2*np][0] = r0; blf[2*np+1][0] = r1; blf[2*np][1] = r2; blf[2*np+1][1] = r3;
            }
#pragma unroll
            for (int mt = 0; mt < 2; mt++) {
                uint32_t ah[4], al[4];
                ldsm4(ah[0], ah[1], ah[2], ah[3], aH + (wm + mt * 16) * 128 + xo);
                ldsm4(al[0], al[1], al[2], al[3], aL + (wm + mt * 16) * 128 + xo);
#pragma unroll
                for (int nt = 0; nt < 4; nt++) {
                    float* a = acc + (mt * 4 + nt) * 4;
                    mma16816(a, ah, bhf[nt]);
                    mma16816(a, ah, blf[nt]);
                    mma16816(a, al, bhf[nt]);
                }
            }
        }
        __syncthreads();
        if (tid == 0 && c + 2 <= 12) {
            const uint32_t mb = (c & 1) ? F1 : F0;
            MBAR_EXPECT_TX(mb, BUF);
            const uint32_t d = sb + 1024 + (c & 1) * BUF;
            const int kc = (c + 2) * 64;
            TMA2D(d,        &mAh, kc, bm, mb);
            TMA2D(d + AL_O, &mAl, kc, bm, mb);
            TMA2D(d + BH_O, &mBh, kc, bn, mb);
            TMA2D(d + BL_O, &mBl, kc, bn, mb);
        }
    }

    // ---- epilogue: stage raw acc (64x128 fp32), then row-coalesced LSTM ----
    float* tile = (float*)(sm + 1024);
#pragma unroll
    for (int mt = 0; mt < 2; mt++)
#pragma unroll
        for (int nt = 0; nt < 4; nt++) {
            int r0 = wm + mt * 16 + gq, c0 = wn + nt * 8 + 2 * tg;
            float* a = acc + (mt * 4 + nt) * 4;
            tile[r0 * 128 + c0]           = a[0];
            tile[r0 * 128 + c0 + 1]       = a[1];
            tile[(r0 + 8) * 128 + c0]     = a[2];
            tile[(r0 + 8) * 128 + c0 + 1] = a[3];
        }
    __syncthreads();

    for (int idx = tid; idx < 64 * 32; idx += 256) {
        int row = idx >> 5, w = idx & 31;
        int b = bm + row, jg = blockIdx.x * 32 + w;
        const float* bg = baseg + (size_t)b * Gd + bn;
        float ig = tile[row * 128 + w]      + bg[w];
        float fg = tile[row * 128 + 32 + w] + bg[32 + w];
        float gg = tile[row * 128 + 64 + w] + bg[64 + w];
        float og = tile[row * 128 + 96 + w] + bg[96 + w];
        float si = fsig(ig), sf = fsig(fg), so = fsig(og);
        float cn = sf * cst[b * Hd + jg] + si * ftanh(gg);
        float hn = so * ftanh(cn);
        cst[b * Hd + jg] = cn;
        __nv_bfloat16 hh, hl, cc, cl;
        bsplit(hn, hh, hl); bsplit(cn, cc, cl);
        Xh[(size_t)b * XK + 320 + jg] = hh;
        Xl[(size_t)b * XK + 320 + jg] = hl;
        Chp[(size_t)b * CK + jg] = cc;
        Clp[(size_t)b * CK + jg] = cl;
    }
}

// ================= mma.sync GEMM (base GEMMs; 80B-row layout) =================
struct GArgs {
    const __nv_bfloat16 *Ah, *Al; int lda;
    const __nv_bfloat16 *Bh, *Bl; int ldb;
    const float* Ci; int ldci;
    float* C; int ldc;
    int K;
};

template<int MT,int NTL,int AHS,int BHS>
__device__ __forceinline__ void stage_mma2(const char* Ab, const char* Bb, float* acc,
                                           int wm, int wn, int laneoff)
{
    uint32_t aH = smem_u32(Ab) + laneoff;
    uint32_t bH = smem_u32(Bb) + laneoff;
#pragma unroll
    for (int kk = 0; kk < 2; kk++) {
        const int kb = kk * 32;
        uint32_t bhf[NTL][2], blf[NTL][2];
#pragma unroll
        for (int np = 0; np < NTL / 2; np++) {
            uint32_t r0, r1, r2, r3;
            ldsm4(r0, r1, r2, r3, bH + (wn + np * 16) * 80 + kb);
            bhf[2*np][0] = r0; bhf[2*np+1][0] = r1; bhf[2*np][1] = r2; bhf[2*np+1][1] = r3;
            ldsm4(r0, r1, r2, r3, bH + BHS + (wn + np * 16) * 80 + kb);
            blf[2*np][0] = r0; blf[2*np+1][0] = r1; blf[2*np][1] = r2; blf[2*np+1][1] = r3;
        }
#pragma unroll
        for (int mt = 0; mt < MT; mt++) {
            uint32_t ah[4], al[4];
            ldsm4(ah[0], ah[1], ah[2], ah[3], aH + (wm + mt * 16) * 80 + kb);
            ldsm4(al[0], al[1], al[2], al[3], aH + AHS + (wm + mt * 16) * 80 + kb);
#pragma unroll
            for (int nt = 0; nt < NTL; nt++) {
                float* a = acc + (mt * NTL + nt) * 4;
                mma16816(a, ah, bhf[nt]);
                mma16816(a, ah, blf[nt]);
                mma16816(a, al, bhf[nt]);
            }
        }
    }
}

template<int BM,int BN,int NTH>
__device__ __forceinline__ void stage_load(char* base, int tid, int bm, int bn,
    const __nv_bfloat16* Ah, const __nv_bfloat16* Al, int lda,
    const __nv_bfloat16* Bh, const __nv_bfloat16* Bl, int ldb, int k0)
{
#pragma unroll
    for (int i = tid; i < BM * 4; i += NTH) {
        int row = i >> 2, c4 = (i & 3) * 16;
        size_t off = ((size_t)(bm + row) * lda + k0) * 2 + c4;
        cpa16(base + row * 80 + c4, (const char*)Ah + off);
        cpa16(base + BM * 80 + row * 80 + c4, (const char*)Al + off);
    }
#pragma unroll
    for (int i = tid; i < BN * 4; i += NTH) {
        int row = i >> 2, c4 = (i & 3) * 16;
        size_t off = ((size_t)(bn + row) * ldb + k0) * 2 + c4;
        cpa16(base + BM * 160 + row * 80 + c4, (const char*)Bh + off);
        cpa16(base + BM * 160 + BN * 80 + row * 80 + c4, (const char*)Bl + off);
    }
    CPA_COMMIT();
}

template<int BM,int BN,int WM,int WN,int NTH>
__global__ void __launch_bounds__(NTH) gemm(GArgs g)
{
    extern __shared__ char sm[];
    constexpr int MT = WM / 16, NTL = WN / 8, NWN = BN / WN;
    constexpr int stageB = (BM + BN) * 160;
    const int tid = threadIdx.x, warp = tid >> 5, lane = tid & 31;
    const int gq = lane >> 2, tg = lane & 3;
    const int laneoff = (lane & 15) * 80 + (lane >> 4) * 16;
    const int wm = (warp / NWN) * WM, wn = (warp % NWN) * WN;
    const int bm = blockIdx.y * BM, bn = blockIdx.x * BN;
    const int K = g.K;

    float acc[MT * NTL * 4];
#pragma unroll
    for (int i = 0; i < MT * NTL * 4; i++) acc[i] = 0.f;

    const int nk = K >> 5;
    stage_load<BM,BN,NTH>(sm, tid, bm, bn, g.Ah, g.Al, g.lda, g.Bh, g.Bl, g.ldb, 0);
    for (int kt = 0; kt < nk; kt++) {
        if (kt + 1 < nk) {
            stage_load<BM,BN,NTH>(sm + ((kt + 1) & 1) * stageB, tid, bm, bn,
                                  g.Ah, g.Al, g.lda, g.Bh, g.Bl, g.ldb, (kt + 1) << 5);
            CPA_WAIT1();
        } else CPA_WAIT0();
        __syncthreads();
        const char* cur = sm + (kt & 1) * stageB;
        stage_mma2<MT,NTL,BM*80,BN*80>(cur, cur + BM * 160, acc, wm, wn, laneoff);
        __syncthreads();
    }

#pragma unroll
    for (int mt = 0; mt < MT; mt++)
#pragma unroll
        for (int nt = 0; nt < NTL; nt++) {
            float* a = acc + (mt * NTL + nt) * 4;
#pragma unroll
            for (int half = 0; half < 2; half++) {
                int r = bm + wm + mt * 16 + gq + half * 8;
                int c = bn + wn + nt * 8 + 2 * tg;
                float v0 = a[half * 2] + g.Ci[c], v1 = a[half * 2 + 1] + g.Ci[c + 1];
                *(float2*)&g.C[(size_t)r * g.ldc + c] = make_float2(v0, v1);
            }
        }
}

// ================= fused tail kernel (unchanged from R13) =================
struct TailArgs {
    const __nv_bfloat16 *XwH, *XwL;
    __nv_bfloat16 *XwHm, *XwLm;
    const __nv_bfloat16 *XrH, *XrL;
    const __nv_bfloat16 *Ch, *Cl;
    const float* basehz;
    const float *b1, *b2, *b3;
    const float *W5, *b5, *W6, *b6, *W8, *b8, *W9, *b9;
    const float *eps_inf, *eps_pri;
    float *fake, *out_mean, *out_lv, *out_z;
    int t;
};

template<int BN,int NTH>
__device__ __forceinline__ void tail_loadB(char* st, int tid,
    const __nv_bfloat16* Bh, const __nv_bfloat16* Bl, int ldb, int kg)
{
#pragma unroll
    for (int i = tid; i < BN * 4; i += NTH) {
        int row = i >> 2, c4 = (i & 3) * 16;
        size_t off = ((size_t)row * ldb + kg) * 2 + c4;
        cpa16(st + row * 80 + c4, (const char*)Bh + off);
        cpa16(st + BN * 80 + row * 80 + c4, (const char*)Bl + off);
    }
}

__device__ __forceinline__ void tail_loadA(char* st, int tid, int r0,
    const __nv_bfloat16* Ah, const __nv_bfloat16* Al, int lda, int kg)
{
    if (tid >= 128) return;
    int arow = tid >> 2, ac4 = (tid & 3) * 16;
    size_t off = ((size_t)(r0 + arow) * lda + kg) * 2 + ac4;
    cpa16(st + arow * 80 + ac4, (const char*)Ah + off);
    cpa16(st + 2560 + arow * 80 + ac4, (const char*)Al + off);
}

template<int NTL>
__device__ __forceinline__ void epi_chunk(const float* acc, const float* bias,
                                          char* dst, int wn, int gq, int tg)
{
#pragma unroll
    for (int mt = 0; mt < 2; mt++)
#pragma unroll
        for (int nt = 0; nt < NTL; nt++)
#pragma unroll
            for (int half = 0; half < 2; half++) {
                int row = mt * 16 + gq + half * 8;
                int col = wn + nt * 8 + 2 * tg;
                const float* a = acc + (mt * NTL + nt) * 4 + half * 2;
                float v0 = fmaxf(a[0] + bias[col], 0.f);
                float v1 = fmaxf(a[1] + bias[col + 1], 0.f);
                __nv_bfloat16 h0, l0, h1, l1;
                bsplit(v0, h0, l0); bsplit(v1, h1, l1);
                char* cb = dst + (col >> 5) * 5120;
                int kp = (col & 31) >> 1;
                ((uint32_t*)cb)[row * 20 + kp] = bpack(h0, h1);
                ((uint32_t*)(cb + 2560))[row * 20 + kp] = bpack(l0, l1);
            }
}

__global__ void __launch_bounds__(256) tail_kernel(TailArgs g)
{
    extern __shared__ char sm[];
    char* stages = sm;
    char* tA = sm + 138240;
    char* tB = sm + 179200;
    float* hzc = (float*)tB;

    const int tid = threadIdx.x, lane = tid & 31, warp = tid >> 5;
    const int gq = lane >> 2, tg = lane & 3;
    const int laneoff = (lane & 15) * 80 + (lane >> 4) * 16;
    const int r0 = blockIdx.x * 32;
    constexpr int DST = 46080;
    constexpr int HST = 25600;

    // dec1
    {
        float acc[32];
#pragma unroll
        for (int i = 0; i < 32; i++) acc[i] = 0.f;
        tail_loadA(stages, tid, r0, g.XwH + 320, g.XwL + 320, XK, 0);
        tail_loadB<256,256>(stages + 5120, tid, g_W1T_h, g_W1T_l, Hd, 0);
        CPA_COMMIT();
        tail_loadA(stages + DST, tid, r0, g.XwH + 320, g.XwL + 320, XK, 32);
        tail_loadB<256,256>(stages + DST + 5120, tid, g_W1T_h, g_W1T_l, Hd, 32);
        CPA_COMMIT();
        int cb = 0;
        for (int kt = 0; kt < 16; kt++) {
            if (kt + 1 < 16) CPA_WAIT1(); else CPA_WAIT0();
            __syncthreads();
            if (kt + 2 < 16) {
                int nb = cb + 2; if (nb >= 3) nb -= 3;
                tail_loadA(stages + nb * DST, tid, r0, g.XwH + 320, g.XwL + 320, XK, (kt + 2) * 32);
                tail_loadB<256,256>(stages + nb * DST + 5120, tid, g_W1T_h, g_W1T_l, Hd, (kt + 2) * 32);
                CPA_COMMIT();
            }
            char* cur = stages + cb * DST;
            stage_mma2<2,4,2560,20480>(cur, cur + 5120, acc, 0, warp * 32, laneoff);
            if (++cb == 3) cb = 0;
        }
        __syncthreads();
        epi_chunk<4>(acc, g.b1, tA, warp * 32, gq, tg);
        __syncthreads();
    }
    // dec2
    {
        float acc[32];
#pragma unroll
        for (int i = 0; i < 32; i++) acc[i] = 0.f;
        tail_loadB<256,256>(stages + 5120, tid, g_W2T_h, g_W2T_l, Fd, 0);
        CPA_COMMIT();
        tail_loadB<256,256>(stages + DST + 5120, tid, g_W2T_h, g_W2T_l, Fd, 32);
        CPA_COMMIT();
        int cb = 0;
        for (int kt = 0; kt < 8; kt++) {
            if (kt + 1 < 8) CPA_WAIT1(); else CPA_WAIT0();
            __syncthreads();
            if (kt + 2 < 8) {
                int nb = cb + 2; if (nb >= 3) nb -= 3;
                tail_loadB<256,256>(stages + nb * DST + 5120, tid, g_W2T_h, g_W2T_l, Fd, (kt + 2) * 32);
                CPA_COMMIT();
            }
            stage_mma2<2,4,2560,20480>(tA + kt * 5120, stages + cb * DST + 5120, acc, 0, warp * 32, laneoff);
            if (++cb == 3) cb = 0;
        }
        __syncthreads();
        epi_chunk<4>(acc, g.b2, tB, warp * 32, gq, tg);
        __syncthreads();
    }
    // dec3
    {
        float acc[32];
#pragma unroll
        for (int i = 0; i < 32; i++) acc[i] = 0.f;
        tail_loadB<256,256>(stages + 5120, tid, g_W3T_h, g_W3T_l, Fd, 0);
        CPA_COMMIT();
        tail_loadB<256,256>(stages + DST + 5120, tid, g_W3T_h, g_W3T_l, Fd, 32);
        CPA_COMMIT();
        int cb = 0;
        for (int kt = 0; kt < 8; kt++) {
            if (kt + 1 < 8) CPA_WAIT1(); else CPA_WAIT0();
            __syncthreads();
            if (kt + 2 < 8) {
                int nb = cb + 2; if (nb >= 3) nb -= 3;
                tail_loadB<256,256>(stages + nb * DST + 5120, tid, g_W3T_h, g_W3T_l, Fd, (kt + 2) * 32);
                CPA_COMMIT();
            }
            stage_mma2<2,4,2560,20480>(tB + kt * 5120, stages + cb * DST + 5120, acc, 0, warp * 32, laneoff);
            if (++cb == 3) cb = 0;
        }
        __syncthreads();
#pragma unroll
        for (int mt = 0; mt < 2; mt++)
#pragma unroll
            for (int nt = 0; nt < 4; nt++)
#pragma unroll
                for (int half = 0; half < 2; half++) {
                    int row = mt * 16 + gq + half * 8;
                    int col = warp * 32 + nt * 8 + 2 * tg;
                    int b = r0 + row;
                    const float* a = acc + (mt * 4 + nt) * 4 + half * 2;
                    float v0 = fmaxf(a[0] + g.b3[col], 0.f);
                    float v1 = fmaxf(a[1] + g.b3[col + 1], 0.f);
                    *(float2*)&g.fake[(size_t)b * (Td * Fd) + g.t * Fd + col] = make_float2(v0, v1);
                    __nv_bfloat16 h0, l0, h1, l1;
                    bsplit(v0, h0, l0); bsplit(v1, h1, l1);
                    *(__nv_bfloat162*)&g.XwHm[(size_t)b * XK + 64 + col] = bmk2(h0, h1);
                    *(__nv_bfloat162*)&g.XwLm[(size_t)b * XK + 64 + col] = bmk2(l0, l1);
                    char* cb2 = tA + (col >> 5) * 5120;
                    int kp = (col & 31) >> 1;
                    ((uint32_t*)cb2)[row * 20 + kp] = bpack(h0, h1);
                    ((uint32_t*)(cb2 + 2560))[row * 20 + kp] = bpack(l0, l1);
                }
        __syncthreads();
    }
    // head
    {
        float acc[16];
#pragma unroll
        for (int i = 0; i < 16; i++) acc[i] = 0.f;
        tail_loadA(stages, tid, r0, g.Ch, g.Cl, CK, 0);
        tail_loadB<128,256>(stages + 5120, tid, g_WheadT_h, g_WheadT_l, IK, 0);
        CPA_COMMIT();
        tail_loadA(stages + HST, tid, r0, g.Ch, g.Cl, CK, 32);
        tail_loadB<128,256>(stages + HST + 5120, tid, g_WheadT_h, g_WheadT_l, IK, 32);
        CPA_COMMIT();
        int cb = 0;
        for (int kt = 0; kt < 32; kt++) {
            if (kt + 1 < 32) CPA_WAIT1(); else CPA_WAIT0();
            __syncthreads();
            if (kt + 2 < 32) {
                int nb = cb + 2; if (nb >= 3) nb -= 3;
                int kn = kt + 2;
                char* nxt = stages + nb * HST;
                if (kn < 16)       tail_loadA(nxt, tid, r0, g.Ch, g.Cl, CK, kn * 32);
                else if (kn >= 24) tail_loadA(nxt, tid, r0, g.XrH, g.XrL, XK, 64 + (kn - 24) * 32);
                tail_loadB<128,256>(nxt + 5120, tid, g_WheadT_h, g_WheadT_l, IK, kn * 32);
                CPA_COMMIT();
            }
            char* cur = stages + cb * HST;
            const char* Ab = (kt >= 16 && kt < 24) ? (tA + (kt - 16) * 5120) : cur;
            stage_mma2<2,2,2560,10240>(Ab, cur + 5120, acc, 0, warp * 16, laneoff);
            if (++cb == 3) cb = 0;
        }
        __syncthreads();
#pragma unroll
        for (int mt = 0; mt < 2; mt++)
#pragma unroll
            for (int nt = 0; nt < 2; nt++)
#pragma unroll
                for (int half = 0; half < 2; half++) {
                    int row = mt * 16 + gq + half * 8;
                    int col = warp * 16 + nt * 8 + 2 * tg;
                    const float* a = acc + (mt * 2 + nt) * 4 + half * 2;
                    const float* bz = g.basehz + (size_t)(r0 + row) * 128 + col;
                    hzc[row * 130 + col]     = fmaxf(a[0] + bz[0], 0.f);
                    hzc[row * 130 + col + 1] = fmaxf(a[1] + bz[1], 0.f);
                }
        __syncthreads();
    }
    // finish
    {
        const int z = tid & 63, rb = tid >> 6;
        float m[8], l[8], mp[8], lp[8];
#pragma unroll
        for (int i = 0; i < 8; i++) { m[i] = g.b5[z]; l[i] = g.b6[z]; mp[i] = g.b8[z]; lp[i] = g.b9[z]; }
#pragma unroll 4
        for (int k = 0; k < 64; k++) {
            float w5 = g.W5[k * Zd + z], w6 = g.W6[k * Zd + z];
            float w8 = g.W8[k * Zd + z], w9 = g.W9[k * Zd + z];
#pragma unroll
            for (int i = 0; i < 8; i++) {
                int row = rb + 4 * i;
                float av = hzc[row * 130 + k];
                float ap = hzc[row * 130 + 64 + k];
                m[i]  += av * w5;  l[i]  += av * w6;
                mp[i] += ap * w8;  lp[i] += ap * w9;
            }
        }
#pragma unroll
        for (int i = 0; i < 8; i++) {
            int row = rb + 4 * i, b = r0 + row;
            float mm = fmaxf(m[i], 0.f),  ll = fmaxf(l[i], 0.f);
            float mmp = fmaxf(mp[i], 0.f), llp = fmaxf(lp[i], 0.f);
            size_t gi = (size_t)b * Zd + z;
            float zi = mm  + g.eps_inf[(size_t)g.t * Bn * Zd + gi] * __expf(0.5f * ll);
            float zp = mmp + g.eps_pri[(size_t)g.t * Bn * Zd + gi] * __expf(0.5f * llp);
            g.out_mean[(size_t)b * Td * Zd + (size_t)g.t * Zd + z] = mm;
            g.out_lv  [(size_t)b * Td * Zd + (size_t)g.t * Zd + z] = ll;
            g.out_z[(size_t)(2 * g.t)     * Bn * Zd + gi] = zi;
            g.out_z[(size_t)(2 * g.t + 1) * Bn * Zd + gi] = zp;
            __nv_bfloat16 zh, zl; bsplit(zi, zh, zl);
            g.XwHm[(size_t)b * XK + z] = zh;
            g.XwLm[(size_t)b * XK + z] = zl;
        }
    }
}

// ---------------- prep + dummy ----------------
__device__ __forceinline__ int perm_n(int np) {
    int chunk = np >> 7, r = np & 127, gate = r >> 5, w = r & 31;
    return gate * 512 + chunk * 32 + w;
}

__global__ void noop_k() {}   // slot filler so ncu (-s 5) profiles tail_kernel

__global__ void prep_all(const float* __restrict__ h_i,
                         const float* __restrict__ Wx, const float* __restrict__ Wh,
                         const float* __restrict__ bl,
                         const float* __restrict__ W1, const float* __restrict__ W2,
                         const float* __restrict__ W3,
                         const float* __restrict__ W4, const float* __restrict__ W7,
                         const float* __restrict__ b4, const float* __restrict__ b7)
{
    size_t i = (size_t)blockIdx.x * blockDim.x + threadIdx.x;
    __nv_bfloat16 h, l;

    const size_t nX = (size_t)Bn * XK;
    if (i < nX) {
        __nv_bfloat16 z = __float2bfloat16(0.f);
        g_Xh0[i] = z; g_Xl0[i] = z; g_Xh1[i] = z; g_Xl1[i] = z;
        return;
    }
    i -= nX;
    const size_t nC = (size_t)Bn * Hd;
    if (i < nC) { g_c[i] = 0.f; return; }
    i -= nC;
    if (i < (size_t)Bn * Hd) {
        bsplit(h_i[i], h, l);
        g_hih[i] = h; g_hil[i] = l;
        return;
    }
    i -= (size_t)Bn * Hd;
    if (i < (size_t)Gd * XK) {
        int k = (int)(i % XK), np = (int)(i / XK);
        int n = perm_n(np);
        float v;
        if (k < 64)       v = Wx[(size_t)k * Gd + n];
        else if (k < 320) v = Wx[(size_t)(512 + k) * Gd + n];
        else              v = Wh[(size_t)(k - 320) * Gd + n];
        bsplit(v, h, l);
        g_WcatT_h[i] = h; g_WcatT_l[i] = l;
        return;
    }
    i -= (size_t)Gd * XK;
    if (i < (size_t)Gd * Hd) {
        int k = (int)(i % Hd), np = (int)(i / Hd);
        int n = perm_n(np);
        bsplit(Wx[(size_t)(64 + k) * Gd + n], h, l);
        g_WxhT_h[i] = h; g_WxhT_l[i] = l;
        if (k == 0) g_blstmp[np] = bl[n];
        return;
    }
    i -= (size_t)Gd * Hd;
    if (i < (size_t)Fd * Hd) {
        int k = (int)(i % Hd), n = (int)(i / Hd);
        bsplit(W1[(size_t)k * Fd + n], h, l);
        g_W1T_h[i] = h; g_W1T_l[i] = l;
        return;
    }
    i -= (size_t)Fd * Hd;
    if (i < (size_t)Fd * Fd) {
        int k = (int)(i % Fd), n = (int)(i / Fd);
        bsplit(W2[(size_t)k * Fd + n], h, l);
        g_W2T_h[i] = h; g_W2T_l[i] = l;
        return;
    }
    i -= (size_t)Fd * Fd;
    if (i < (size_t)Fd * Fd) {
        int k = (int)(i % Fd), n = (int)(i / Fd);
        bsplit(W3[(size_t)k * Fd + n], h, l);
        g_W3T_h[i] = h; g_W3T_l[i] = l;
        return;
    }
    i -= (size_t)Fd * Fd;
    if (i < (size_t)128 * IK) {
        int k = (int)(i % IK), n = (int)(i / IK);
        float v;
        if (n < 64) v = W4[(size_t)(512 + k) * Zd + n];
        else {
            int n2 = n - 64;
            if (k < 512)      v = W7[(size_t)(512 + k) * Zd + n2];
            else if (k < 768) v = 0.f;
            else              v = W7[(size_t)(1024 + k - 768) * Zd + n2];
        }
        bsplit(v, h, l);
        g_WheadT_h[i] = h; g_WheadT_l[i] = l;
        return;
    }
    i -= (size_t)128 * IK;
    if (i < (size_t)128 * Hd) {
        int k = (int)(i % Hd), n = (int)(i / Hd);
        float v = (n < 64) ? W4[(size_t)k * Zd + n] : W7[(size_t)k * Zd + (n - 64)];
        bsplit(v, h, l);
        g_WbaseT_h[i] = h; g_WbaseT_l[i] = l;
        if (k == 0) g_bhz[n] = (n < 64) ? b4[n] : b7[n - 64];
    }
}

// ---------------- host ----------------
template<typename T> static T* sym(const void* s) { void* p = nullptr; cudaGetSymbolAddress(&p, s); return (T*)p; }

typedef CUresult (*PFN_encode)(CUtensorMap*, CUtensorMapDataType, cuuint32_t, void*,
                               const cuuint64_t*, const cuuint64_t*, const cuuint32_t*,
                               const cuuint32_t*, CUtensorMapInterleave, CUtensorMapSwizzle,
                               CUtensorMapL2promotion, CUtensorMapFloatOOBfill);

static void make_map(PFN_encode enc, CUtensorMap* m, void* base,
                     unsigned long long rows, unsigned boxRows) {
    cuuint64_t dims[2]    = {(cuuint64_t)XK, (cuuint64_t)rows};
    cuuint64_t strides[1] = {(cuuint64_t)XK * 2};
    cuuint32_t box[2]     = {64, boxRows};
    cuuint32_t es[2]      = {1, 1};
    enc(m, CU_TENSOR_MAP_DATA_TYPE_BFLOAT16, 2, base, dims, strides, box, es,
        CU_TENSOR_MAP_INTERLEAVE_NONE, CU_TENSOR_MAP_SWIZZLE_128B,
        CU_TENSOR_MAP_L2_PROMOTION_L2_128B, CU_TENSOR_MAP_FLOAT_OOB_FILL_NONE);
}

extern "C" void kernel_launch(void* const* d_in, const int* in_sizes, int n_in,
                              void* d_out, int out_size) {
    const float* h_i     = (const float*)d_in[0];
    const float* eps_inf = (const float*)d_in[1];
    const float* eps_pri = (const float*)d_in[2];
    const float* Wx      = (const float*)d_in[3];
    const float* Wh      = (const float*)d_in[4];
    const float* b_lstm  = (const float*)d_in[5];
    const float* W1 = (const float*)d_in[6],  *b1 = (const float*)d_in[7];
    const float* W2 = (const float*)d_in[8],  *b2 = (const float*)d_in[9];
    const float* W3 = (const float*)d_in[10], *b3 = (const float*)d_in[11];
    const float* W4 = (const float*)d_in[12], *b4 = (const float*)d_in[13];
    const float* W5 = (const float*)d_in[14], *b5 = (const float*)d_in[15];
    const float* W6 = (const float*)d_in[16], *b6 = (const float*)d_in[17];
    const float* W7 = (const float*)d_in[18], *b7 = (const float*)d_in[19];
    const float* W8 = (const float*)d_in[20], *b8 = (const float*)d_in[21];
    const float* W9 = (const float*)d_in[22], *b9 = (const float*)d_in[23];

    float* out      = (float*)d_out;
    float* out_fake = out;
    float* out_mean = out_fake + (size_t)Bn * Td * Fd;
    float* out_lv   = out_mean + (size_t)Bn * Td * Zd;
    float* out_z    = out_lv   + (size_t)Bn * Td * Zd;

    __nv_bfloat16* Xh0 = sym<__nv_bfloat16>(g_Xh0); __nv_bfloat16* Xl0 = sym<__nv_bfloat16>(g_Xl0);
    __nv_bfloat16* Xh1 = sym<__nv_bfloat16>(g_Xh1); __nv_bfloat16* Xl1 = sym<__nv_bfloat16>(g_Xl1);
    __nv_bfloat16* Ch  = sym<__nv_bfloat16>(g_Ch);  __nv_bfloat16* Cl  = sym<__nv_bfloat16>(g_Cl);

    float* pBaseg  = sym<float>(g_baseg);
    float* pBasehz = sym<float>(g_basehz);
    float* pBlstmp = sym<float>(g_blstmp);
    float* pBhz    = sym<float>(g_bhz);

    PFN_encode enc = nullptr;
    {
        void* fn = nullptr;
        cudaDriverEntryPointQueryResult st;
#if CUDART_VERSION >= 12050
        cudaGetDriverEntryPointByVersion("cuTensorMapEncodeTiled", &fn, 12000,
                                         cudaEnableDefault, &st);
#else
        cudaGetDriverEntryPoint("cuTensorMapEncodeTiled", &fn, cudaEnableDefault, &st);
#endif
        enc = (PFN_encode)fn;
    }
    static CUtensorMap mX[4], mW[2];
    make_map(enc, &mX[0], Xh0, Bn, 64); make_map(enc, &mX[1], Xl0, Bn, 64);
    make_map(enc, &mX[2], Xh1, Bn, 64); make_map(enc, &mX[3], Xl1, Bn, 64);
    make_map(enc, &mW[0], sym<__nv_bfloat16>(g_WcatT_h), Gd, 128);
    make_map(enc, &mW[1], sym<__nv_bfloat16>(g_WcatT_l), Gd, 128);

    constexpr int SMBASE  = 2 * (256 + 128) * 160;
    constexpr int SMSMALL = 2 * (64 + 64) * 160;
    constexpr int SMTAIL  = 220160;
    constexpr int SMGATE  = 1024 + 2 * 49152;   // 99328 -> 2 blocks/SM
    cudaFuncSetAttribute(gemm<256,128,64,64,256>, cudaFuncAttributeMaxDynamicSharedMemorySize, SMBASE);
    cudaFuncSetAttribute(gemm<64,64,32,32,128>,   cudaFuncAttributeMaxDynamicSharedMemorySize, SMSMALL);
    cudaFuncSetAttribute(tail_kernel,             cudaFuncAttributeMaxDynamicSharedMemorySize, SMTAIL);
    cudaFuncSetAttribute(gate_tma,                cudaFuncAttributeMaxDynamicSharedMemorySize, SMGATE);

    // ---- init ----
    {
        size_t tot = (size_t)Bn * XK + 2 * (size_t)Bn * Hd
                   + (size_t)Gd * XK + (size_t)Gd * Hd
                   + (size_t)Fd * Hd + 2 * (size_t)Fd * Fd
                   + (size_t)128 * IK + (size_t)128 * Hd;
        prep_all<<<(unsigned)((tot + 255) / 256), 256>>>(h_i, Wx, Wh, b_lstm,
                                                         W1, W2, W3, W4, W7, b4, b7);
    }

    // ---- hoisted base GEMMs ----
    {
        GArgs b{};
        b.Ah = sym<__nv_bfloat16>(g_hih); b.Al = sym<__nv_bfloat16>(g_hil); b.lda = Hd;
        b.Bh = sym<__nv_bfloat16>(g_WxhT_h); b.Bl = sym<__nv_bfloat16>(g_WxhT_l); b.ldb = Hd;
        b.Ci = pBlstmp; b.C = pBaseg; b.ldc = Gd; b.K = Hd;
        gemm<256,128,64,64,256><<<dim3(16, 16), 256, SMBASE>>>(b);

        b.Bh = sym<__nv_bfloat16>(g_WbaseT_h); b.Bl = sym<__nv_bfloat16>(g_WbaseT_l); b.ldb = Hd;
        b.Ci = pBhz; b.C = pBasehz; b.ldc = 128; b.K = Hd;
        gemm<64,64,32,32,128><<<dim3(2, 64), 128, SMSMALL>>>(b);
    }
    noop_k<<<1, 32>>>();   // slot filler: ncu -s 5 now lands on tail_kernel

    for (int t = 0; t < Td; t++) {
        __nv_bfloat16* XrH = (t & 1) ? Xh1 : Xh0;
        __nv_bfloat16* XrL = (t & 1) ? Xl1 : Xl0;
        __nv_bfloat16* XwH = (t & 1) ? Xh0 : Xh1;
        __nv_bfloat16* XwL = (t & 1) ? Xl0 : Xl1;
        const CUtensorMap& mAh = (t & 1) ? mX[2] : mX[0];
        const CUtensorMap& mAl = (t & 1) ? mX[3] : mX[1];

        gate_tma<<<dim3(16, 64), 256, SMGATE>>>(mAh, mAl, mW[0], mW[1],
                                                pBaseg, sym<float>(g_c),
                                                XwH, XwL, Ch, Cl);
        {
            TailArgs ta{};
            ta.XwH = XwH; ta.XwL = XwL; ta.XwHm = XwH; ta.XwLm = XwL;
            ta.XrH = XrH; ta.XrL = XrL;
            ta.Ch = Ch; ta.Cl = Cl;
            ta.basehz = pBasehz;
            ta.b1 = b1; ta.b2 = b2; ta.b3 = b3;
            ta.W5 = W5; ta.b5 = b5; ta.W6 = W6; ta.b6 = b6;
            ta.W8 = W8; ta.b8 = b8; ta.W9 = W9; ta.b9 = b9;
            ta.eps_inf = eps_inf; ta.eps_pri = eps_pri;
            ta.fake = out_fake; ta.out_mean = out_mean; ta.out_lv = out_lv; ta.out_z = out_z;
            ta.t = t;
            tail_kernel<<<Bn / 32, 256, SMTAIL>>>(ta);
        }
    }
}

// round 15
// speedup vs baseline: 1.5828x; 1.0303x over previous
#include <cuda_runtime.h>
#include <cuda.h>
#include <cuda_bf16.h>
#include <math.h>
#include <stdint.h>

#define Bn   4096
#define Hd   512
#define Fd   256
#define Zd   64
#define Td   16
#define Gd   2048
#define XK   832      // bf16 X row: [z(64) | y(256) | h(512)]
#define IK   1024     // head K:     [c(512) | y_j(256) | y_prev(256)]
#define CK   512      // c buffer row

// ---------------- persistent buffers ----------------
__device__ float g_baseg [(size_t)Bn * Gd];
__device__ float g_basehz[Bn * 128];
__device__ float g_c     [Bn * Hd];
__device__ float g_blstmp[Gd];
__device__ float g_bhz   [128];

__device__ __nv_bfloat16 g_Xh0[(size_t)Bn * XK], g_Xl0[(size_t)Bn * XK];
__device__ __nv_bfloat16 g_Xh1[(size_t)Bn * XK], g_Xl1[(size_t)Bn * XK];
__device__ __nv_bfloat16 g_Ch [(size_t)Bn * CK], g_Cl [(size_t)Bn * CK];
__device__ __nv_bfloat16 g_hih[(size_t)Bn * Hd], g_hil[(size_t)Bn * Hd];

__device__ __nv_bfloat16 g_WcatT_h[(size_t)Gd * XK], g_WcatT_l[(size_t)Gd * XK];
__device__ __nv_bfloat16 g_WxhT_h [(size_t)Gd * Hd], g_WxhT_l [(size_t)Gd * Hd];
__device__ __nv_bfloat16 g_W1T_h  [Fd * Hd], g_W1T_l  [Fd * Hd];
__device__ __nv_bfloat16 g_W2T_h  [Fd * Fd], g_W2T_l  [Fd * Fd];
__device__ __nv_bfloat16 g_W3T_h  [Fd * Fd], g_W3T_l  [Fd * Fd];
__device__ __nv_bfloat16 g_WheadT_h[128 * IK], g_WheadT_l[128 * IK];
__device__ __nv_bfloat16 g_WbaseT_h[128 * Hd], g_WbaseT_l[128 * Hd];

// ---------------- helpers ----------------
__device__ __forceinline__ void bsplit(float v, __nv_bfloat16& h, __nv_bfloat16& l) {
    h = __float2bfloat16_rn(v);
    l = __float2bfloat16_rn(v - __bfloat162float(h));
}
__device__ __forceinline__ uint32_t bpack(__nv_bfloat16 a, __nv_bfloat16 b) {
    __nv_bfloat162 t; t.x = a; t.y = b;
    return reinterpret_cast<uint32_t&>(t);
}
__device__ __forceinline__ __nv_bfloat162 bmk2(__nv_bfloat16 a, __nv_bfloat16 b) {
    __nv_bfloat162 t; t.x = a; t.y = b; return t;
}
__device__ __forceinline__ float fsig(float x) {
    return __fdividef(1.f, 1.f + __expf(-x));
}
__device__ __forceinline__ float ftanh(float x) {
    return 2.f * fsig(2.f * x) - 1.f;
}
__device__ __forceinline__ void mma16816(float* c, const uint32_t* a, const uint32_t* b) {
    asm volatile(
        "mma.sync.aligned.m16n8k16.row.col.f32.bf16.bf16.f32 "
        "{%0,%1,%2,%3}, {%4,%5,%6,%7}, {%8,%9}, {%0,%1,%2,%3};\n"
        : "+f"(c[0]), "+f"(c[1]), "+f"(c[2]), "+f"(c[3])
        : "r"(a[0]), "r"(a[1]), "r"(a[2]), "r"(a[3]), "r"(b[0]), "r"(b[1]));
}
__device__ __forceinline__ void ldsm4(uint32_t& r0, uint32_t& r1, uint32_t& r2, uint32_t& r3,
                                      uint32_t addr) {
    asm volatile("ldmatrix.sync.aligned.m8n8.x4.shared.b16 {%0,%1,%2,%3}, [%4];"
        : "=r"(r0), "=r"(r1), "=r"(r2), "=r"(r3) : "r"(addr));
}
__device__ __forceinline__ void cpa16(void* dst, const void* src) {
    uint32_t d = (uint32_t)__cvta_generic_to_shared(dst);
    asm volatile("cp.async.cg.shared.global [%0], [%1], 16;\n" :: "r"(d), "l"(src));
}
#define CPA_COMMIT() asm volatile("cp.async.commit_group;\n")
#define CPA_WAIT1()  asm volatile("cp.async.wait_group 1;\n")
#define CPA_WAIT0()  asm volatile("cp.async.wait_group 0;\n")

__device__ __forceinline__ uint32_t smem_u32(const void* p) {
    return (uint32_t)__cvta_generic_to_shared(p);
}

// ---- TMA / mbarrier ----
#define MBAR_INIT(a, n) \
    asm volatile("mbarrier.init.shared.b64 [%0], %1;" :: "r"(a), "r"(n) : "memory")
#define MBAR_EXPECT_TX(a, bytes) \
    asm volatile("mbarrier.arrive.expect_tx.shared.b64 _, [%0], %1;" :: "r"(a), "r"(bytes) : "memory")
#define MBAR_WAIT(a, par) do { \
    asm volatile("{\n\t.reg .pred P1;\n\tWL%=:\n\t" \
        "mbarrier.try_wait.parity.acquire.cta.shared::cta.b64 P1, [%0], %1, 0x989680;\n\t" \
        "@P1 bra.uni WD%=;\n\tbra.uni WL%=;\n\tWD%=:\n\t}" \
        :: "r"(a), "r"(par) : "memory"); \
} while (0)
#define TMA2D(dst, mapp, cx, cy, mb) \
    asm volatile("cp.async.bulk.tensor.2d.shared::cta.global.tile.mbarrier::complete_tx::bytes " \
        "[%0], [%1, {%2, %3}], [%4];" \
        :: "r"(dst), "l"(mapp), "r"(cx), "r"(cy), "r"(mb) : "memory")

// ================= TMA + mma.sync gate kernel (BM=64, 2 blocks/SM) =================
__global__ void __launch_bounds__(256) gate_tma(
    const __grid_constant__ CUtensorMap mAh,   // box {64,64}
    const __grid_constant__ CUtensorMap mAl,
    const __grid_constant__ CUtensorMap mBh,   // box {64,128}
    const __grid_constant__ CUtensorMap mBl,
    const float* __restrict__ baseg, float* __restrict__ cst,
    __nv_bfloat16* __restrict__ Xh, __nv_bfloat16* __restrict__ Xl,
    __nv_bfloat16* __restrict__ Chp, __nv_bfloat16* __restrict__ Clp)
{
    extern __shared__ char sm[];
    const uint32_t sb = smem_u32(sm);
    const int tid = threadIdx.x, warp = tid >> 5, lane = tid & 31;
    const int bm = blockIdx.y * 64, bn = blockIdx.x * 128;
    const uint32_t F0 = sb + 8, F1 = sb + 16;
    const int wm = (warp >> 2) * 32, wn = (warp & 3) * 32;
    const int gq = lane >> 2, tg = lane & 3;
    const int ch = lane >> 4, r7 = lane & 7;
    const int lrow = (lane & 15) * 128;
    constexpr int BUF = 49152;
    constexpr int AL_O = 8192, BH_O = 16384, BL_O = 32768;

    if (tid == 0) { MBAR_INIT(F0, 1); MBAR_INIT(F1, 1); }
    __syncthreads();

    float acc[32];
#pragma unroll
    for (int i = 0; i < 32; i++) acc[i] = 0.f;

    if (tid == 0) {
        MBAR_EXPECT_TX(F0, BUF);
        uint32_t d = sb + 1024;
        TMA2D(d,        &mAh, 0, bm, F0);
        TMA2D(d + AL_O, &mAl, 0, bm, F0);
        TMA2D(d + BH_O, &mBh, 0, bn, F0);
        TMA2D(d + BL_O, &mBl, 0, bn, F0);
        MBAR_EXPECT_TX(F1, BUF);
        d = sb + 1024 + BUF;
        TMA2D(d,        &mAh, 64, bm, F1);
        TMA2D(d + AL_O, &mAl, 64, bm, F1);
        TMA2D(d + BH_O, &mBh, 64, bn, F1);
        TMA2D(d + BL_O, &mBl, 64, bn, F1);
    }

    int pf0 = 0, pf1 = 0;
    for (int c = 0; c <= 12; c++) {
        if ((c & 1) == 0) { MBAR_WAIT(F0, pf0); pf0 ^= 1; }
        else              { MBAR_WAIT(F1, pf1); pf1 ^= 1; }
        const uint32_t bo = sb + 1024 + (c & 1) * BUF;
        const uint32_t aH = bo, aL = bo + AL_O, bH = bo + BH_O, bL = bo + BL_O;
#pragma unroll
        for (int g = 0; g < 4; g++) {
            const int xo = (((2 * g + ch) ^ r7) << 4) + lrow;
            uint32_t bhf[4][2], blf[4][2];
#pragma unroll
            for (int np = 0; np < 2; np++) {
                uint32_t r0, r1, r2, r3;
                ldsm4(r0, r1, r2, r3, bH + (wn + np * 16) * 128 + xo);
                bhf[2*np][0] = r0; bhf[2*np+1][0] = r1; bhf[2*np][1] = r2; bhf[2*np+1][1] = r3;
                ldsm4(r0, r1, r2, r3, bL + (wn + np * 16) * 128 + xo);
                blf[2*np][0] = r0; blf[2*np+1][0] = r1; blf[2*np][1] = r2; blf[2*np+1][1] = r3;
            }
#pragma unroll
            for (int mt = 0; mt < 2; mt++) {
                uint32_t ah[4], al[4];
                ldsm4(ah[0], ah[1], ah[2], ah[3], aH + (wm + mt * 16) * 128 + xo);
                ldsm4(al[0], al[1], al[2], al[3], aL + (wm + mt * 16) * 128 + xo);
#pragma unroll
                for (int nt = 0; nt < 4; nt++) {
                    float* a = acc + (mt * 4 + nt) * 4;
                    mma16816(a, ah, bhf[nt]);
                    mma16816(a, ah, blf[nt]);
                    mma16816(a, al, bhf[nt]);
                }
            }
        }
        __syncthreads();
        if (tid == 0 && c + 2 <= 12) {
            const uint32_t mb = (c & 1) ? F1 : F0;
            MBAR_EXPECT_TX(mb, BUF);
            const uint32_t d = sb + 1024 + (c & 1) * BUF;
            const int kc = (c + 2) * 64;
            TMA2D(d,        &mAh, kc, bm, mb);
            TMA2D(d + AL_O, &mAl, kc, bm, mb);
            TMA2D(d + BH_O, &mBh, kc, bn, mb);
            TMA2D(d + BL_O, &mBl, kc, bn, mb);
        }
    }

    float* tile = (float*)(sm + 1024);
#pragma unroll
    for (int mt = 0; mt < 2; mt++)
#pragma unroll
        for (int nt = 0; nt < 4; nt++) {
            int r0 = wm + mt * 16 + gq, c0 = wn + nt * 8 + 2 * tg;
            float* a = acc + (mt * 4 + nt) * 4;
            tile[r0 * 128 + c0]           = a[0];
            tile[r0 * 128 + c0 + 1]       = a[1];
            tile[(r0 + 8) * 128 + c0]     = a[2];
            tile[(r0 + 8) * 128 + c0 + 1] = a[3];
        }
    __syncthreads();

    for (int idx = tid; idx < 64 * 32; idx += 256) {
        int row = idx >> 5, w = idx & 31;
        int b = bm + row, jg = blockIdx.x * 32 + w;
        const float* bg = baseg + (size_t)b * Gd + bn;
        float ig = tile[row * 128 + w]      + bg[w];
        float fg = tile[row * 128 + 32 + w] + bg[32 + w];
        float gg = tile[row * 128 + 64 + w] + bg[64 + w];
        float og = tile[row * 128 + 96 + w] + bg[96 + w];
        float si = fsig(ig), sf = fsig(fg), so = fsig(og);
        float cn = sf * cst[b * Hd + jg] + si * ftanh(gg);
        float hn = so * ftanh(cn);
        cst[b * Hd + jg] = cn;
        __nv_bfloat16 hh, hl, cc, cl;
        bsplit(hn, hh, hl); bsplit(cn, cc, cl);
        Xh[(size_t)b * XK + 320 + jg] = hh;
        Xl[(size_t)b * XK + 320 + jg] = hl;
        Chp[(size_t)b * CK + jg] = cc;
        Clp[(size_t)b * CK + jg] = cl;
    }
}

// ================= mma.sync GEMM (base GEMMs; 80B-row layout) =================
struct GArgs {
    const __nv_bfloat16 *Ah, *Al; int lda;
    const __nv_bfloat16 *Bh, *Bl; int ldb;
    const float* Ci; int ldci;
    float* C; int ldc;
    int K;
};

template<int MT,int NTL,int AHS,int BHS>
__device__ __forceinline__ void stage_mma2(const char* Ab, const char* Bb, float* acc,
                                           int wm, int wn, int laneoff)
{
    uint32_t aH = smem_u32(Ab) + laneoff;
    uint32_t bH = smem_u32(Bb) + laneoff;
#pragma unroll
    for (int kk = 0; kk < 2; kk++) {
        const int kb = kk * 32;
        uint32_t bhf[NTL][2], blf[NTL][2];
#pragma unroll
        for (int np = 0; np < NTL / 2; np++) {
            uint32_t r0, r1, r2, r3;
            ldsm4(r0, r1, r2, r3, bH + (wn + np * 16) * 80 + kb);
            bhf[2*np][0] = r0; bhf[2*np+1][0] = r1; bhf[2*np][1] = r2; bhf[2*np+1][1] = r3;
            ldsm4(r0, r1, r2, r3, bH + BHS + (wn + np * 16) * 80 + kb);
            blf[2*np][0] = r0; blf[2*np+1][0] = r1; blf[2*np][1] = r2; blf[2*np+1][1] = r3;
        }
#pragma unroll
        for (int mt = 0; mt < MT; mt++) {
            uint32_t ah[4], al[4];
            ldsm4(ah[0], ah[1], ah[2], ah[3], aH + (wm + mt * 16) * 80 + kb);
            ldsm4(al[0], al[1], al[2], al[3], aH + AHS + (wm + mt * 16) * 80 + kb);
#pragma unroll
            for (int nt = 0; nt < NTL; nt++) {
                float* a = acc + (mt * NTL + nt) * 4;
                mma16816(a, ah, bhf[nt]);
                mma16816(a, ah, blf[nt]);
                mma16816(a, al, bhf[nt]);
            }
        }
    }
}

template<int BM,int BN,int NTH>
__device__ __forceinline__ void stage_load(char* base, int tid, int bm, int bn,
    const __nv_bfloat16* Ah, const __nv_bfloat16* Al, int lda,
    const __nv_bfloat16* Bh, const __nv_bfloat16* Bl, int ldb, int k0)
{
#pragma unroll
    for (int i = tid; i < BM * 4; i += NTH) {
        int row = i >> 2, c4 = (i & 3) * 16;
        size_t off = ((size_t)(bm + row) * lda + k0) * 2 + c4;
        cpa16(base + row * 80 + c4, (const char*)Ah + off);
        cpa16(base + BM * 80 + row * 80 + c4, (const char*)Al + off);
    }
#pragma unroll
    for (int i = tid; i < BN * 4; i += NTH) {
        int row = i >> 2, c4 = (i & 3) * 16;
        size_t off = ((size_t)(bn + row) * ldb + k0) * 2 + c4;
        cpa16(base + BM * 160 + row * 80 + c4, (const char*)Bh + off);
        cpa16(base + BM * 160 + BN * 80 + row * 80 + c4, (const char*)Bl + off);
    }
    CPA_COMMIT();
}

template<int BM,int BN,int WM,int WN,int NTH>
__global__ void __launch_bounds__(NTH) gemm(GArgs g)
{
    extern __shared__ char sm[];
    constexpr int MT = WM / 16, NTL = WN / 8, NWN = BN / WN;
    constexpr int stageB = (BM + BN) * 160;
    const int tid = threadIdx.x, warp = tid >> 5, lane = tid & 31;
    const int gq = lane >> 2, tg = lane & 3;
    const int laneoff = (lane & 15) * 80 + (lane >> 4) * 16;
    const int wm = (warp / NWN) * WM, wn = (warp % NWN) * WN;
    const int bm = blockIdx.y * BM, bn = blockIdx.x * BN;
    const int K = g.K;

    float acc[MT * NTL * 4];
#pragma unroll
    for (int i = 0; i < MT * NTL * 4; i++) acc[i] = 0.f;

    const int nk = K >> 5;
    stage_load<BM,BN,NTH>(sm, tid, bm, bn, g.Ah, g.Al, g.lda, g.Bh, g.Bl, g.ldb, 0);
    for (int kt = 0; kt < nk; kt++) {
        if (kt + 1 < nk) {
            stage_load<BM,BN,NTH>(sm + ((kt + 1) & 1) * stageB, tid, bm, bn,
                                  g.Ah, g.Al, g.lda, g.Bh, g.Bl, g.ldb, (kt + 1) << 5);
            CPA_WAIT1();
        } else CPA_WAIT0();
        __syncthreads();
        const char* cur = sm + (kt & 1) * stageB;
        stage_mma2<MT,NTL,BM*80,BN*80>(cur, cur + BM * 160, acc, wm, wn, laneoff);
        __syncthreads();
    }

#pragma unroll
    for (int mt = 0; mt < MT; mt++)
#pragma unroll
        for (int nt = 0; nt < NTL; nt++) {
            float* a = acc + (mt * NTL + nt) * 4;
#pragma unroll
            for (int half = 0; half < 2; half++) {
                int r = bm + wm + mt * 16 + gq + half * 8;
                int c = bn + wn + nt * 8 + 2 * tg;
                float v0 = a[half * 2] + g.Ci[c], v1 = a[half * 2 + 1] + g.Ci[c + 1];
                *(float2*)&g.C[(size_t)r * g.ldc + c] = make_float2(v0, v1);
            }
        }
}

// ================= fused tail kernel (512 threads / 16 warps) =================
// smem: stages 3 x 46080 = 138240 | tA @138240 (40960) | tB @179200 (40960)
struct TailArgs {
    const __nv_bfloat16 *XwH, *XwL;
    __nv_bfloat16 *XwHm, *XwLm;
    const __nv_bfloat16 *XrH, *XrL;
    const __nv_bfloat16 *Ch, *Cl;
    const float* basehz;
    const float *b1, *b2, *b3;
    const float *W5, *b5, *W6, *b6, *W8, *b8, *W9, *b9;
    const float *eps_inf, *eps_pri;
    float *fake, *out_mean, *out_lv, *out_z;
    int t;
};

template<int BN,int NTH>
__device__ __forceinline__ void tail_loadB(char* st, int tid,
    const __nv_bfloat16* Bh, const __nv_bfloat16* Bl, int ldb, int kg)
{
#pragma unroll
    for (int i = tid; i < BN * 4; i += NTH) {
        int row = i >> 2, c4 = (i & 3) * 16;
        size_t off = ((size_t)row * ldb + kg) * 2 + c4;
        cpa16(st + row * 80 + c4, (const char*)Bh + off);
        cpa16(st + BN * 80 + row * 80 + c4, (const char*)Bl + off);
    }
}

__device__ __forceinline__ void tail_loadA(char* st, int tid, int r0,
    const __nv_bfloat16* Ah, const __nv_bfloat16* Al, int lda, int kg)
{
    if (tid >= 128) return;
    int arow = tid >> 2, ac4 = (tid & 3) * 16;
    size_t off = ((size_t)(r0 + arow) * lda + kg) * 2 + ac4;
    cpa16(st + arow * 80 + ac4, (const char*)Ah + off);
    cpa16(st + 2560 + arow * 80 + ac4, (const char*)Al + off);
}

// MT=1 epilogue: relu(acc+bias) -> chunked bf16 hi/lo A-layout
template<int NTL>
__device__ __forceinline__ void epi_chunk1(const float* acc, const float* bias,
                                           char* dst, int wm, int wn, int gq, int tg)
{
#pragma unroll
    for (int nt = 0; nt < NTL; nt++)
#pragma unroll
        for (int half = 0; half < 2; half++) {
            int row = wm + gq + half * 8;
            int col = wn + nt * 8 + 2 * tg;
            const float* a = acc + nt * 4 + half * 2;
            float v0 = fmaxf(a[0] + bias[col], 0.f);
            float v1 = fmaxf(a[1] + bias[col + 1], 0.f);
            __nv_bfloat16 h0, l0, h1, l1;
            bsplit(v0, h0, l0); bsplit(v1, h1, l1);
            char* cb = dst + (col >> 5) * 5120;
            int kp = (col & 31) >> 1;
            ((uint32_t*)cb)[row * 20 + kp] = bpack(h0, h1);
            ((uint32_t*)(cb + 2560))[row * 20 + kp] = bpack(l0, l1);
        }
}

__global__ void __launch_bounds__(512) tail_kernel(TailArgs g)
{
    extern __shared__ char sm[];
    char* stages = sm;
    char* tA = sm + 138240;
    char* tB = sm + 179200;
    float* hzc = (float*)tB;

    const int tid = threadIdx.x, lane = tid & 31, warp = tid >> 5;
    const int gq = lane >> 2, tg = lane & 3;
    const int laneoff = (lane & 15) * 80 + (lane >> 4) * 16;
    const int r0 = blockIdx.x * 32;
    constexpr int DST = 46080;
    constexpr int HST = 25600;
    // dec mapping: 16 warps = 2 (M) x 8 (N); warp tile 16x32
    const int dwm = (warp >> 3) * 16, dwn = (warp & 7) * 32;
    // head mapping: 16 warps = 2 (M) x 8 (N); warp tile 16x16
    const int hwm = (warp >> 3) * 16, hwn = (warp & 7) * 16;

    // ---------- dec1: K=512, 16 stages ----------
    {
        float acc[16];
#pragma unroll
        for (int i = 0; i < 16; i++) acc[i] = 0.f;
        tail_loadA(stages, tid, r0, g.XwH + 320, g.XwL + 320, XK, 0);
        tail_loadB<256,512>(stages + 5120, tid, g_W1T_h, g_W1T_l, Hd, 0);
        CPA_COMMIT();
        tail_loadA(stages + DST, tid, r0, g.XwH + 320, g.XwL + 320, XK, 32);
        tail_loadB<256,512>(stages + DST + 5120, tid, g_W1T_h, g_W1T_l, Hd, 32);
        CPA_COMMIT();
        int cb = 0;
        for (int kt = 0; kt < 16; kt++) {
            if (kt + 1 < 16) CPA_WAIT1(); else CPA_WAIT0();
            __syncthreads();
            if (kt + 2 < 16) {
                int nb = cb + 2; if (nb >= 3) nb -= 3;
                tail_loadA(stages + nb * DST, tid, r0, g.XwH + 320, g.XwL + 320, XK, (kt + 2) * 32);
                tail_loadB<256,512>(stages + nb * DST + 5120, tid, g_W1T_h, g_W1T_l, Hd, (kt + 2) * 32);
                CPA_COMMIT();
            }
            char* cur = stages + cb * DST;
            stage_mma2<1,4,2560,20480>(cur, cur + 5120, acc, dwm, dwn, laneoff);
            if (++cb == 3) cb = 0;
        }
        __syncthreads();
        epi_chunk1<4>(acc, g.b1, tA, dwm, dwn, gq, tg);
        __syncthreads();
    }
    // ---------- dec2: K=256 (A local in tA), 8 stages ----------
    {
        float acc[16];
#pragma unroll
        for (int i = 0; i < 16; i++) acc[i] = 0.f;
        tail_loadB<256,512>(stages + 5120, tid, g_W2T_h, g_W2T_l, Fd, 0);
        CPA_COMMIT();
        tail_loadB<256,512>(stages + DST + 5120, tid, g_W2T_h, g_W2T_l, Fd, 32);
        CPA_COMMIT();
        int cb = 0;
        for (int kt = 0; kt < 8; kt++) {
            if (kt + 1 < 8) CPA_WAIT1(); else CPA_WAIT0();
            __syncthreads();
            if (kt + 2 < 8) {
                int nb = cb + 2; if (nb >= 3) nb -= 3;
                tail_loadB<256,512>(stages + nb * DST + 5120, tid, g_W2T_h, g_W2T_l, Fd, (kt + 2) * 32);
                CPA_COMMIT();
            }
            stage_mma2<1,4,2560,20480>(tA + kt * 5120, stages + cb * DST + 5120, acc, dwm, dwn, laneoff);
            if (++cb == 3) cb = 0;
        }
        __syncthreads();
        epi_chunk1<4>(acc, g.b2, tB, dwm, dwn, gq, tg);
        __syncthreads();
    }
    // ---------- dec3: K=256 (A local in tB), 8 stages ----------
    {
        float acc[16];
#pragma unroll
        for (int i = 0; i < 16; i++) acc[i] = 0.f;
        tail_loadB<256,512>(stages + 5120, tid, g_W3T_h, g_W3T_l, Fd, 0);
        CPA_COMMIT();
        tail_loadB<256,512>(stages + DST + 5120, tid, g_W3T_h, g_W3T_l, Fd, 32);
        CPA_COMMIT();
        int cb = 0;
        for (int kt = 0; kt < 8; kt++) {
            if (kt + 1 < 8) CPA_WAIT1(); else CPA_WAIT0();
            __syncthreads();
            if (kt + 2 < 8) {
                int nb = cb + 2; if (nb >= 3) nb -= 3;
                tail_loadB<256,512>(stages + nb * DST + 5120, tid, g_W3T_h, g_W3T_l, Fd, (kt + 2) * 32);
                CPA_COMMIT();
            }
            stage_mma2<1,4,2560,20480>(tB + kt * 5120, stages + cb * DST + 5120, acc, dwm, dwn, laneoff);
            if (++cb == 3) cb = 0;
        }
        __syncthreads();
#pragma unroll
        for (int nt = 0; nt < 4; nt++)
#pragma unroll
            for (int half = 0; half < 2; half++) {
                int row = dwm + gq + half * 8;
                int col = dwn + nt * 8 + 2 * tg;
                int b = r0 + row;
                const float* a = acc + nt * 4 + half * 2;
                float v0 = fmaxf(a[0] + g.b3[col], 0.f);
                float v1 = fmaxf(a[1] + g.b3[col + 1], 0.f);
                *(float2*)&g.fake[(size_t)b * (Td * Fd) + g.t * Fd + col] = make_float2(v0, v1);
                __nv_bfloat16 h0, l0, h1, l1;
                bsplit(v0, h0, l0); bsplit(v1, h1, l1);
                *(__nv_bfloat162*)&g.XwHm[(size_t)b * XK + 64 + col] = bmk2(h0, h1);
                *(__nv_bfloat162*)&g.XwLm[(size_t)b * XK + 64 + col] = bmk2(l0, l1);
                char* cb2 = tA + (col >> 5) * 5120;
                int kp = (col & 31) >> 1;
                ((uint32_t*)cb2)[row * 20 + kp] = bpack(h0, h1);
                ((uint32_t*)(cb2 + 2560))[row * 20 + kp] = bpack(l0, l1);
            }
        __syncthreads();
    }
    // ---------- head: K=1024, 32 stages ----------
    {
        float acc[8];
#pragma unroll
        for (int i = 0; i < 8; i++) acc[i] = 0.f;
        tail_loadA(stages, tid, r0, g.Ch, g.Cl, CK, 0);
        tail_loadB<128,512>(stages + 5120, tid, g_WheadT_h, g_WheadT_l, IK, 0);
        CPA_COMMIT();
        tail_loadA(stages + HST, tid, r0, g.Ch, g.Cl, CK, 32);
        tail_loadB<128,512>(stages + HST + 5120, tid, g_WheadT_h, g_WheadT_l, IK, 32);
        CPA_COMMIT();
        int cb = 0;
        for (int kt = 0; kt < 32; kt++) {
            if (kt + 1 < 32) CPA_WAIT1(); else CPA_WAIT0();
            __syncthreads();
            if (kt + 2 < 32) {
                int nb = cb + 2; if (nb >= 3) nb -= 3;
                int kn = kt + 2;
                char* nxt = stages + nb * HST;
                if (kn < 16)       tail_loadA(nxt, tid, r0, g.Ch, g.Cl, CK, kn * 32);
                else if (kn >= 24) tail_loadA(nxt, tid, r0, g.XrH, g.XrL, XK, 64 + (kn - 24) * 32);
                tail_loadB<128,512>(nxt + 5120, tid, g_WheadT_h, g_WheadT_l, IK, kn * 32);
                CPA_COMMIT();
            }
            char* cur = stages + cb * HST;
            const char* Ab = (kt >= 16 && kt < 24) ? (tA + (kt - 16) * 5120) : cur;
            stage_mma2<1,2,2560,10240>(Ab, cur + 5120, acc, hwm, hwn, laneoff);
            if (++cb == 3) cb = 0;
        }
        __syncthreads();
#pragma unroll
        for (int nt = 0; nt < 2; nt++)
#pragma unroll
            for (int half = 0; half < 2; half++) {
                int row = hwm + gq + half * 8;
                int col = hwn + nt * 8 + 2 * tg;
                const float* a = acc + nt * 4 + half * 2;
                const float* bz = g.basehz + (size_t)(r0 + row) * 128 + col;
                hzc[row * 130 + col]     = fmaxf(a[0] + bz[0], 0.f);
                hzc[row * 130 + col + 1] = fmaxf(a[1] + bz[1], 0.f);
            }
        __syncthreads();
    }
    // ---------- finish: k-outer (512 threads: 4 rows each) ----------
    {
        const int z = tid & 63, rb = tid >> 6;      // rows rb, rb+8, rb+16, rb+24
        float m[4], l[4], mp[4], lp[4];
#pragma unroll
        for (int i = 0; i < 4; i++) { m[i] = g.b5[z]; l[i] = g.b6[z]; mp[i] = g.b8[z]; lp[i] = g.b9[z]; }
#pragma unroll 4
        for (int k = 0; k < 64; k++) {
            float w5 = g.W5[k * Zd + z], w6 = g.W6[k * Zd + z];
            float w8 = g.W8[k * Zd + z], w9 = g.W9[k * Zd + z];
#pragma unroll
            for (int i = 0; i < 4; i++) {
                int row = rb + 8 * i;
                float av = hzc[row * 130 + k];
                float ap = hzc[row * 130 + 64 + k];
                m[i]  += av * w5;  l[i]  += av * w6;
                mp[i] += ap * w8;  lp[i] += ap * w9;
            }
        }
#pragma unroll
        for (int i = 0; i < 4; i++) {
            int row = rb + 8 * i, b = r0 + row;
            float mm = fmaxf(m[i], 0.f),  ll = fmaxf(l[i], 0.f);
            float mmp = fmaxf(mp[i], 0.f), llp = fmaxf(lp[i], 0.f);
            size_t gi = (size_t)b * Zd + z;
            float zi = mm  + g.eps_inf[(size_t)g.t * Bn * Zd + gi] * __expf(0.5f * ll);
            float zp = mmp + g.eps_pri[(size_t)g.t * Bn * Zd + gi] * __expf(0.5f * llp);
            g.out_mean[(size_t)b * Td * Zd + (size_t)g.t * Zd + z] = mm;
            g.out_lv  [(size_t)b * Td * Zd + (size_t)g.t * Zd + z] = ll;
            g.out_z[(size_t)(2 * g.t)     * Bn * Zd + gi] = zi;
            g.out_z[(size_t)(2 * g.t + 1) * Bn * Zd + gi] = zp;
            __nv_bfloat16 zh, zl; bsplit(zi, zh, zl);
            g.XwHm[(size_t)b * XK + z] = zh;
            g.XwLm[(size_t)b * XK + z] = zl;
        }
    }
}

// ---------------- prep ----------------
__device__ __forceinline__ int perm_n(int np) {
    int chunk = np >> 7, r = np & 127, gate = r >> 5, w = r & 31;
    return gate * 512 + chunk * 32 + w;
}

__global__ void prep_all(const float* __restrict__ h_i,
                         const float* __restrict__ Wx, const float* __restrict__ Wh,
                         const float* __restrict__ bl,
                         const float* __restrict__ W1, const float* __restrict__ W2,
                         const float* __restrict__ W3,
                         const float* __restrict__ W4, const float* __restrict__ W7,
                         const float* __restrict__ b4, const float* __restrict__ b7)
{
    size_t i = (size_t)blockIdx.x * blockDim.x + threadIdx.x;
    __nv_bfloat16 h, l;

    const size_t nX = (size_t)Bn * XK;
    if (i < nX) {
        __nv_bfloat16 z = __float2bfloat16(0.f);
        g_Xh0[i] = z; g_Xl0[i] = z; g_Xh1[i] = z; g_Xl1[i] = z;
        return;
    }
    i -= nX;
    const size_t nC = (size_t)Bn * Hd;
    if (i < nC) { g_c[i] = 0.f; return; }
    i -= nC;
    if (i < (size_t)Bn * Hd) {
        bsplit(h_i[i], h, l);
        g_hih[i] = h; g_hil[i] = l;
        return;
    }
    i -= (size_t)Bn * Hd;
    if (i < (size_t)Gd * XK) {
        int k = (int)(i % XK), np = (int)(i / XK);
        int n = perm_n(np);
        float v;
        if (k < 64)       v = Wx[(size_t)k * Gd + n];
        else if (k < 320) v = Wx[(size_t)(512 + k) * Gd + n];
        else              v = Wh[(size_t)(k - 320) * Gd + n];
        bsplit(v, h, l);
        g_WcatT_h[i] = h; g_WcatT_l[i] = l;
        return;
    }
    i -= (size_t)Gd * XK;
    if (i < (size_t)Gd * Hd) {
        int k = (int)(i % Hd), np = (int)(i / Hd);
        int n = perm_n(np);
        bsplit(Wx[(size_t)(64 + k) * Gd + n], h, l);
        g_WxhT_h[i] = h; g_WxhT_l[i] = l;
        if (k == 0) g_blstmp[np] = bl[n];
        return;
    }
    i -= (size_t)Gd * Hd;
    if (i < (size_t)Fd * Hd) {
        int k = (int)(i % Hd), n = (int)(i / Hd);
        bsplit(W1[(size_t)k * Fd + n], h, l);
        g_W1T_h[i] = h; g_W1T_l[i] = l;
        return;
    }
    i -= (size_t)Fd * Hd;
    if (i < (size_t)Fd * Fd) {
        int k = (int)(i % Fd), n = (int)(i / Fd);
        bsplit(W2[(size_t)k * Fd + n], h, l);
        g_W2T_h[i] = h; g_W2T_l[i] = l;
        return;
    }
    i -= (size_t)Fd * Fd;
    if (i < (size_t)Fd * Fd) {
        int k = (int)(i % Fd), n = (int)(i / Fd);
        bsplit(W3[(size_t)k * Fd + n], h, l);
        g_W3T_h[i] = h; g_W3T_l[i] = l;
        return;
    }
    i -= (size_t)Fd * Fd;
    if (i < (size_t)128 * IK) {
        int k = (int)(i % IK), n = (int)(i / IK);
        float v;
        if (n < 64) v = W4[(size_t)(512 + k) * Zd + n];
        else {
            int n2 = n - 64;
            if (k < 512)      v = W7[(size_t)(512 + k) * Zd + n2];
            else if (k < 768) v = 0.f;
            else              v = W7[(size_t)(1024 + k - 768) * Zd + n2];
        }
        bsplit(v, h, l);
        g_WheadT_h[i] = h; g_WheadT_l[i] = l;
        return;
    }
    i -= (size_t)128 * IK;
    if (i < (size_t)128 * Hd) {
        int k = (int)(i % Hd), n = (int)(i / Hd);
        float v = (n < 64) ? W4[(size_t)k * Zd + n] : W7[(size_t)k * Zd + (n - 64)];
        bsplit(v, h, l);
        g_WbaseT_h[i] = h; g_WbaseT_l[i] = l;
        if (k == 0) g_bhz[n] = (n < 64) ? b4[n] : b7[n - 64];
    }
}

// ---------------- host ----------------
template<typename T> static T* sym(const void* s) { void* p = nullptr; cudaGetSymbolAddress(&p, s); return (T*)p; }

typedef CUresult (*PFN_encode)(CUtensorMap*, CUtensorMapDataType, cuuint32_t, void*,
                               const cuuint64_t*, const cuuint64_t*, const cuuint32_t*,
                               const cuuint32_t*, CUtensorMapInterleave, CUtensorMapSwizzle,
                               CUtensorMapL2promotion, CUtensorMapFloatOOBfill);

static void make_map(PFN_encode enc, CUtensorMap* m, void* base,
                     unsigned long long rows, unsigned boxRows) {
    cuuint64_t dims[2]    = {(cuuint64_t)XK, (cuuint64_t)rows};
    cuuint64_t strides[1] = {(cuuint64_t)XK * 2};
    cuuint32_t box[2]     = {64, boxRows};
    cuuint32_t es[2]      = {1, 1};
    enc(m, CU_TENSOR_MAP_DATA_TYPE_BFLOAT16, 2, base, dims, strides, box, es,
        CU_TENSOR_MAP_INTERLEAVE_NONE, CU_TENSOR_MAP_SWIZZLE_128B,
        CU_TENSOR_MAP_L2_PROMOTION_L2_128B, CU_TENSOR_MAP_FLOAT_OOB_FILL_NONE);
}

extern "C" void kernel_launch(void* const* d_in, const int* in_sizes, int n_in,
                              void* d_out, int out_size) {
    const float* h_i     = (const float*)d_in[0];
    const float* eps_inf = (const float*)d_in[1];
    const float* eps_pri = (const float*)d_in[2];
    const float* Wx      = (const float*)d_in[3];
    const float* Wh      = (const float*)d_in[4];
    const float* b_lstm  = (const float*)d_in[5];
    const float* W1 = (const float*)d_in[6],  *b1 = (const float*)d_in[7];
    const float* W2 = (const float*)d_in[8],  *b2 = (const float*)d_in[9];
    const float* W3 = (const float*)d_in[10], *b3 = (const float*)d_in[11];
    const float* W4 = (const float*)d_in[12], *b4 = (const float*)d_in[13];
    const float* W5 = (const float*)d_in[14], *b5 = (const float*)d_in[15];
    const float* W6 = (const float*)d_in[16], *b6 = (const float*)d_in[17];
    const float* W7 = (const float*)d_in[18], *b7 = (const float*)d_in[19];
    const float* W8 = (const float*)d_in[20], *b8 = (const float*)d_in[21];
    const float* W9 = (const float*)d_in[22], *b9 = (const float*)d_in[23];

    float* out      = (float*)d_out;
    float* out_fake = out;
    float* out_mean = out_fake + (size_t)Bn * Td * Fd;
    float* out_lv   = out_mean + (size_t)Bn * Td * Zd;
    float* out_z    = out_lv   + (size_t)Bn * Td * Zd;

    __nv_bfloat16* Xh0 = sym<__nv_bfloat16>(g_Xh0); __nv_bfloat16* Xl0 = sym<__nv_bfloat16>(g_Xl0);
    __nv_bfloat16* Xh1 = sym<__nv_bfloat16>(g_Xh1); __nv_bfloat16* Xl1 = sym<__nv_bfloat16>(g_Xl1);
    __nv_bfloat16* Ch  = sym<__nv_bfloat16>(g_Ch);  __nv_bfloat16* Cl  = sym<__nv_bfloat16>(g_Cl);

    float* pBaseg  = sym<float>(g_baseg);
    float* pBasehz = sym<float>(g_basehz);
    float* pBlstmp = sym<float>(g_blstmp);
    float* pBhz    = sym<float>(g_bhz);

    PFN_encode enc = nullptr;
    {
        void* fn = nullptr;
        cudaDriverEntryPointQueryResult st;
#if CUDART_VERSION >= 12050
        cudaGetDriverEntryPointByVersion("cuTensorMapEncodeTiled", &fn, 12000,
                                         cudaEnableDefault, &st);
#else
        cudaGetDriverEntryPoint("cuTensorMapEncodeTiled", &fn, cudaEnableDefault, &st);
#endif
        enc = (PFN_encode)fn;
    }
    static CUtensorMap mX[4], mW[2];
    make_map(enc, &mX[0], Xh0, Bn, 64); make_map(enc, &mX[1], Xl0, Bn, 64);
    make_map(enc, &mX[2], Xh1, Bn, 64); make_map(enc, &mX[3], Xl1, Bn, 64);
    make_map(enc, &mW[0], sym<__nv_bfloat16>(g_WcatT_h), Gd, 128);
    make_map(enc, &mW[1], sym<__nv_bfloat16>(g_WcatT_l), Gd, 128);

    constexpr int SMBASE  = 2 * (256 + 128) * 160;
    constexpr int SMSMALL = 2 * (64 + 64) * 160;
    constexpr int SMTAIL  = 220160;
    constexpr int SMGATE  = 1024 + 2 * 49152;   // 99328 -> 2 blocks/SM
    cudaFuncSetAttribute(gemm<256,128,64,64,256>, cudaFuncAttributeMaxDynamicSharedMemorySize, SMBASE);
    cudaFuncSetAttribute(gemm<64,64,32,32,128>,   cudaFuncAttributeMaxDynamicSharedMemorySize, SMSMALL);
    cudaFuncSetAttribute(tail_kernel,             cudaFuncAttributeMaxDynamicSharedMemorySize, SMTAIL);
    cudaFuncSetAttribute(gate_tma,                cudaFuncAttributeMaxDynamicSharedMemorySize, SMGATE);

    // ---- init ----
    {
        size_t tot = (size_t)Bn * XK + 2 * (size_t)Bn * Hd
                   + (size_t)Gd * XK + (size_t)Gd * Hd
                   + (size_t)Fd * Hd + 2 * (size_t)Fd * Fd
                   + (size_t)128 * IK + (size_t)128 * Hd;
        prep_all<<<(unsigned)((tot + 255) / 256), 256>>>(h_i, Wx, Wh, b_lstm,
                                                         W1, W2, W3, W4, W7, b4, b7);
    }

    // ---- hoisted base GEMMs ----
    {
        GArgs b{};
        b.Ah = sym<__nv_bfloat16>(g_hih); b.Al = sym<__nv_bfloat16>(g_hil); b.lda = Hd;
        b.Bh = sym<__nv_bfloat16>(g_WxhT_h); b.Bl = sym<__nv_bfloat16>(g_WxhT_l); b.ldb = Hd;
        b.Ci = pBlstmp; b.C = pBaseg; b.ldc = Gd; b.K = Hd;
        gemm<256,128,64,64,256><<<dim3(16, 16), 256, SMBASE>>>(b);

        b.Bh = sym<__nv_bfloat16>(g_WbaseT_h); b.Bl = sym<__nv_bfloat16>(g_WbaseT_l); b.ldb = Hd;
        b.Ci = pBhz; b.C = pBasehz; b.ldc = 128; b.K = Hd;
        gemm<64,64,32,32,128><<<dim3(2, 64), 128, SMSMALL>>>(b);
    }

    for (int t = 0; t < Td; t++) {
        __nv_bfloat16* XrH = (t & 1) ? Xh1 : Xh0;
        __nv_bfloat16* XrL = (t & 1) ? Xl1 : Xl0;
        __nv_bfloat16* XwH = (t & 1) ? Xh0 : Xh1;
        __nv_bfloat16* XwL = (t & 1) ? Xl0 : Xl1;
        const CUtensorMap& mAh = (t & 1) ? mX[2] : mX[0];
        const CUtensorMap& mAl = (t & 1) ? mX[3] : mX[1];

        gate_tma<<<dim3(16, 64), 256, SMGATE>>>(mAh, mAl, mW[0], mW[1],
                                                pBaseg, sym<float>(g_c),
                                                XwH, XwL, Ch, Cl);
        {
            TailArgs ta{};
            ta.XwH = XwH; ta.XwL = XwL; ta.XwHm = XwH; ta.XwLm = XwL;
            ta.XrH = XrH; ta.XrL = XrL;
            ta.Ch = Ch; ta.Cl = Cl;
            ta.basehz = pBasehz;
            ta.b1 = b1; ta.b2 = b2; ta.b3 = b3;
            ta.W5 = W5; ta.b5 = b5; ta.W6 = W6; ta.b6 = b6;
            ta.W8 = W8; ta.b8 = b8; ta.W9 = W9; ta.b9 = b9;
            ta.eps_inf = eps_inf; ta.eps_pri = eps_pri;
            ta.fake = out_fake; ta.out_mean = out_mean; ta.out_lv = out_lv; ta.out_z = out_z;
            ta.t = t;
            tail_kernel<<<Bn / 32, 512, SMTAIL>>>(ta);
        }
    }
}

// round 16
// speedup vs baseline: 1.5920x; 1.0058x over previous
#include <cuda_runtime.h>
#include <cuda.h>
#include <cuda_bf16.h>
#include <math.h>
#include <stdint.h>

#define Bn   4096
#define Hd   512
#define Fd   256
#define Zd   64
#define Td   16
#define Gd   2048
#define XK   832      // bf16 X row: [z(64) | y(256) | h(512)]
#define IK   1024     // head K:     [c(512) | y_j(256) | y_prev(256)]
#define CK   512      // c buffer row

// ---------------- persistent buffers ----------------
__device__ float g_baseg [(size_t)Bn * Gd];
__device__ float g_basehz[Bn * 128];
__device__ float g_c     [Bn * Hd];
__device__ float g_blstmp[Gd];
__device__ float g_bhz   [128];

__device__ __nv_bfloat16 g_Xh0[(size_t)Bn * XK], g_Xl0[(size_t)Bn * XK];
__device__ __nv_bfloat16 g_Xh1[(size_t)Bn * XK], g_Xl1[(size_t)Bn * XK];
__device__ __nv_bfloat16 g_Ch [(size_t)Bn * CK], g_Cl [(size_t)Bn * CK];
__device__ __nv_bfloat16 g_hih[(size_t)Bn * Hd], g_hil[(size_t)Bn * Hd];

__device__ __nv_bfloat16 g_WcatT_h[(size_t)Gd * XK], g_WcatT_l[(size_t)Gd * XK];
__device__ __nv_bfloat16 g_WxhT_h [(size_t)Gd * Hd], g_WxhT_l [(size_t)Gd * Hd];
__device__ __nv_bfloat16 g_W1T_h  [Fd * Hd], g_W1T_l  [Fd * Hd];
__device__ __nv_bfloat16 g_W2T_h  [Fd * Fd], g_W2T_l  [Fd * Fd];
__device__ __nv_bfloat16 g_W3T_h  [Fd * Fd], g_W3T_l  [Fd * Fd];
__device__ __nv_bfloat16 g_WheadT_h[128 * IK], g_WheadT_l[128 * IK];
__device__ __nv_bfloat16 g_WbaseT_h[128 * Hd], g_WbaseT_l[128 * Hd];

// ---------------- helpers ----------------
__device__ __forceinline__ void bsplit(float v, __nv_bfloat16& h, __nv_bfloat16& l) {
    h = __float2bfloat16_rn(v);
    l = __float2bfloat16_rn(v - __bfloat162float(h));
}
__device__ __forceinline__ uint32_t bpack(__nv_bfloat16 a, __nv_bfloat16 b) {
    __nv_bfloat162 t; t.x = a; t.y = b;
    return reinterpret_cast<uint32_t&>(t);
}
__device__ __forceinline__ __nv_bfloat162 bmk2(__nv_bfloat16 a, __nv_bfloat16 b) {
    __nv_bfloat162 t; t.x = a; t.y = b; return t;
}
__device__ __forceinline__ float fsig(float x) {
    return __fdividef(1.f, 1.f + __expf(-x));
}
__device__ __forceinline__ float ftanh(float x) {
    return 2.f * fsig(2.f * x) - 1.f;
}
__device__ __forceinline__ void mma16816(float* c, const uint32_t* a, const uint32_t* b) {
    asm volatile(
        "mma.sync.aligned.m16n8k16.row.col.f32.bf16.bf16.f32 "
        "{%0,%1,%2,%3}, {%4,%5,%6,%7}, {%8,%9}, {%0,%1,%2,%3};\n"
        : "+f"(c[0]), "+f"(c[1]), "+f"(c[2]), "+f"(c[3])
        : "r"(a[0]), "r"(a[1]), "r"(a[2]), "r"(a[3]), "r"(b[0]), "r"(b[1]));
}
__device__ __forceinline__ void ldsm4(uint32_t& r0, uint32_t& r1, uint32_t& r2, uint32_t& r3,
                                      uint32_t addr) {
    asm volatile("ldmatrix.sync.aligned.m8n8.x4.shared.b16 {%0,%1,%2,%3}, [%4];"
        : "=r"(r0), "=r"(r1), "=r"(r2), "=r"(r3) : "r"(addr));
}
__device__ __forceinline__ void cpa16(void* dst, const void* src) {
    uint32_t d = (uint32_t)__cvta_generic_to_shared(dst);
    asm volatile("cp.async.cg.shared.global [%0], [%1], 16;\n" :: "r"(d), "l"(src));
}
#define CPA_COMMIT() asm volatile("cp.async.commit_group;\n")
#define CPA_WAIT2()  asm volatile("cp.async.wait_group 2;\n")
#define CPA_WAIT1()  asm volatile("cp.async.wait_group 1;\n")
#define CPA_WAIT0()  asm volatile("cp.async.wait_group 0;\n")

__device__ __forceinline__ uint32_t smem_u32(const void* p) {
    return (uint32_t)__cvta_generic_to_shared(p);
}

// ---- TMA / mbarrier ----
#define MBAR_INIT(a, n) \
    asm volatile("mbarrier.init.shared.b64 [%0], %1;" :: "r"(a), "r"(n) : "memory")
#define MBAR_EXPECT_TX(a, bytes) \
    asm volatile("mbarrier.arrive.expect_tx.shared.b64 _, [%0], %1;" :: "r"(a), "r"(bytes) : "memory")
#define MBAR_WAIT(a, par) do { \
    asm volatile("{\n\t.reg .pred P1;\n\tWL%=:\n\t" \
        "mbarrier.try_wait.parity.acquire.cta.shared::cta.b64 P1, [%0], %1, 0x989680;\n\t" \
        "@P1 bra.uni WD%=;\n\tbra.uni WL%=;\n\tWD%=:\n\t}" \
        :: "r"(a), "r"(par) : "memory"); \
} while (0)
#define TMA2D(dst, mapp, cx, cy, mb) \
    asm volatile("cp.async.bulk.tensor.2d.shared::cta.global.tile.mbarrier::complete_tx::bytes " \
        "[%0], [%1, {%2, %3}], [%4];" \
        :: "r"(dst), "l"(mapp), "r"(cx), "r"(cy), "r"(mb) : "memory")

// ================= TMA + mma.sync gate kernel (BM=64, 2 blocks/SM) =================
__global__ void __launch_bounds__(256) gate_tma(
    const __grid_constant__ CUtensorMap mAh,   // box {64,64}
    const __grid_constant__ CUtensorMap mAl,
    const __grid_constant__ CUtensorMap mBh,   // box {64,128}
    const __grid_constant__ CUtensorMap mBl,
    const float* __restrict__ baseg, float* __restrict__ cst,
    __nv_bfloat16* __restrict__ Xh, __nv_bfloat16* __restrict__ Xl,
    __nv_bfloat16* __restrict__ Chp, __nv_bfloat16* __restrict__ Clp)
{
    extern __shared__ char sm[];
    const uint32_t sb = smem_u32(sm);
    const int tid = threadIdx.x, warp = tid >> 5, lane = tid & 31;
    const int bm = blockIdx.y * 64, bn = blockIdx.x * 128;
    const uint32_t F0 = sb + 8, F1 = sb + 16;
    const int wm = (warp >> 2) * 32, wn = (warp & 3) * 32;
    const int gq = lane >> 2, tg = lane & 3;
    const int ch = lane >> 4, r7 = lane & 7;
    const int lrow = (lane & 15) * 128;
    constexpr int BUF = 49152;
    constexpr int AL_O = 8192, BH_O = 16384, BL_O = 32768;

    if (tid == 0) { MBAR_INIT(F0, 1); MBAR_INIT(F1, 1); }
    __syncthreads();

    float acc[32];
#pragma unroll
    for (int i = 0; i < 32; i++) acc[i] = 0.f;

    if (tid == 0) {
        MBAR_EXPECT_TX(F0, BUF);
        uint32_t d = sb + 1024;
        TMA2D(d,        &mAh, 0, bm, F0);
        TMA2D(d + AL_O, &mAl, 0, bm, F0);
        TMA2D(d + BH_O, &mBh, 0, bn, F0);
        TMA2D(d + BL_O, &mBl, 0, bn, F0);
        MBAR_EXPECT_TX(F1, BUF);
        d = sb + 1024 + BUF;
        TMA2D(d,        &mAh, 64, bm, F1);
        TMA2D(d + AL_O, &mAl, 64, bm, F1);
        TMA2D(d + BH_O, &mBh, 64, bn, F1);
        TMA2D(d + BL_O, &mBl, 64, bn, F1);
    }

    int pf0 = 0, pf1 = 0;
    for (int c = 0; c <= 12; c++) {
        if ((c & 1) == 0) { MBAR_WAIT(F0, pf0); pf0 ^= 1; }
        else              { MBAR_WAIT(F1, pf1); pf1 ^= 1; }
        const uint32_t bo = sb + 1024 + (c & 1) * BUF;
        const uint32_t aH = bo, aL = bo + AL_O, bH = bo + BH_O, bL = bo + BL_O;
#pragma unroll
        for (int g = 0; g < 4; g++) {
            const int xo = (((2 * g + ch) ^ r7) << 4) + lrow;
            uint32_t bhf[4][2], blf[4][2];
#pragma unroll
            for (int np = 0; np < 2; np++) {
                uint32_t r0, r1, r2, r3;
                ldsm4(r0, r1, r2, r3, bH + (wn + np * 16) * 128 + xo);
                bhf[2*np][0] = r0; bhf[2*np+1][0] = r1; bhf[2*np][1] = r2; bhf[2*np+1][1] = r3;
                ldsm4(r0, r1, r2, r3, bL + (wn + np * 16) * 128 + xo);
                blf[2*np][0] = r0; blf[2*np+1][0] = r1; blf[2*np][1] = r2; blf[2*np+1][1] = r3;
            }
#pragma unroll
            for (int mt = 0; mt < 2; mt++) {
                uint32_t ah[4], al[4];
                ldsm4(ah[0], ah[1], ah[2], ah[3], aH + (wm + mt * 16) * 128 + xo);
                ldsm4(al[0], al[1], al[2], al[3], aL + (wm + mt * 16) * 128 + xo);
#pragma unroll
                for (int nt = 0; nt < 4; nt++) {
                    float* a = acc + (mt * 4 + nt) * 4;
                    mma16816(a, ah, bhf[nt]);
                    mma16816(a, ah, blf[nt]);
                    mma16816(a, al, bhf[nt]);
                }
            }
        }
        __syncthreads();
        if (tid == 0 && c + 2 <= 12) {
            const uint32_t mb = (c & 1) ? F1 : F0;
            MBAR_EXPECT_TX(mb, BUF);
            const uint32_t d = sb + 1024 + (c & 1) * BUF;
            const int kc = (c + 2) * 64;
            TMA2D(d,        &mAh, kc, bm, mb);
            TMA2D(d + AL_O, &mAl, kc, bm, mb);
            TMA2D(d + BH_O, &mBh, kc, bn, mb);
            TMA2D(d + BL_O, &mBl, kc, bn, mb);
        }
    }

    float* tile = (float*)(sm + 1024);
#pragma unroll
    for (int mt = 0; mt < 2; mt++)
#pragma unroll
        for (int nt = 0; nt < 4; nt++) {
            int r0 = wm + mt * 16 + gq, c0 = wn + nt * 8 + 2 * tg;
            float* a = acc + (mt * 4 + nt) * 4;
            tile[r0 * 128 + c0]           = a[0];
            tile[r0 * 128 + c0 + 1]       = a[1];
            tile[(r0 + 8) * 128 + c0]     = a[2];
            tile[(r0 + 8) * 128 + c0 + 1] = a[3];
        }
    __syncthreads();

    for (int idx = tid; idx < 64 * 32; idx += 256) {
        int row = idx >> 5, w = idx & 31;
        int b = bm + row, jg = blockIdx.x * 32 + w;
        const float* bg = baseg + (size_t)b * Gd + bn;
        float ig = tile[row * 128 + w]      + bg[w];
        float fg = tile[row * 128 + 32 + w] + bg[32 + w];
        float gg = tile[row * 128 + 64 + w] + bg[64 + w];
        float og = tile[row * 128 + 96 + w] + bg[96 + w];
        float si = fsig(ig), sf = fsig(fg), so = fsig(og);
        float cn = sf * cst[b * Hd + jg] + si * ftanh(gg);
        float hn = so * ftanh(cn);
        cst[b * Hd + jg] = cn;
        __nv_bfloat16 hh, hl, cc, cl;
        bsplit(hn, hh, hl); bsplit(cn, cc, cl);
        Xh[(size_t)b * XK + 320 + jg] = hh;
        Xl[(size_t)b * XK + 320 + jg] = hl;
        Chp[(size_t)b * CK + jg] = cc;
        Clp[(size_t)b * CK + jg] = cl;
    }
}

// ================= mma.sync GEMM body (base GEMMs; 80B-row layout) =================
struct GArgs {
    const __nv_bfloat16 *Ah, *Al; int lda;
    const __nv_bfloat16 *Bh, *Bl; int ldb;
    const float* Ci; int ldci;
    float* C; int ldc;
    int K;
};

template<int MT,int NTL,int AHS,int BHS>
__device__ __forceinline__ void stage_mma2(const char* Ab, const char* Bb, float* acc,
                                           int wm, int wn, int laneoff)
{
    uint32_t aH = smem_u32(Ab) + laneoff;
    uint32_t bH = smem_u32(Bb) + laneoff;
#pragma unroll
    for (int kk = 0; kk < 2; kk++) {
        const int kb = kk * 32;
        uint32_t bhf[NTL][2], blf[NTL][2];
#pragma unroll
        for (int np = 0; np < NTL / 2; np++) {
            uint32_t r0, r1, r2, r3;
            ldsm4(r0, r1, r2, r3, bH + (wn + np * 16) * 80 + kb);
            bhf[2*np][0] = r0; bhf[2*np+1][0] = r1; bhf[2*np][1] = r2; bhf[2*np+1][1] = r3;
            ldsm4(r0, r1, r2, r3, bH + BHS + (wn + np * 16) * 80 + kb);
            blf[2*np][0] = r0; blf[2*np+1][0] = r1; blf[2*np][1] = r2; blf[2*np+1][1] = r3;
        }
#pragma unroll
        for (int mt = 0; mt < MT; mt++) {
            uint32_t ah[4], al[4];
            ldsm4(ah[0], ah[1], ah[2], ah[3], aH + (wm + mt * 16) * 80 + kb);
            ldsm4(al[0], al[1], al[2], al[3], aH + AHS + (wm + mt * 16) * 80 + kb);
#pragma unroll
            for (int nt = 0; nt < NTL; nt++) {
                float* a = acc + (mt * NTL + nt) * 4;
                mma16816(a, ah, bhf[nt]);
                mma16816(a, ah, blf[nt]);
                mma16816(a, al, bhf[nt]);
            }
        }
    }
}

template<int BM,int BN,int NTH>
__device__ __forceinline__ void stage_load(char* base, int tid, int bm, int bn,
    const __nv_bfloat16* Ah, const __nv_bfloat16* Al, int lda,
    const __nv_bfloat16* Bh, const __nv_bfloat16* Bl, int ldb, int k0)
{
#pragma unroll
    for (int i = tid; i < BM * 4; i += NTH) {
        int row = i >> 2, c4 = (i & 3) * 16;
        size_t off = ((size_t)(bm + row) * lda + k0) * 2 + c4;
        cpa16(base + row * 80 + c4, (const char*)Ah + off);
        cpa16(base + BM * 80 + row * 80 + c4, (const char*)Al + off);
    }
#pragma unroll
    for (int i = tid; i < BN * 4; i += NTH) {
        int row = i >> 2, c4 = (i & 3) * 16;
        size_t off = ((size_t)(bn + row) * ldb + k0) * 2 + c4;
        cpa16(base + BM * 160 + row * 80 + c4, (const char*)Bh + off);
        cpa16(base + BM * 160 + BN * 80 + row * 80 + c4, (const char*)Bl + off);
    }
    CPA_COMMIT();
}

template<int BM,int BN,int WM,int WN,int NTH>
__device__ void gemm_body(const GArgs& g, char* sm, int bm, int bn, int tid)
{
    constexpr int MT = WM / 16, NTL = WN / 8, NWN = BN / WN;
    constexpr int stageB = (BM + BN) * 160;
    const int warp = tid >> 5, lane = tid & 31;
    const int gq = lane >> 2, tg = lane & 3;
    const int laneoff = (lane & 15) * 80 + (lane >> 4) * 16;
    const int wm = (warp / NWN) * WM, wn = (warp % NWN) * WN;
    const int K = g.K;

    float acc[MT * NTL * 4];
#pragma unroll
    for (int i = 0; i < MT * NTL * 4; i++) acc[i] = 0.f;

    const int nk = K >> 5;
    stage_load<BM,BN,NTH>(sm, tid, bm, bn, g.Ah, g.Al, g.lda, g.Bh, g.Bl, g.ldb, 0);
    for (int kt = 0; kt < nk; kt++) {
        if (kt + 1 < nk) {
            stage_load<BM,BN,NTH>(sm + ((kt + 1) & 1) * stageB, tid, bm, bn,
                                  g.Ah, g.Al, g.lda, g.Bh, g.Bl, g.ldb, (kt + 1) << 5);
            CPA_WAIT1();
        } else CPA_WAIT0();
        __syncthreads();
        const char* cur = sm + (kt & 1) * stageB;
        stage_mma2<MT,NTL,BM*80,BN*80>(cur, cur + BM * 160, acc, wm, wn, laneoff);
        __syncthreads();
    }

#pragma unroll
    for (int mt = 0; mt < MT; mt++)
#pragma unroll
        for (int nt = 0; nt < NTL; nt++) {
            float* a = acc + (mt * NTL + nt) * 4;
#pragma unroll
            for (int half = 0; half < 2; half++) {
                int r = bm + wm + mt * 16 + gq + half * 8;
                int c = bn + wn + nt * 8 + 2 * tg;
                float v0 = a[half * 2] + g.Ci[c], v1 = a[half * 2 + 1] + g.Ci[c + 1];
                *(float2*)&g.C[(size_t)r * g.ldc + c] = make_float2(v0, v1);
            }
        }
}

// both base GEMMs in one launch (keeps tail at launch slot #4 for ncu)
__global__ void __launch_bounds__(256) base_both(GArgs big, GArgs small)
{
    extern __shared__ char sm[];
    if (blockIdx.z == 0) {
        gemm_body<256,128,64,64,256>(big, sm, blockIdx.y * 256, blockIdx.x * 128, threadIdx.x);
    } else {
        int flat = blockIdx.y * 16 + blockIdx.x;
        if (flat >= 128) return;
        if (threadIdx.x >= 128) return;
        gemm_body<64,64,32,32,128>(small, sm, (flat >> 1) * 64, (flat & 1) * 64, threadIdx.x);
    }
}

// ================= fused tail kernel (512 threads; 4-buffer dec1/head) =================
struct TailArgs {
    const __nv_bfloat16 *XwH, *XwL;
    __nv_bfloat16 *XwHm, *XwLm;
    const __nv_bfloat16 *XrH, *XrL;
    const __nv_bfloat16 *Ch, *Cl;
    const float* basehz;
    const float *b1, *b2, *b3;
    const float *W5, *b5, *W6, *b6, *W8, *b8, *W9, *b9;
    const float *eps_inf, *eps_pri;
    float *fake, *out_mean, *out_lv, *out_z;
    int t;
};

template<int BN,int NTH>
__device__ __forceinline__ void tail_loadB(char* st, int tid,
    const __nv_bfloat16* Bh, const __nv_bfloat16* Bl, int ldb, int kg)
{
#pragma unroll
    for (int i = tid; i < BN * 4; i += NTH) {
        int row = i >> 2, c4 = (i & 3) * 16;
        size_t off = ((size_t)row * ldb + kg) * 2 + c4;
        cpa16(st + row * 80 + c4, (const char*)Bh + off);
        cpa16(st + BN * 80 + row * 80 + c4, (const char*)Bl + off);
    }
}

__device__ __forceinline__ void tail_loadA(char* st, int tid, int r0,
    const __nv_bfloat16* Ah, const __nv_bfloat16* Al, int lda, int kg)
{
    if (tid >= 128) return;
    int arow = tid >> 2, ac4 = (tid & 3) * 16;
    size_t off = ((size_t)(r0 + arow) * lda + kg) * 2 + ac4;
    cpa16(st + arow * 80 + ac4, (const char*)Ah + off);
    cpa16(st + 2560 + arow * 80 + ac4, (const char*)Al + off);
}

template<int NTL>
__device__ __forceinline__ void epi_chunk1(const float* acc, const float* bias,
                                           char* dst, int wm, int wn, int gq, int tg)
{
#pragma unroll
    for (int nt = 0; nt < NTL; nt++)
#pragma unroll
        for (int half = 0; half < 2; half++) {
            int row = wm + gq + half * 8;
            int col = wn + nt * 8 + 2 * tg;
            const float* a = acc + nt * 4 + half * 2;
            float v0 = fmaxf(a[0] + bias[col], 0.f);
            float v1 = fmaxf(a[1] + bias[col + 1], 0.f);
            __nv_bfloat16 h0, l0, h1, l1;
            bsplit(v0, h0, l0); bsplit(v1, h1, l1);
            char* cb = dst + (col >> 5) * 5120;
            int kp = (col & 31) >> 1;
            ((uint32_t*)cb)[row * 20 + kp] = bpack(h0, h1);
            ((uint32_t*)(cb + 2560))[row * 20 + kp] = bpack(l0, l1);
        }
}

// wait helper: ensures group kt complete given committed up to kt+LOOKAHEAD-1
#define TAIL_WAIT(kt, N) do { \
    if ((kt) + 2 < (N)) CPA_WAIT2(); \
    else if ((kt) + 1 < (N)) CPA_WAIT1(); \
    else CPA_WAIT0(); \
} while (0)

__global__ void __launch_bounds__(512) tail_kernel(TailArgs g)
{
    extern __shared__ char sm[];
    char* stages = sm;
    char* tA = sm + 138240;
    char* tB = sm + 179200;
    float* hzc = (float*)tB;

    const int tid = threadIdx.x, lane = tid & 31, warp = tid >> 5;
    const int gq = lane >> 2, tg = lane & 3;
    const int laneoff = (lane & 15) * 80 + (lane >> 4) * 16;
    const int r0 = blockIdx.x * 32;
    constexpr int DST = 46080;
    constexpr int HST = 25600;
    const int dwm = (warp >> 3) * 16, dwn = (warp & 7) * 32;
    const int hwm = (warp >> 3) * 16, hwn = (warp & 7) * 16;

    // ---------- dec1: K=512, 16 stages, 4 buffers (buf3 borrows dead tA/tB region) ----------
    {
        float acc[16];
#pragma unroll
        for (int i = 0; i < 16; i++) acc[i] = 0.f;
#pragma unroll
        for (int p = 0; p < 3; p++) {
            tail_loadA(stages + p * DST, tid, r0, g.XwH + 320, g.XwL + 320, XK, p * 32);
            tail_loadB<256,512>(stages + p * DST + 5120, tid, g_W1T_h, g_W1T_l, Hd, p * 32);
            CPA_COMMIT();
        }
        for (int kt = 0; kt < 16; kt++) {
            TAIL_WAIT(kt, 16);
            __syncthreads();
            if (kt + 3 < 16) {
                char* nxt = stages + ((kt + 3) & 3) * DST;
                tail_loadA(nxt, tid, r0, g.XwH + 320, g.XwL + 320, XK, (kt + 3) * 32);
                tail_loadB<256,512>(nxt + 5120, tid, g_W1T_h, g_W1T_l, Hd, (kt + 3) * 32);
                CPA_COMMIT();
            }
            char* cur = stages + (kt & 3) * DST;
            stage_mma2<1,4,2560,20480>(cur, cur + 5120, acc, dwm, dwn, laneoff);
        }
        __syncthreads();
        epi_chunk1<4>(acc, g.b1, tA, dwm, dwn, gq, tg);
        __syncthreads();
    }
    // ---------- dec2: K=256 (A local in tA), 8 stages, 3 buffers ----------
    {
        float acc[16];
#pragma unroll
        for (int i = 0; i < 16; i++) acc[i] = 0.f;
        tail_loadB<256,512>(stages + 5120, tid, g_W2T_h, g_W2T_l, Fd, 0);
        CPA_COMMIT();
        tail_loadB<256,512>(stages + DST + 5120, tid, g_W2T_h, g_W2T_l, Fd, 32);
        CPA_COMMIT();
        int cb = 0;
        for (int kt = 0; kt < 8; kt++) {
            if (kt + 1 < 8) CPA_WAIT1(); else CPA_WAIT0();
            __syncthreads();
            if (kt + 2 < 8) {
                int nb = cb + 2; if (nb >= 3) nb -= 3;
                tail_loadB<256,512>(stages + nb * DST + 5120, tid, g_W2T_h, g_W2T_l, Fd, (kt + 2) * 32);
                CPA_COMMIT();
            }
            stage_mma2<1,4,2560,20480>(tA + kt * 5120, stages + cb * DST + 5120, acc, dwm, dwn, laneoff);
            if (++cb == 3) cb = 0;
        }
        __syncthreads();
        epi_chunk1<4>(acc, g.b2, tB, dwm, dwn, gq, tg);
        __syncthreads();
    }
    // ---------- dec3: K=256 (A local in tB), 8 stages, 3 buffers ----------
    {
        float acc[16];
#pragma unroll
        for (int i = 0; i < 16; i++) acc[i] = 0.f;
        tail_loadB<256,512>(stages + 5120, tid, g_W3T_h, g_W3T_l, Fd, 0);
        CPA_COMMIT();
        tail_loadB<256,512>(stages + DST + 5120, tid, g_W3T_h, g_W3T_l, Fd, 32);
        CPA_COMMIT();
        int cb = 0;
        for (int kt = 0; kt < 8; kt++) {
            if (kt + 1 < 8) CPA_WAIT1(); else CPA_WAIT0();
            __syncthreads();
            if (kt + 2 < 8) {
                int nb = cb + 2; if (nb >= 3) nb -= 3;
                tail_loadB<256,512>(stages + nb * DST + 5120, tid, g_W3T_h, g_W3T_l, Fd, (kt + 2) * 32);
                CPA_COMMIT();
            }
            stage_mma2<1,4,2560,20480>(tB + kt * 5120, stages + cb * DST + 5120, acc, dwm, dwn, laneoff);
            if (++cb == 3) cb = 0;
        }
        __syncthreads();
#pragma unroll
        for (int nt = 0; nt < 4; nt++)
#pragma unroll
            for (int half = 0; half < 2; half++) {
                int row = dwm + gq + half * 8;
                int col = dwn + nt * 8 + 2 * tg;
                int b = r0 + row;
                const float* a = acc + nt * 4 + half * 2;
                float v0 = fmaxf(a[0] + g.b3[col], 0.f);
                float v1 = fmaxf(a[1] + g.b3[col + 1], 0.f);
                *(float2*)&g.fake[(size_t)b * (Td * Fd) + g.t * Fd + col] = make_float2(v0, v1);
                __nv_bfloat16 h0, l0, h1, l1;
                bsplit(v0, h0, l0); bsplit(v1, h1, l1);
                *(__nv_bfloat162*)&g.XwHm[(size_t)b * XK + 64 + col] = bmk2(h0, h1);
                *(__nv_bfloat162*)&g.XwLm[(size_t)b * XK + 64 + col] = bmk2(l0, l1);
                char* cb2 = tA + (col >> 5) * 5120;
                int kp = (col & 31) >> 1;
                ((uint32_t*)cb2)[row * 20 + kp] = bpack(h0, h1);
                ((uint32_t*)(cb2 + 2560))[row * 20 + kp] = bpack(l0, l1);
            }
        __syncthreads();
    }
    // ---------- head: K=1024, 32 stages, 4 buffers ----------
    {
        float acc[8];
#pragma unroll
        for (int i = 0; i < 8; i++) acc[i] = 0.f;
#pragma unroll
        for (int p = 0; p < 3; p++) {
            char* st = stages + p * HST;
            tail_loadA(st, tid, r0, g.Ch, g.Cl, CK, p * 32);
            tail_loadB<128,512>(st + 5120, tid, g_WheadT_h, g_WheadT_l, IK, p * 32);
            CPA_COMMIT();
        }
        for (int kt = 0; kt < 32; kt++) {
            TAIL_WAIT(kt, 32);
            __syncthreads();
            if (kt + 3 < 32) {
                int kn = kt + 3;
                char* nxt = stages + (kn & 3) * HST;
                if (kn < 16)       tail_loadA(nxt, tid, r0, g.Ch, g.Cl, CK, kn * 32);
                else if (kn >= 24) tail_loadA(nxt, tid, r0, g.XrH, g.XrL, XK, 64 + (kn - 24) * 32);
                tail_loadB<128,512>(nxt + 5120, tid, g_WheadT_h, g_WheadT_l, IK, kn * 32);
                CPA_COMMIT();
            }
            char* cur = stages + (kt & 3) * HST;
            const char* Ab = (kt >= 16 && kt < 24) ? (tA + (kt - 16) * 5120) : cur;
            stage_mma2<1,2,2560,10240>(Ab, cur + 5120, acc, hwm, hwn, laneoff);
        }
        __syncthreads();
#pragma unroll
        for (int nt = 0; nt < 2; nt++)
#pragma unroll
            for (int half = 0; half < 2; half++) {
                int row = hwm + gq + half * 8;
                int col = hwn + nt * 8 + 2 * tg;
                const float* a = acc + nt * 4 + half * 2;
                const float* bz = g.basehz + (size_t)(r0 + row) * 128 + col;
                hzc[row * 130 + col]     = fmaxf(a[0] + bz[0], 0.f);
                hzc[row * 130 + col + 1] = fmaxf(a[1] + bz[1], 0.f);
            }
        __syncthreads();
    }
    // ---------- finish: k-outer ----------
    {
        const int z = tid & 63, rb = tid >> 6;
        float m[4], l[4], mp[4], lp[4];
#pragma unroll
        for (int i = 0; i < 4; i++) { m[i] = g.b5[z]; l[i] = g.b6[z]; mp[i] = g.b8[z]; lp[i] = g.b9[z]; }
#pragma unroll 4
        for (int k = 0; k < 64; k++) {
            float w5 = g.W5[k * Zd + z], w6 = g.W6[k * Zd + z];
            float w8 = g.W8[k * Zd + z], w9 = g.W9[k * Zd + z];
#pragma unroll
            for (int i = 0; i < 4; i++) {
                int row = rb + 8 * i;
                float av = hzc[row * 130 + k];
                float ap = hzc[row * 130 + 64 + k];
                m[i]  += av * w5;  l[i]  += av * w6;
                mp[i] += ap * w8;  lp[i] += ap * w9;
            }
        }
#pragma unroll
        for (int i = 0; i < 4; i++) {
            int row = rb + 8 * i, b = r0 + row;
            float mm = fmaxf(m[i], 0.f),  ll = fmaxf(l[i], 0.f);
            float mmp = fmaxf(mp[i], 0.f), llp = fmaxf(lp[i], 0.f);
            size_t gi = (size_t)b * Zd + z;
            float zi = mm  + g.eps_inf[(size_t)g.t * Bn * Zd + gi] * __expf(0.5f * ll);
            float zp = mmp + g.eps_pri[(size_t)g.t * Bn * Zd + gi] * __expf(0.5f * llp);
            g.out_mean[(size_t)b * Td * Zd + (size_t)g.t * Zd + z] = mm;
            g.out_lv  [(size_t)b * Td * Zd + (size_t)g.t * Zd + z] = ll;
            g.out_z[(size_t)(2 * g.t)     * Bn * Zd + gi] = zi;
            g.out_z[(size_t)(2 * g.t + 1) * Bn * Zd + gi] = zp;
            __nv_bfloat16 zh, zl; bsplit(zi, zh, zl);
            g.XwHm[(size_t)b * XK + z] = zh;
            g.XwLm[(size_t)b * XK + z] = zl;
        }
    }
}

// ---------------- prep ----------------
__device__ __forceinline__ int perm_n(int np) {
    int chunk = np >> 7, r = np & 127, gate = r >> 5, w = r & 31;
    return gate * 512 + chunk * 32 + w;
}

__global__ void prep_all(const float* __restrict__ h_i,
                         const float* __restrict__ Wx, const float* __restrict__ Wh,
                         const float* __restrict__ bl,
                         const float* __restrict__ W1, const float* __restrict__ W2,
                         const float* __restrict__ W3,
                         const float* __restrict__ W4, const float* __restrict__ W7,
                         const float* __restrict__ b4, const float* __restrict__ b7)
{
    size_t i = (size_t)blockIdx.x * blockDim.x + threadIdx.x;
    __nv_bfloat16 h, l;

    const size_t nX = (size_t)Bn * XK;
    if (i < nX) {
        __nv_bfloat16 z = __float2bfloat16(0.f);
        g_Xh0[i] = z; g_Xl0[i] = z; g_Xh1[i] = z; g_Xl1[i] = z;
        return;
    }
    i -= nX;
    const size_t nC = (size_t)Bn * Hd;
    if (i < nC) { g_c[i] = 0.f; return; }
    i -= nC;
    if (i < (size_t)Bn * Hd) {
        bsplit(h_i[i], h, l);
        g_hih[i] = h; g_hil[i] = l;
        return;
    }
    i -= (size_t)Bn * Hd;
    if (i < (size_t)Gd * XK) {
        int k = (int)(i % XK), np = (int)(i / XK);
        int n = perm_n(np);
        float v;
        if (k < 64)       v = Wx[(size_t)k * Gd + n];
        else if (k < 320) v = Wx[(size_t)(512 + k) * Gd + n];
        else              v = Wh[(size_t)(k - 320) * Gd + n];
        bsplit(v, h, l);
        g_WcatT_h[i] = h; g_WcatT_l[i] = l;
        return;
    }
    i -= (size_t)Gd * XK;
    if (i < (size_t)Gd * Hd) {
        int k = (int)(i % Hd), np = (int)(i / Hd);
        int n = perm_n(np);
        bsplit(Wx[(size_t)(64 + k) * Gd + n], h, l);
        g_WxhT_h[i] = h; g_WxhT_l[i] = l;
        if (k == 0) g_blstmp[np] = bl[n];
        return;
    }
    i -= (size_t)Gd * Hd;
    if (i < (size_t)Fd * Hd) {
        int k = (int)(i % Hd), n = (int)(i / Hd);
        bsplit(W1[(size_t)k * Fd + n], h, l);
        g_W1T_h[i] = h; g_W1T_l[i] = l;
        return;
    }
    i -= (size_t)Fd * Hd;
    if (i < (size_t)Fd * Fd) {
        int k = (int)(i % Fd), n = (int)(i / Fd);
        bsplit(W2[(size_t)k * Fd + n], h, l);
        g_W2T_h[i] = h; g_W2T_l[i] = l;
        return;
    }
    i -= (size_t)Fd * Fd;
    if (i < (size_t)Fd * Fd) {
        int k = (int)(i % Fd), n = (int)(i / Fd);
        bsplit(W3[(size_t)k * Fd + n], h, l);
        g_W3T_h[i] = h; g_W3T_l[i] = l;
        return;
    }
    i -= (size_t)Fd * Fd;
    if (i < (size_t)128 * IK) {
        int k = (int)(i % IK), n = (int)(i / IK);
        float v;
        if (n < 64) v = W4[(size_t)(512 + k) * Zd + n];
        else {
            int n2 = n - 64;
            if (k < 512)      v = W7[(size_t)(512 + k) * Zd + n2];
            else if (k < 768) v = 0.f;
            else              v = W7[(size_t)(1024 + k - 768) * Zd + n2];
        }
        bsplit(v, h, l);
        g_WheadT_h[i] = h; g_WheadT_l[i] = l;
        return;
    }
    i -= (size_t)128 * IK;
    if (i < (size_t)128 * Hd) {
        int k = (int)(i % Hd), n = (int)(i / Hd);
        float v = (n < 64) ? W4[(size_t)k * Zd + n] : W7[(size_t)k * Zd + (n - 64)];
        bsplit(v, h, l);
        g_WbaseT_h[i] = h; g_WbaseT_l[i] = l;
        if (k == 0) g_bhz[n] = (n < 64) ? b4[n] : b7[n - 64];
    }
}

// ---------------- host ----------------
template<typename T> static T* sym(const void* s) { void* p = nullptr; cudaGetSymbolAddress(&p, s); return (T*)p; }

typedef CUresult (*PFN_encode)(CUtensorMap*, CUtensorMapDataType, cuuint32_t, void*,
                               const cuuint64_t*, const cuuint64_t*, const cuuint32_t*,
                               const cuuint32_t*, CUtensorMapInterleave, CUtensorMapSwizzle,
                               CUtensorMapL2promotion, CUtensorMapFloatOOBfill);

static void make_map(PFN_encode enc, CUtensorMap* m, void* base,
                     unsigned long long rows, unsigned boxRows) {
    cuuint64_t dims[2]    = {(cuuint64_t)XK, (cuuint64_t)rows};
    cuuint64_t strides[1] = {(cuuint64_t)XK * 2};
    cuuint32_t box[2]     = {64, boxRows};
    cuuint32_t es[2]      = {1, 1};
    enc(m, CU_TENSOR_MAP_DATA_TYPE_BFLOAT16, 2, base, dims, strides, box, es,
        CU_TENSOR_MAP_INTERLEAVE_NONE, CU_TENSOR_MAP_SWIZZLE_128B,
        CU_TENSOR_MAP_L2_PROMOTION_L2_128B, CU_TENSOR_MAP_FLOAT_OOB_FILL_NONE);
}

extern "C" void kernel_launch(void* const* d_in, const int* in_sizes, int n_in,
                              void* d_out, int out_size) {
    const float* h_i     = (const float*)d_in[0];
    const float* eps_inf = (const float*)d_in[1];
    const float* eps_pri = (const float*)d_in[2];
    const float* Wx      = (const float*)d_in[3];
    const float* Wh      = (const float*)d_in[4];
    const float* b_lstm  = (const float*)d_in[5];
    const float* W1 = (const float*)d_in[6],  *b1 = (const float*)d_in[7];
    const float* W2 = (const float*)d_in[8],  *b2 = (const float*)d_in[9];
    const float* W3 = (const float*)d_in[10], *b3 = (const float*)d_in[11];
    const float* W4 = (const float*)d_in[12], *b4 = (const float*)d_in[13];
    const float* W5 = (const float*)d_in[14], *b5 = (const float*)d_in[15];
    const float* W6 = (const float*)d_in[16], *b6 = (const float*)d_in[17];
    const float* W7 = (const float*)d_in[18], *b7 = (const float*)d_in[19];
    const float* W8 = (const float*)d_in[20], *b8 = (const float*)d_in[21];
    const float* W9 = (const float*)d_in[22], *b9 = (const float*)d_in[23];

    float* out      = (float*)d_out;
    float* out_fake = out;
    float* out_mean = out_fake + (size_t)Bn * Td * Fd;
    float* out_lv   = out_mean + (size_t)Bn * Td * Zd;
    float* out_z    = out_lv   + (size_t)Bn * Td * Zd;

    __nv_bfloat16* Xh0 = sym<__nv_bfloat16>(g_Xh0); __nv_bfloat16* Xl0 = sym<__nv_bfloat16>(g_Xl0);
    __nv_bfloat16* Xh1 = sym<__nv_bfloat16>(g_Xh1); __nv_bfloat16* Xl1 = sym<__nv_bfloat16>(g_Xl1);
    __nv_bfloat16* Ch  = sym<__nv_bfloat16>(g_Ch);  __nv_bfloat16* Cl  = sym<__nv_bfloat16>(g_Cl);

    float* pBaseg  = sym<float>(g_baseg);
    float* pBasehz = sym<float>(g_basehz);
    float* pBlstmp = sym<float>(g_blstmp);
    float* pBhz    = sym<float>(g_bhz);

    PFN_encode enc = nullptr;
    {
        void* fn = nullptr;
        cudaDriverEntryPointQueryResult st;
#if CUDART_VERSION >= 12050
        cudaGetDriverEntryPointByVersion("cuTensorMapEncodeTiled", &fn, 12000,
                                         cudaEnableDefault, &st);
#else
        cudaGetDriverEntryPoint("cuTensorMapEncodeTiled", &fn, cudaEnableDefault, &st);
#endif
        enc = (PFN_encode)fn;
    }
    static CUtensorMap mX[4], mW[2];
    make_map(enc, &mX[0], Xh0, Bn, 64); make_map(enc, &mX[1], Xl0, Bn, 64);
    make_map(enc, &mX[2], Xh1, Bn, 64); make_map(enc, &mX[3], Xl1, Bn, 64);
    make_map(enc, &mW[0], sym<__nv_bfloat16>(g_WcatT_h), Gd, 128);
    make_map(enc, &mW[1], sym<__nv_bfloat16>(g_WcatT_l), Gd, 128);

    constexpr int SMBASE  = 2 * (256 + 128) * 160;   // 122880
    constexpr int SMTAIL  = 220160;
    constexpr int SMGATE  = 1024 + 2 * 49152;        // 99328
    cudaFuncSetAttribute(base_both,   cudaFuncAttributeMaxDynamicSharedMemorySize, SMBASE);
    cudaFuncSetAttribute(tail_kernel, cudaFuncAttributeMaxDynamicSharedMemorySize, SMTAIL);
    cudaFuncSetAttribute(gate_tma,    cudaFuncAttributeMaxDynamicSharedMemorySize, SMGATE);

    // ---- init (launch #1) ----
    {
        size_t tot = (size_t)Bn * XK + 2 * (size_t)Bn * Hd
                   + (size_t)Gd * XK + (size_t)Gd * Hd
                   + (size_t)Fd * Hd + 2 * (size_t)Fd * Fd
                   + (size_t)128 * IK + (size_t)128 * Hd;
        prep_all<<<(unsigned)((tot + 255) / 256), 256>>>(h_i, Wx, Wh, b_lstm,
                                                         W1, W2, W3, W4, W7, b4, b7);
    }

    // ---- hoisted base GEMMs (launch #2, merged) ----
    {
        GArgs big{};
        big.Ah = sym<__nv_bfloat16>(g_hih); big.Al = sym<__nv_bfloat16>(g_hil); big.lda = Hd;
        big.Bh = sym<__nv_bfloat16>(g_WxhT_h); big.Bl = sym<__nv_bfloat16>(g_WxhT_l); big.ldb = Hd;
        big.Ci = pBlstmp; big.C = pBaseg; big.ldc = Gd; big.K = Hd;
        GArgs small = big;
        small.Bh = sym<__nv_bfloat16>(g_WbaseT_h); small.Bl = sym<__nv_bfloat16>(g_WbaseT_l);
        small.Ci = pBhz; small.C = pBasehz; small.ldc = 128;
        base_both<<<dim3(16, 16, 2), 256, SMBASE>>>(big, small);
    }

    for (int t = 0; t < Td; t++) {
        __nv_bfloat16* XrH = (t & 1) ? Xh1 : Xh0;
        __nv_bfloat16* XrL = (t & 1) ? Xl1 : Xl0;
        __nv_bfloat16* XwH = (t & 1) ? Xh0 : Xh1;
        __nv_bfloat16* XwL = (t & 1) ? Xl0 : Xl1;
        const CUtensorMap& mAh = (t & 1) ? mX[2] : mX[0];
        const CUtensorMap& mAl = (t & 1) ? mX[3] : mX[1];

        gate_tma<<<dim3(16, 64), 256, SMGATE>>>(mAh, mAl, mW[0], mW[1],
                                                pBaseg, sym<float>(g_c),
                                                XwH, XwL, Ch, Cl);
        {
            TailArgs ta{};
            ta.XwH = XwH; ta.XwL = XwL; ta.XwHm = XwH; ta.XwLm = XwL;
            ta.XrH = XrH; ta.XrL = XrL;
            ta.Ch = Ch; ta.Cl = Cl;
            ta.basehz = pBasehz;
            ta.b1 = b1; ta.b2 = b2; ta.b3 = b3;
            ta.W5 = W5; ta.b5 = b5; ta.W6 = W6; ta.b6 = b6;
            ta.W8 = W8; ta.b8 = b8; ta.W9 = W9; ta.b9 = b9;
            ta.eps_inf = eps_inf; ta.eps_pri = eps_pri;
            ta.fake = out_fake; ta.out_mean = out_mean; ta.out_lv = out_lv; ta.out_z = out_z;
            ta.t = t;
            tail_kernel<<<Bn / 32, 512, SMTAIL>>>(ta);
        }
    }
}

// round 17
// speedup vs baseline: 1.7861x; 1.1219x over previous
#include <cuda_runtime.h>
#include <cuda.h>
#include <cuda_bf16.h>
#include <math.h>
#include <stdint.h>

#define Bn   4096
#define Hd   512
#define Fd   256
#define Zd   64
#define Td   16
#define Gd   2048
#define XK   832      // bf16 X row: [z(64) | y(256) | h(512)]
#define IK   1024
#define CK   512

// ---------------- persistent buffers ----------------
__device__ float g_baseg [(size_t)Bn * Gd];
__device__ float g_basehz[Bn * 128];
__device__ float g_c     [Bn * Hd];
__device__ float g_blstmp[Gd];
__device__ float g_bhz   [128];

__device__ __nv_bfloat16 g_Xh0[(size_t)Bn * XK], g_Xl0[(size_t)Bn * XK];
__device__ __nv_bfloat16 g_Xh1[(size_t)Bn * XK], g_Xl1[(size_t)Bn * XK];
__device__ __nv_bfloat16 g_Ch [(size_t)Bn * CK], g_Cl [(size_t)Bn * CK];
__device__ __nv_bfloat16 g_hih[(size_t)Bn * Hd], g_hil[(size_t)Bn * Hd];

__device__ __nv_bfloat16 g_WcatT_h[(size_t)Gd * XK], g_WcatT_l[(size_t)Gd * XK];
__device__ __nv_bfloat16 g_WxhT_h [(size_t)Gd * Hd], g_WxhT_l [(size_t)Gd * Hd];
__device__ __nv_bfloat16 g_W1T_h  [Fd * Hd], g_W1T_l  [Fd * Hd];
__device__ __nv_bfloat16 g_W2T_h  [Fd * Fd], g_W2T_l  [Fd * Fd];
__device__ __nv_bfloat16 g_W3T_h  [Fd * Fd], g_W3T_l  [Fd * Fd];
__device__ __nv_bfloat16 g_WheadT_h[128 * IK], g_WheadT_l[128 * IK];
__device__ __nv_bfloat16 g_WbaseT_h[128 * Hd], g_WbaseT_l[128 * Hd];

// ---------------- helpers ----------------
__device__ __forceinline__ void bsplit(float v, __nv_bfloat16& h, __nv_bfloat16& l) {
    h = __float2bfloat16_rn(v);
    l = __float2bfloat16_rn(v - __bfloat162float(h));
}
__device__ __forceinline__ uint32_t bpack(__nv_bfloat16 a, __nv_bfloat16 b) {
    __nv_bfloat162 t; t.x = a; t.y = b;
    return reinterpret_cast<uint32_t&>(t);
}
__device__ __forceinline__ __nv_bfloat162 bmk2(__nv_bfloat16 a, __nv_bfloat16 b) {
    __nv_bfloat162 t; t.x = a; t.y = b; return t;
}
__device__ __forceinline__ float fsig(float x) {
    return __fdividef(1.f, 1.f + __expf(-x));
}
__device__ __forceinline__ float ftanh(float x) {
    return 2.f * fsig(2.f * x) - 1.f;
}
__device__ __forceinline__ void mma16816(float* c, const uint32_t* a, const uint32_t* b) {
    asm volatile(
        "mma.sync.aligned.m16n8k16.row.col.f32.bf16.bf16.f32 "
        "{%0,%1,%2,%3}, {%4,%5,%6,%7}, {%8,%9}, {%0,%1,%2,%3};\n"
        : "+f"(c[0]), "+f"(c[1]), "+f"(c[2]), "+f"(c[3])
        : "r"(a[0]), "r"(a[1]), "r"(a[2]), "r"(a[3]), "r"(b[0]), "r"(b[1]));
}
__device__ __forceinline__ void ldsm4(uint32_t& r0, uint32_t& r1, uint32_t& r2, uint32_t& r3,
                                      uint32_t addr) {
    asm volatile("ldmatrix.sync.aligned.m8n8.x4.shared.b16 {%0,%1,%2,%3}, [%4];"
        : "=r"(r0), "=r"(r1), "=r"(r2), "=r"(r3) : "r"(addr));
}
__device__ __forceinline__ void cpa16(void* dst, const void* src) {
    uint32_t d = (uint32_t)__cvta_generic_to_shared(dst);
    asm volatile("cp.async.cg.shared.global [%0], [%1], 16;\n" :: "r"(d), "l"(src));
}
#define CPA_COMMIT() asm volatile("cp.async.commit_group;\n")
#define CPA_WAIT1()  asm volatile("cp.async.wait_group 1;\n")
#define CPA_WAIT0()  asm volatile("cp.async.wait_group 0;\n")

__device__ __forceinline__ uint32_t smem_u32(const void* p) {
    return (uint32_t)__cvta_generic_to_shared(p);
}

// ---- TMA / mbarrier ----
#define MBAR_INIT(a, n) \
    asm volatile("mbarrier.init.shared.b64 [%0], %1;" :: "r"(a), "r"(n) : "memory")
#define MBAR_EXPECT_TX(a, bytes) \
    asm volatile("mbarrier.arrive.expect_tx.shared.b64 _, [%0], %1;" :: "r"(a), "r"(bytes) : "memory")
#define MBAR_WAIT(a, par) do { \
    asm volatile("{\n\t.reg .pred P1;\n\tWL%=:\n\t" \
        "mbarrier.try_wait.parity.acquire.cta.shared::cta.b64 P1, [%0], %1, 0x989680;\n\t" \
        "@P1 bra.uni WD%=;\n\tbra.uni WL%=;\n\tWD%=:\n\t}" \
        :: "r"(a), "r"(par) : "memory"); \
} while (0)
#define TMA2D(dst, mapp, cx, cy, mb) \
    asm volatile("cp.async.bulk.tensor.2d.shared::cta.global.tile.mbarrier::complete_tx::bytes " \
        "[%0], [%1, {%2, %3}], [%4];" \
        :: "r"(dst), "l"(mapp), "r"(cx), "r"(cy), "r"(mb) : "memory")

// ================= TMA + mma.sync gate kernel (unchanged from R15/16) =================
__global__ void __launch_bounds__(256) gate_tma(
    const __grid_constant__ CUtensorMap mAh,
    const __grid_constant__ CUtensorMap mAl,
    const __grid_constant__ CUtensorMap mBh,
    const __grid_constant__ CUtensorMap mBl,
    const float* __restrict__ baseg, float* __restrict__ cst,
    __nv_bfloat16* __restrict__ Xh, __nv_bfloat16* __restrict__ Xl,
    __nv_bfloat16* __restrict__ Chp, __nv_bfloat16* __restrict__ Clp)
{
    extern __shared__ char sm[];
    const uint32_t sb = smem_u32(sm);
    const int tid = threadIdx.x, warp = tid >> 5, lane = tid & 31;
    const int bm = blockIdx.y * 64, bn = blockIdx.x * 128;
    const uint32_t F0 = sb + 8, F1 = sb + 16;
    const int wm = (warp >> 2) * 32, wn = (warp & 3) * 32;
    const int gq = lane >> 2, tg = lane & 3;
    const int ch = lane >> 4, r7 = lane & 7;
    const int lrow = (lane & 15) * 128;
    constexpr int BUF = 49152;
    constexpr int AL_O = 8192, BH_O = 16384, BL_O = 32768;

    if (tid == 0) { MBAR_INIT(F0, 1); MBAR_INIT(F1, 1); }
    __syncthreads();

    float acc[32];
#pragma unroll
    for (int i = 0; i < 32; i++) acc[i] = 0.f;

    if (tid == 0) {
        MBAR_EXPECT_TX(F0, BUF);
        uint32_t d = sb + 1024;
        TMA2D(d,        &mAh, 0, bm, F0);
        TMA2D(d + AL_O, &mAl, 0, bm, F0);
        TMA2D(d + BH_O, &mBh, 0, bn, F0);
        TMA2D(d + BL_O, &mBl, 0, bn, F0);
        MBAR_EXPECT_TX(F1, BUF);
        d = sb + 1024 + BUF;
        TMA2D(d,        &mAh, 64, bm, F1);
        TMA2D(d + AL_O, &mAl, 64, bm, F1);
        TMA2D(d + BH_O, &mBh, 64, bn, F1);
        TMA2D(d + BL_O, &mBl, 64, bn, F1);
    }

    int pf0 = 0, pf1 = 0;
    for (int c = 0; c <= 12; c++) {
        if ((c & 1) == 0) { MBAR_WAIT(F0, pf0); pf0 ^= 1; }
        else              { MBAR_WAIT(F1, pf1); pf1 ^= 1; }
        const uint32_t bo = sb + 1024 + (c & 1) * BUF;
        const uint32_t aH = bo, aL = bo + AL_O, bH = bo + BH_O, bL = bo + BL_O;
#pragma unroll
        for (int g = 0; g < 4; g++) {
            const int xo = (((2 * g + ch) ^ r7) << 4) + lrow;
            uint32_t bhf[4][2], blf[4][2];
#pragma unroll
            for (int np = 0; np < 2; np++) {
                uint32_t r0, r1, r2, r3;
                ldsm4(r0, r1, r2, r3, bH + (wn + np * 16) * 128 + xo);
                bhf[2*np][0] = r0; bhf[2*np+1][0] = r1; bhf[2*np][1] = r2; bhf[2*np+1][1] = r3;
                ldsm4(r0, r1, r2, r3, bL + (wn + np * 16) * 128 + xo);
                blf[2*np][0] = r0; blf[2*np+1][0] = r1; blf[2*np][1] = r2; blf[2*np+1][1] = r3;
            }
#pragma unroll
            for (int mt = 0; mt < 2; mt++) {
                uint32_t ah[4], al[4];
                ldsm4(ah[0], ah[1], ah[2], ah[3], aH + (wm + mt * 16) * 128 + xo);
                ldsm4(al[0], al[1], al[2], al[3], aL + (wm + mt * 16) * 128 + xo);
#pragma unroll
                for (int nt = 0; nt < 4; nt++) {
                    float* a = acc + (mt * 4 + nt) * 4;
                    mma16816(a, ah, bhf[nt]);
                    mma16816(a, ah, blf[nt]);
                    mma16816(a, al, bhf[nt]);
                }
            }
        }
        __syncthreads();
        if (tid == 0 && c + 2 <= 12) {
            const uint32_t mb = (c & 1) ? F1 : F0;
            MBAR_EXPECT_TX(mb, BUF);
            const uint32_t d = sb + 1024 + (c & 1) * BUF;
            const int kc = (c + 2) * 64;
            TMA2D(d,        &mAh, kc, bm, mb);
            TMA2D(d + AL_O, &mAl, kc, bm, mb);
            TMA2D(d + BH_O, &mBh, kc, bn, mb);
            TMA2D(d + BL_O, &mBl, kc, bn, mb);
        }
    }

    float* tile = (float*)(sm + 1024);
#pragma unroll
    for (int mt = 0; mt < 2; mt++)
#pragma unroll
        for (int nt = 0; nt < 4; nt++) {
            int r0 = wm + mt * 16 + gq, c0 = wn + nt * 8 + 2 * tg;
            float* a = acc + (mt * 4 + nt) * 4;
            tile[r0 * 128 + c0]           = a[0];
            tile[r0 * 128 + c0 + 1]       = a[1];
            tile[(r0 + 8) * 128 + c0]     = a[2];
            tile[(r0 + 8) * 128 + c0 + 1] = a[3];
        }
    __syncthreads();

    for (int idx = tid; idx < 64 * 32; idx += 256) {
        int row = idx >> 5, w = idx & 31;
        int b = bm + row, jg = blockIdx.x * 32 + w;
        const float* bg = baseg + (size_t)b * Gd + bn;
        float ig = tile[row * 128 + w]      + bg[w];
        float fg = tile[row * 128 + 32 + w] + bg[32 + w];
        float gg = tile[row * 128 + 64 + w] + bg[64 + w];
        float og = tile[row * 128 + 96 + w] + bg[96 + w];
        float si = fsig(ig), sf = fsig(fg), so = fsig(og);
        float cn = sf * cst[b * Hd + jg] + si * ftanh(gg);
        float hn = so * ftanh(cn);
        cst[b * Hd + jg] = cn;
        __nv_bfloat16 hh, hl, cc, cl;
        bsplit(hn, hh, hl); bsplit(cn, cc, cl);
        Xh[(size_t)b * XK + 320 + jg] = hh;
        Xl[(size_t)b * XK + 320 + jg] = hl;
        Chp[(size_t)b * CK + jg] = cc;
        Clp[(size_t)b * CK + jg] = cl;
    }
}

// ================= mma.sync GEMM body (base GEMMs; cp.async path, one-time) =================
struct GArgs {
    const __nv_bfloat16 *Ah, *Al; int lda;
    const __nv_bfloat16 *Bh, *Bl; int ldb;
    const float* Ci; int ldci;
    float* C; int ldc;
    int K;
};

template<int MT,int NTL,int AHS,int BHS>
__device__ __forceinline__ void stage_mma2(const char* Ab, const char* Bb, float* acc,
                                           int wm, int wn, int laneoff)
{
    uint32_t aH = smem_u32(Ab) + laneoff;
    uint32_t bH = smem_u32(Bb) + laneoff;
#pragma unroll
    for (int kk = 0; kk < 2; kk++) {
        const int kb = kk * 32;
        uint32_t bhf[NTL][2], blf[NTL][2];
#pragma unroll
        for (int np = 0; np < NTL / 2; np++) {
            uint32_t r0, r1, r2, r3;
            ldsm4(r0, r1, r2, r3, bH + (wn + np * 16) * 80 + kb);
            bhf[2*np][0] = r0; bhf[2*np+1][0] = r1; bhf[2*np][1] = r2; bhf[2*np+1][1] = r3;
            ldsm4(r0, r1, r2, r3, bH + BHS + (wn + np * 16) * 80 + kb);
            blf[2*np][0] = r0; blf[2*np+1][0] = r1; blf[2*np][1] = r2; blf[2*np+1][1] = r3;
        }
#pragma unroll
        for (int mt = 0; mt < MT; mt++) {
            uint32_t ah[4], al[4];
            ldsm4(ah[0], ah[1], ah[2], ah[3], aH + (wm + mt * 16) * 80 + kb);
            ldsm4(al[0], al[1], al[2], al[3], aH + AHS + (wm + mt * 16) * 80 + kb);
#pragma unroll
            for (int nt = 0; nt < NTL; nt++) {
                float* a = acc + (mt * NTL + nt) * 4;
                mma16816(a, ah, bhf[nt]);
                mma16816(a, ah, blf[nt]);
                mma16816(a, al, bhf[nt]);
            }
        }
    }
}

template<int BM,int BN,int NTH>
__device__ __forceinline__ void stage_load(char* base, int tid, int bm, int bn,
    const __nv_bfloat16* Ah, const __nv_bfloat16* Al, int lda,
    const __nv_bfloat16* Bh, const __nv_bfloat16* Bl, int ldb, int k0)
{
#pragma unroll
    for (int i = tid; i < BM * 4; i += NTH) {
        int row = i >> 2, c4 = (i & 3) * 16;
        size_t off = ((size_t)(bm + row) * lda + k0) * 2 + c4;
        cpa16(base + row * 80 + c4, (const char*)Ah + off);
        cpa16(base + BM * 80 + row * 80 + c4, (const char*)Al + off);
    }
#pragma unroll
    for (int i = tid; i < BN * 4; i += NTH) {
        int row = i >> 2, c4 = (i & 3) * 16;
        size_t off = ((size_t)(bn + row) * ldb + k0) * 2 + c4;
        cpa16(base + BM * 160 + row * 80 + c4, (const char*)Bh + off);
        cpa16(base + BM * 160 + BN * 80 + row * 80 + c4, (const char*)Bl + off);
    }
    CPA_COMMIT();
}

template<int BM,int BN,int WM,int WN,int NTH>
__device__ void gemm_body(const GArgs& g, char* sm, int bm, int bn, int tid)
{
    constexpr int MT = WM / 16, NTL = WN / 8, NWN = BN / WN;
    constexpr int stageB = (BM + BN) * 160;
    const int warp = tid >> 5, lane = tid & 31;
    const int gq = lane >> 2, tg = lane & 3;
    const int laneoff = (lane & 15) * 80 + (lane >> 4) * 16;
    const int wm = (warp / NWN) * WM, wn = (warp % NWN) * WN;
    const int K = g.K;

    float acc[MT * NTL * 4];
#pragma unroll
    for (int i = 0; i < MT * NTL * 4; i++) acc[i] = 0.f;

    const int nk = K >> 5;
    stage_load<BM,BN,NTH>(sm, tid, bm, bn, g.Ah, g.Al, g.lda, g.Bh, g.Bl, g.ldb, 0);
    for (int kt = 0; kt < nk; kt++) {
        if (kt + 1 < nk) {
            stage_load<BM,BN,NTH>(sm + ((kt + 1) & 1) * stageB, tid, bm, bn,
                                  g.Ah, g.Al, g.lda, g.Bh, g.Bl, g.ldb, (kt + 1) << 5);
            CPA_WAIT1();
        } else CPA_WAIT0();
        __syncthreads();
        const char* cur = sm + (kt & 1) * stageB;
        stage_mma2<MT,NTL,BM*80,BN*80>(cur, cur + BM * 160, acc, wm, wn, laneoff);
        __syncthreads();
    }

#pragma unroll
    for (int mt = 0; mt < MT; mt++)
#pragma unroll
        for (int nt = 0; nt < NTL; nt++) {
            float* a = acc + (mt * NTL + nt) * 4;
#pragma unroll
            for (int half = 0; half < 2; half++) {
                int r = bm + wm + mt * 16 + gq + half * 8;
                int c = bn + wn + nt * 8 + 2 * tg;
                float v0 = a[half * 2] + g.Ci[c], v1 = a[half * 2 + 1] + g.Ci[c + 1];
                *(float2*)&g.C[(size_t)r * g.ldc + c] = make_float2(v0, v1);
            }
        }
}

__global__ void __launch_bounds__(256) base_both(GArgs big, GArgs small)
{
    extern __shared__ char sm[];
    if (blockIdx.z == 0) {
        gemm_body<256,128,64,64,256>(big, sm, blockIdx.y * 256, blockIdx.x * 128, threadIdx.x);
    } else {
        int flat = blockIdx.y * 16 + blockIdx.x;
        if (flat >= 128) return;
        if (threadIdx.x >= 128) return;
        gemm_body<64,64,32,32,128>(small, sm, (flat >> 1) * 64, (flat & 1) * 64, threadIdx.x);
    }
}

// ================= TMA tail kernel (512 threads) =================
// smem: [8,16) mbars | buffers 2x73728 @1024 | tA 32768 @148480 | tB 32768 @181248
// stage layout: A_h 0 (4KB) | A_l 4096 | B_h 8192 | B_l 8192+Bsz
struct TailArgs {
    __nv_bfloat16 *XwHm, *XwLm;
    const float* basehz;
    const float *b1, *b2, *b3;
    const float *W5, *b5, *W6, *b6, *W8, *b8, *W9, *b9;
    const float *eps_inf, *eps_pri;
    float *fake, *out_mean, *out_lv, *out_z;
    int t;
};

// one K=64 stage: MT=1 (32 A rows), NTL B tiles of 8
template<int NTL>
__device__ __forceinline__ void tstage(uint32_t aH, uint32_t aL,
                                       uint32_t bH, uint32_t bL,
                                       float* acc, int wm, int wn,
                                       int ch, int r7, int lrow)
{
#pragma unroll
    for (int g = 0; g < 4; g++) {
        const int xo = (((2 * g + ch) ^ r7) << 4) + lrow;
        uint32_t bhf[NTL][2], blf[NTL][2];
#pragma unroll
        for (int np = 0; np < NTL / 2; np++) {
            uint32_t q0, q1, q2, q3;
            ldsm4(q0, q1, q2, q3, bH + (wn + np * 16) * 128 + xo);
            bhf[2*np][0] = q0; bhf[2*np+1][0] = q1; bhf[2*np][1] = q2; bhf[2*np+1][1] = q3;
            ldsm4(q0, q1, q2, q3, bL + (wn + np * 16) * 128 + xo);
            blf[2*np][0] = q0; blf[2*np+1][0] = q1; blf[2*np][1] = q2; blf[2*np+1][1] = q3;
        }
        uint32_t ah[4], al[4];
        ldsm4(ah[0], ah[1], ah[2], ah[3], aH + wm * 128 + xo);
        ldsm4(al[0], al[1], al[2], al[3], aL + wm * 128 + xo);
#pragma unroll
        for (int nt = 0; nt < NTL; nt++) {
            float* a = acc + nt * 4;
            mma16816(a, ah, bhf[nt]);
            mma16816(a, ah, blf[nt]);
            mma16816(a, al, bhf[nt]);
        }
    }
}

// smem write in TMA-SW128 layout: chunk base cb (4KB region), row 0..31, col-in-chunk k 0..63 (even)
__device__ __forceinline__ void sw_store(char* cb, int row, int k, uint32_t val) {
    int cc = k >> 3, off = (k & 7) * 2;
    *(uint32_t*)(cb + row * 128 + ((cc ^ (row & 7)) << 4) + off) = val;
}

__global__ void __launch_bounds__(512) tail_kernel(
    const __grid_constant__ CUtensorMap mAh,   // Xw (h-part source), box {64,32}
    const __grid_constant__ CUtensorMap mAl,
    const __grid_constant__ CUtensorMap mRh,   // Xr (y_prev source), box {64,32}
    const __grid_constant__ CUtensorMap mRl,
    const __grid_constant__ CUtensorMap mCh_,  // Ch/Cl, box {64,32}
    const __grid_constant__ CUtensorMap mCl_,
    const __grid_constant__ CUtensorMap mW1h, const __grid_constant__ CUtensorMap mW1l,
    const __grid_constant__ CUtensorMap mW2h, const __grid_constant__ CUtensorMap mW2l,
    const __grid_constant__ CUtensorMap mW3h, const __grid_constant__ CUtensorMap mW3l,
    const __grid_constant__ CUtensorMap mWHh, const __grid_constant__ CUtensorMap mWHl,
    TailArgs g)
{
    extern __shared__ char sm[];
    const uint32_t sb = smem_u32(sm);
    const uint32_t F0 = sb + 8, F1 = sb + 16;
    constexpr int STG = 73728;
    const uint32_t sbuf = sb + 1024;
    const uint32_t tAa = sbuf + 2 * STG;       // 4 chunks x (4KB h + 4KB l)
    const uint32_t tBa = tAa + 32768;
    char* tAp = sm + 1024 + 2 * STG;
    char* tBp = tAp + 32768;
    float* hzc = (float*)(sm + 1024);          // 32 x 130 fp32, after head loop

    const int tid = threadIdx.x, lane = tid & 31, warp = tid >> 5;
    const int gq = lane >> 2, tg = lane & 3;
    const int ch = lane >> 4, r7 = lane & 7;
    const int lrow = (lane & 15) * 128;
    const int r0 = blockIdx.x * 32;
    const int dwm = (warp >> 3) * 16, dwn = (warp & 7) * 32;
    const int hwn = (warp & 7) * 16;

    if (tid == 0) { MBAR_INIT(F0, 1); MBAR_INIT(F1, 1); }
    __syncthreads();
    int pf0 = 0, pf1 = 0;

#define TWAIT(c) do { if (((c) & 1) == 0) { MBAR_WAIT(F0, pf0); pf0 ^= 1; } \
                      else { MBAR_WAIT(F1, pf1); pf1 ^= 1; } } while (0)
#define ISSUE_DEC1(k) do { \
    uint32_t mb = ((k) & 1) ? F1 : F0; uint32_t d = sbuf + ((k) & 1) * STG; \
    MBAR_EXPECT_TX(mb, 73728); \
    TMA2D(d,         &mAh, 320 + (k) * 64, r0, mb); \
    TMA2D(d + 4096,  &mAl, 320 + (k) * 64, r0, mb); \
    TMA2D(d + 8192,  &mW1h, (k) * 64, 0, mb); \
    TMA2D(d + 40960, &mW1l, (k) * 64, 0, mb); \
} while (0)
#define ISSUE_W(k, mh, ml) do { \
    uint32_t mb = ((k) & 1) ? F1 : F0; uint32_t d = sbuf + ((k) & 1) * STG; \
    MBAR_EXPECT_TX(mb, 65536); \
    TMA2D(d + 8192,  &mh, (k) * 64, 0, mb); \
    TMA2D(d + 40960, &ml, (k) * 64, 0, mb); \
} while (0)
#define ISSUE_HEAD(k) do { \
    uint32_t mb = ((k) & 1) ? F1 : F0; uint32_t d = sbuf + ((k) & 1) * STG; \
    if ((k) < 8) { \
        MBAR_EXPECT_TX(mb, 40960); \
        TMA2D(d,        &mCh_, (k) * 64, r0, mb); \
        TMA2D(d + 4096, &mCl_, (k) * 64, r0, mb); \
    } else if ((k) >= 12) { \
        MBAR_EXPECT_TX(mb, 40960); \
        TMA2D(d,        &mRh, 64 + ((k) - 12) * 64, r0, mb); \
        TMA2D(d + 4096, &mRl, 64 + ((k) - 12) * 64, r0, mb); \
    } else { \
        MBAR_EXPECT_TX(mb, 32768); \
    } \
    TMA2D(d + 8192,  &mWHh, (k) * 64, 0, mb); \
    TMA2D(d + 24576, &mWHl, (k) * 64, 0, mb); \
} while (0)

    // ---------- dec1: t1 = relu(h @ W1 + b1), 8 stages of K=64 ----------
    {
        float acc[16];
#pragma unroll
        for (int i = 0; i < 16; i++) acc[i] = 0.f;
        if (tid == 0) { ISSUE_DEC1(0); ISSUE_DEC1(1); }
        for (int c = 0; c < 8; c++) {
            TWAIT(c);
            uint32_t d = sbuf + (c & 1) * STG;
            tstage<4>(d, d + 4096, d + 8192, d + 40960, acc, dwm, dwn, ch, r7, lrow);
            __syncthreads();
            if (tid == 0 && c + 2 < 8) ISSUE_DEC1(c + 2);
        }
        if (tid == 0) { ISSUE_W(0, mW2h, mW2l); ISSUE_W(1, mW2h, mW2l); }
#pragma unroll
        for (int nt = 0; nt < 4; nt++)
#pragma unroll
            for (int half = 0; half < 2; half++) {
                int row = dwm + gq + half * 8;
                int col = dwn + nt * 8 + 2 * tg;
                const float* a = acc + nt * 4 + half * 2;
                float v0 = fmaxf(a[0] + g.b1[col], 0.f);
                float v1 = fmaxf(a[1] + g.b1[col + 1], 0.f);
                __nv_bfloat16 h0, l0, h1, l1;
                bsplit(v0, h0, l0); bsplit(v1, h1, l1);
                char* cb = tAp + (col >> 6) * 8192;
                sw_store(cb,        row, col & 63, bpack(h0, h1));
                sw_store(cb + 4096, row, col & 63, bpack(l0, l1));
            }
        __syncthreads();
    }
    // ---------- dec2: t2 = relu(t1 @ W2 + b2), 4 stages (A local tA) ----------
    {
        float acc[16];
#pragma unroll
        for (int i = 0; i < 16; i++) acc[i] = 0.f;
        for (int c = 0; c < 4; c++) {
            TWAIT(c);
            uint32_t d = sbuf + (c & 1) * STG;
            tstage<4>(tAa + c * 8192, tAa + c * 8192 + 4096, d + 8192, d + 40960,
                      acc, dwm, dwn, ch, r7, lrow);
            __syncthreads();
            if (tid == 0 && c + 2 < 4) ISSUE_W(c + 2, mW2h, mW2l);
        }
        if (tid == 0) { ISSUE_W(0, mW3h, mW3l); ISSUE_W(1, mW3h, mW3l); }
#pragma unroll
        for (int nt = 0; nt < 4; nt++)
#pragma unroll
            for (int half = 0; half < 2; half++) {
                int row = dwm + gq + half * 8;
                int col = dwn + nt * 8 + 2 * tg;
                const float* a = acc + nt * 4 + half * 2;
                float v0 = fmaxf(a[0] + g.b2[col], 0.f);
                float v1 = fmaxf(a[1] + g.b2[col + 1], 0.f);
                __nv_bfloat16 h0, l0, h1, l1;
                bsplit(v0, h0, l0); bsplit(v1, h1, l1);
                char* cb = tBp + (col >> 6) * 8192;
                sw_store(cb,        row, col & 63, bpack(h0, h1));
                sw_store(cb + 4096, row, col & 63, bpack(l0, l1));
            }
        __syncthreads();
    }
    // ---------- dec3: y = relu(t2 @ W3 + b3), 4 stages (A local tB) ----------
    {
        float acc[16];
#pragma unroll
        for (int i = 0; i < 16; i++) acc[i] = 0.f;
        for (int c = 0; c < 4; c++) {
            TWAIT(c);
            uint32_t d = sbuf + (c & 1) * STG;
            tstage<4>(tBa + c * 8192, tBa + c * 8192 + 4096, d + 8192, d + 40960,
                      acc, dwm, dwn, ch, r7, lrow);
            __syncthreads();
            if (tid == 0 && c + 2 < 4) ISSUE_W(c + 2, mW3h, mW3l);
        }
        if (tid == 0) { ISSUE_HEAD(0); ISSUE_HEAD(1); }
#pragma unroll
        for (int nt = 0; nt < 4; nt++)
#pragma unroll
            for (int half = 0; half < 2; half++) {
                int row = dwm + gq + half * 8;
                int col = dwn + nt * 8 + 2 * tg;
                int b = r0 + row;
                const float* a = acc + nt * 4 + half * 2;
                float v0 = fmaxf(a[0] + g.b3[col], 0.f);
                float v1 = fmaxf(a[1] + g.b3[col + 1], 0.f);
                *(float2*)&g.fake[(size_t)b * (Td * Fd) + g.t * Fd + col] = make_float2(v0, v1);
                __nv_bfloat16 h0, l0, h1, l1;
                bsplit(v0, h0, l0); bsplit(v1, h1, l1);
                *(__nv_bfloat162*)&g.XwHm[(size_t)b * XK + 64 + col] = bmk2(h0, h1);
                *(__nv_bfloat162*)&g.XwLm[(size_t)b * XK + 64 + col] = bmk2(l0, l1);
                char* cb = tAp + (col >> 6) * 8192;
                sw_store(cb,        row, col & 63, bpack(h0, h1));
                sw_store(cb + 4096, row, col & 63, bpack(l0, l1));
            }
        __syncthreads();
    }
    // ---------- head: [hz|hzp] = relu(I @ Whead + basehz), 16 stages ----------
    {
        float acc[8];
#pragma unroll
        for (int i = 0; i < 8; i++) acc[i] = 0.f;
        for (int c = 0; c < 16; c++) {
            TWAIT(c);
            uint32_t d = sbuf + (c & 1) * STG;
            uint32_t aH, aL;
            if (c >= 8 && c < 12) { aH = tAa + (c - 8) * 8192; aL = aH + 4096; }
            else                  { aH = d; aL = d + 4096; }
            tstage<2>(aH, aL, d + 8192, d + 24576, acc, dwm, hwn, ch, r7, lrow);
            __syncthreads();
            if (tid == 0 && c + 2 < 16) ISSUE_HEAD(c + 2);
        }
#pragma unroll
        for (int nt = 0; nt < 2; nt++)
#pragma unroll
            for (int half = 0; half < 2; half++) {
                int row = dwm + gq + half * 8;
                int col = hwn + nt * 8 + 2 * tg;
                const float* a = acc + nt * 4 + half * 2;
                const float* bz = g.basehz + (size_t)(r0 + row) * 128 + col;
                hzc[row * 130 + col]     = fmaxf(a[0] + bz[0], 0.f);
                hzc[row * 130 + col + 1] = fmaxf(a[1] + bz[1], 0.f);
            }
        __syncthreads();
    }
    // ---------- finish: k-outer ----------
    {
        const int z = tid & 63, rb = tid >> 6;
        float m[4], l[4], mp[4], lp[4];
#pragma unroll
        for (int i = 0; i < 4; i++) { m[i] = g.b5[z]; l[i] = g.b6[z]; mp[i] = g.b8[z]; lp[i] = g.b9[z]; }
#pragma unroll 4
        for (int k = 0; k < 64; k++) {
            float w5 = g.W5[k * Zd + z], w6 = g.W6[k * Zd + z];
            float w8 = g.W8[k * Zd + z], w9 = g.W9[k * Zd + z];
#pragma unroll
            for (int i = 0; i < 4; i++) {
                int row = rb + 8 * i;
                float av = hzc[row * 130 + k];
                float ap = hzc[row * 130 + 64 + k];
                m[i]  += av * w5;  l[i]  += av * w6;
                mp[i] += ap * w8;  lp[i] += ap * w9;
            }
        }
#pragma unroll
        for (int i = 0; i < 4; i++) {
            int row = rb + 8 * i, b = r0 + row;
            float mm = fmaxf(m[i], 0.f),  ll = fmaxf(l[i], 0.f);
            float mmp = fmaxf(mp[i], 0.f), llp = fmaxf(lp[i], 0.f);
            size_t gi = (size_t)b * Zd + z;
            float zi = mm  + g.eps_inf[(size_t)g.t * Bn * Zd + gi] * __expf(0.5f * ll);
            float zp = mmp + g.eps_pri[(size_t)g.t * Bn * Zd + gi] * __expf(0.5f * llp);
            g.out_mean[(size_t)b * Td * Zd + (size_t)g.t * Zd + z] = mm;
            g.out_lv  [(size_t)b * Td * Zd + (size_t)g.t * Zd + z] = ll;
            g.out_z[(size_t)(2 * g.t)     * Bn * Zd + gi] = zi;
            g.out_z[(size_t)(2 * g.t + 1) * Bn * Zd + gi] = zp;
            __nv_bfloat16 zh, zl; bsplit(zi, zh, zl);
            g.XwHm[(size_t)b * XK + z] = zh;
            g.XwLm[(size_t)b * XK + z] = zl;
        }
    }
#undef TWAIT
#undef ISSUE_DEC1
#undef ISSUE_W
#undef ISSUE_HEAD
}

// ---------------- prep ----------------
__device__ __forceinline__ int perm_n(int np) {
    int chunk = np >> 7, r = np & 127, gate = r >> 5, w = r & 31;
    return gate * 512 + chunk * 32 + w;
}

__global__ void prep_all(const float* __restrict__ h_i,
                         const float* __restrict__ Wx, const float* __restrict__ Wh,
                         const float* __restrict__ bl,
                         const float* __restrict__ W1, const float* __restrict__ W2,
                         const float* __restrict__ W3,
                         const float* __restrict__ W4, const float* __restrict__ W7,
                         const float* __restrict__ b4, const float* __restrict__ b7)
{
    size_t i = (size_t)blockIdx.x * blockDim.x + threadIdx.x;
    __nv_bfloat16 h, l;

    const size_t nX = (size_t)Bn * XK;
    if (i < nX) {
        __nv_bfloat16 z = __float2bfloat16(0.f);
        g_Xh0[i] = z; g_Xl0[i] = z; g_Xh1[i] = z; g_Xl1[i] = z;
        return;
    }
    i -= nX;
    const size_t nC = (size_t)Bn * Hd;
    if (i < nC) { g_c[i] = 0.f; return; }
    i -= nC;
    if (i < (size_t)Bn * Hd) {
        bsplit(h_i[i], h, l);
        g_hih[i] = h; g_hil[i] = l;
        return;
    }
    i -= (size_t)Bn * Hd;
    if (i < (size_t)Gd * XK) {
        int k = (int)(i % XK), np = (int)(i / XK);
        int n = perm_n(np);
        float v;
        if (k < 64)       v = Wx[(size_t)k * Gd + n];
        else if (k < 320) v = Wx[(size_t)(512 + k) * Gd + n];
        else              v = Wh[(size_t)(k - 320) * Gd + n];
        bsplit(v, h, l);
        g_WcatT_h[i] = h; g_WcatT_l[i] = l;
        return;
    }
    i -= (size_t)Gd * XK;
    if (i < (size_t)Gd * Hd) {
        int k = (int)(i % Hd), np = (int)(i / Hd);
        int n = perm_n(np);
        bsplit(Wx[(size_t)(64 + k) * Gd + n], h, l);
        g_WxhT_h[i] = h; g_WxhT_l[i] = l;
        if (k == 0) g_blstmp[np] = bl[n];
        return;
    }
    i -= (size_t)Gd * Hd;
    if (i < (size_t)Fd * Hd) {
        int k = (int)(i % Hd), n = (int)(i / Hd);
        bsplit(W1[(size_t)k * Fd + n], h, l);
        g_W1T_h[i] = h; g_W1T_l[i] = l;
        return;
    }
    i -= (size_t)Fd * Hd;
    if (i < (size_t)Fd * Fd) {
        int k = (int)(i % Fd), n = (int)(i / Fd);
        bsplit(W2[(size_t)k * Fd + n], h, l);
        g_W2T_h[i] = h; g_W2T_l[i] = l;
        return;
    }
    i -= (size_t)Fd * Fd;
    if (i < (size_t)Fd * Fd) {
        int k = (int)(i % Fd), n = (int)(i / Fd);
        bsplit(W3[(size_t)k * Fd + n], h, l);
        g_W3T_h[i] = h; g_W3T_l[i] = l;
        return;
    }
    i -= (size_t)Fd * Fd;
    if (i < (size_t)128 * IK) {
        int k = (int)(i % IK), n = (int)(i / IK);
        float v;
        if (n < 64) v = W4[(size_t)(512 + k) * Zd + n];
        else {
            int n2 = n - 64;
            if (k < 512)      v = W7[(size_t)(512 + k) * Zd + n2];
            else if (k < 768) v = 0.f;
            else              v = W7[(size_t)(1024 + k - 768) * Zd + n2];
        }
        bsplit(v, h, l);
        g_WheadT_h[i] = h; g_WheadT_l[i] = l;
        return;
    }
    i -= (size_t)128 * IK;
    if (i < (size_t)128 * Hd) {
        int k = (int)(i % Hd), n = (int)(i / Hd);
        float v = (n < 64) ? W4[(size_t)k * Zd + n] : W7[(size_t)k * Zd + (n - 64)];
        bsplit(v, h, l);
        g_WbaseT_h[i] = h; g_WbaseT_l[i] = l;
        if (k == 0) g_bhz[n] = (n < 64) ? b4[n] : b7[n - 64];
    }
}

// ---------------- host ----------------
template<typename T> static T* sym(const void* s) { void* p = nullptr; cudaGetSymbolAddress(&p, s); return (T*)p; }

typedef CUresult (*PFN_encode)(CUtensorMap*, CUtensorMapDataType, cuuint32_t, void*,
                               const cuuint64_t*, const cuuint64_t*, const cuuint32_t*,
                               const cuuint32_t*, CUtensorMapInterleave, CUtensorMapSwizzle,
                               CUtensorMapL2promotion, CUtensorMapFloatOOBfill);

static void make_map(PFN_encode enc, CUtensorMap* m, void* base,
                     unsigned long long kdim, unsigned long long rows,
                     unsigned boxK, unsigned boxRows) {
    cuuint64_t dims[2]    = {(cuuint64_t)kdim, (cuuint64_t)rows};
    cuuint64_t strides[1] = {(cuuint64_t)kdim * 2};
    cuuint32_t box[2]     = {boxK, boxRows};
    cuuint32_t es[2]      = {1, 1};
    enc(m, CU_TENSOR_MAP_DATA_TYPE_BFLOAT16, 2, base, dims, strides, box, es,
        CU_TENSOR_MAP_INTERLEAVE_NONE, CU_TENSOR_MAP_SWIZZLE_128B,
        CU_TENSOR_MAP_L2_PROMOTION_L2_128B, CU_TENSOR_MAP_FLOAT_OOB_FILL_NONE);
}

extern "C" void kernel_launch(void* const* d_in, const int* in_sizes, int n_in,
                              void* d_out, int out_size) {
    const float* h_i     = (const float*)d_in[0];
    const float* eps_inf = (const float*)d_in[1];
    const float* eps_pri = (const float*)d_in[2];
    const float* Wx      = (const float*)d_in[3];
    const float* Wh      = (const float*)d_in[4];
    const float* b_lstm  = (const float*)d_in[5];
    const float* W1 = (const float*)d_in[6],  *b1 = (const float*)d_in[7];
    const float* W2 = (const float*)d_in[8],  *b2 = (const float*)d_in[9];
    const float* W3 = (const float*)d_in[10], *b3 = (const float*)d_in[11];
    const float* W4 = (const float*)d_in[12], *b4 = (const float*)d_in[13];
    const float* W5 = (const float*)d_in[14], *b5 = (const float*)d_in[15];
    const float* W6 = (const float*)d_in[16], *b6 = (const float*)d_in[17];
    const float* W7 = (const float*)d_in[18], *b7 = (const float*)d_in[19];
    const float* W8 = (const float*)d_in[20], *b8 = (const float*)d_in[21];
    const float* W9 = (const float*)d_in[22], *b9 = (const float*)d_in[23];

    float* out      = (float*)d_out;
    float* out_fake = out;
    float* out_mean = out_fake + (size_t)Bn * Td * Fd;
    float* out_lv   = out_mean + (size_t)Bn * Td * Zd;
    float* out_z    = out_lv   + (size_t)Bn * Td * Zd;

    __nv_bfloat16* Xh0 = sym<__nv_bfloat16>(g_Xh0); __nv_bfloat16* Xl0 = sym<__nv_bfloat16>(g_Xl0);
    __nv_bfloat16* Xh1 = sym<__nv_bfloat16>(g_Xh1); __nv_bfloat16* Xl1 = sym<__nv_bfloat16>(g_Xl1);
    __nv_bfloat16* Ch  = sym<__nv_bfloat16>(g_Ch);  __nv_bfloat16* Cl  = sym<__nv_bfloat16>(g_Cl);

    float* pBaseg  = sym<float>(g_baseg);
    float* pBasehz = sym<float>(g_basehz);
    float* pBlstmp = sym<float>(g_blstmp);
    float* pBhz    = sym<float>(g_bhz);

    PFN_encode enc = nullptr;
    {
        void* fn = nullptr;
        cudaDriverEntryPointQueryResult st;
#if CUDART_VERSION >= 12050
        cudaGetDriverEntryPointByVersion("cuTensorMapEncodeTiled", &fn, 12000,
                                         cudaEnableDefault, &st);
#else
        cudaGetDriverEntryPoint("cuTensorMapEncodeTiled", &fn, cudaEnableDefault, &st);
#endif
        enc = (PFN_encode)fn;
    }
    static CUtensorMap mX[4], mW[2], mXs[4], mC[2], mw1[2], mw2[2], mw3[2], mwh[2];
    make_map(enc, &mX[0], Xh0, XK, Bn, 64, 64); make_map(enc, &mX[1], Xl0, XK, Bn, 64, 64);
    make_map(enc, &mX[2], Xh1, XK, Bn, 64, 64); make_map(enc, &mX[3], Xl1, XK, Bn, 64, 64);
    make_map(enc, &mW[0], sym<__nv_bfloat16>(g_WcatT_h), XK, Gd, 64, 128);
    make_map(enc, &mW[1], sym<__nv_bfloat16>(g_WcatT_l), XK, Gd, 64, 128);
    make_map(enc, &mXs[0], Xh0, XK, Bn, 64, 32); make_map(enc, &mXs[1], Xl0, XK, Bn, 64, 32);
    make_map(enc, &mXs[2], Xh1, XK, Bn, 64, 32); make_map(enc, &mXs[3], Xl1, XK, Bn, 64, 32);
    make_map(enc, &mC[0], Ch, CK, Bn, 64, 32);  make_map(enc, &mC[1], Cl, CK, Bn, 64, 32);
    make_map(enc, &mw1[0], sym<__nv_bfloat16>(g_W1T_h), Hd, Fd, 64, 256);
    make_map(enc, &mw1[1], sym<__nv_bfloat16>(g_W1T_l), Hd, Fd, 64, 256);
    make_map(enc, &mw2[0], sym<__nv_bfloat16>(g_W2T_h), Fd, Fd, 64, 256);
    make_map(enc, &mw2[1], sym<__nv_bfloat16>(g_W2T_l), Fd, Fd, 64, 256);
    make_map(enc, &mw3[0], sym<__nv_bfloat16>(g_W3T_h), Fd, Fd, 64, 256);
    make_map(enc, &mw3[1], sym<__nv_bfloat16>(g_W3T_l), Fd, Fd, 64, 256);
    make_map(enc, &mwh[0], sym<__nv_bfloat16>(g_WheadT_h), IK, 128, 64, 128);
    make_map(enc, &mwh[1], sym<__nv_bfloat16>(g_WheadT_l), IK, 128, 64, 128);

    constexpr int SMBASE  = 2 * (256 + 128) * 160;
    constexpr int SMGATE  = 1024 + 2 * 49152;
    constexpr int SMTAIL  = 1024 + 2 * 73728 + 2 * 32768;   // 214016
    cudaFuncSetAttribute(base_both,   cudaFuncAttributeMaxDynamicSharedMemorySize, SMBASE);
    cudaFuncSetAttribute(tail_kernel, cudaFuncAttributeMaxDynamicSharedMemorySize, SMTAIL);
    cudaFuncSetAttribute(gate_tma,    cudaFuncAttributeMaxDynamicSharedMemorySize, SMGATE);

    // ---- init ----
    {
        size_t tot = (size_t)Bn * XK + 2 * (size_t)Bn * Hd
                   + (size_t)Gd * XK + (size_t)Gd * Hd
                   + (size_t)Fd * Hd + 2 * (size_t)Fd * Fd
                   + (size_t)128 * IK + (size_t)128 * Hd;
        prep_all<<<(unsigned)((tot + 255) / 256), 256>>>(h_i, Wx, Wh, b_lstm,
                                                         W1, W2, W3, W4, W7, b4, b7);
    }

    // ---- hoisted base GEMMs ----
    {
        GArgs big{};
        big.Ah = sym<__nv_bfloat16>(g_hih); big.Al = sym<__nv_bfloat16>(g_hil); big.lda = Hd;
        big.Bh = sym<__nv_bfloat16>(g_WxhT_h); big.Bl = sym<__nv_bfloat16>(g_WxhT_l); big.ldb = Hd;
        big.Ci = pBlstmp; big.C = pBaseg; big.ldc = Gd; big.K = Hd;
        GArgs small = big;
        small.Bh = sym<__nv_bfloat16>(g_WbaseT_h); small.Bl = sym<__nv_bfloat16>(g_WbaseT_l);
        small.Ci = pBhz; small.C = pBasehz; small.ldc = 128;
        base_both<<<dim3(16, 16, 2), 256, SMBASE>>>(big, small);
    }

    for (int t = 0; t < Td; t++) {
        __nv_bfloat16* XwH = (t & 1) ? Xh0 : Xh1;
        __nv_bfloat16* XwL = (t & 1) ? Xl0 : Xl1;
        const CUtensorMap& gAh = (t & 1) ? mX[2] : mX[0];   // gate reads Xr
        const CUtensorMap& gAl = (t & 1) ? mX[3] : mX[1];
        const CUtensorMap& tAh = (t & 1) ? mXs[0] : mXs[2]; // tail dec1 reads Xw (h)
        const CUtensorMap& tAl = (t & 1) ? mXs[1] : mXs[3];
        const CUtensorMap& tRh = (t & 1) ? mXs[2] : mXs[0]; // tail head reads Xr (y_prev)
        const CUtensorMap& tRl = (t & 1) ? mXs[3] : mXs[1];

        gate_tma<<<dim3(16, 64), 256, SMGATE>>>(gAh, gAl, mW[0], mW[1],
                                                pBaseg, sym<float>(g_c),
                                                XwH, XwL, Ch, Cl);
        {
            TailArgs ta{};
            ta.XwHm = XwH; ta.XwLm = XwL;
            ta.basehz = pBasehz;
            ta.b1 = b1; ta.b2 = b2; ta.b3 = b3;
            ta.W5 = W5; ta.b5 = b5; ta.W6 = W6; ta.b6 = b6;
            ta.W8 = W8; ta.b8 = b8; ta.W9 = W9; ta.b9 = b9;
            ta.eps_inf = eps_inf; ta.eps_pri = eps_pri;
            ta.fake = out_fake; ta.out_mean = out_mean; ta.out_lv = out_lv; ta.out_z = out_z;
            ta.t = t;
            tail_kernel<<<Bn / 32, 512, SMTAIL>>>(tAh, tAl, tRh, tRl, mC[0], mC[1],
                                                  mw1[0], mw1[1], mw2[0], mw2[1],
                                                  mw3[0], mw3[1], mwh[0], mwh[1], ta);
        }
    }
}